// round 1
// baseline (speedup 1.0000x reference)
#include <cuda_runtime.h>
#include <math.h>

// Problem constants
#define D_MODEL   1024
#define NUM_HEADS 16
#define HEAD_DIM  64
#define BATCH     4
#define SEQ       2048
#define M_TOTAL   (BATCH * SEQ)   // 8192

// Scratch (device globals: allocation-free rule)
__device__ float g_q[BATCH * NUM_HEADS * SEQ * HEAD_DIM];    // [b,h,s,e]
__device__ float g_k[BATCH * NUM_HEADS * SEQ * HEAD_DIM];
__device__ float g_v[BATCH * NUM_HEADS * SEQ * HEAD_DIM];
__device__ float g_attn[BATCH * SEQ * D_MODEL];              // [b,s,h*64+e]

// ---------------------------------------------------------------------------
// Kernel 1: fused QKV projection GEMM.
// C[m, n] over M=8192, N=3072 (q|k|v), K=1024.
// X row-major [M,K]. W{q,k,v}: [H, D, E]. Output scattered to g_q/g_k/g_v
// in [b,h,s,e] layout, bias added.
// Tiles: BM=128, BN=128, BK=8; 256 threads; 8x8 per-thread microtile.
// ---------------------------------------------------------------------------
__global__ __launch_bounds__(256) void qkv_gemm(
    const float* __restrict__ X,
    const float* __restrict__ Wq, const float* __restrict__ bq,
    const float* __restrict__ Wk, const float* __restrict__ bk,
    const float* __restrict__ Wv, const float* __restrict__ bv)
{
    __shared__ float As[8][128];   // transposed A tile
    __shared__ float Bs[8][128];

    const int tid = threadIdx.x;
    const int tx = tid & 15;
    const int ty = tid >> 4;

    const int n0 = blockIdx.x * 128;
    const int m0 = blockIdx.y * 128;

    const int proj = n0 >> 10;  // 0:q 1:k 2:v (128 | 1024, so constant per block)
    const float* __restrict__ W    = (proj == 0) ? Wq : (proj == 1) ? Wk : Wv;
    const float* __restrict__ bias = (proj == 0) ? bq : (proj == 1) ? bk : bv;
    float* __restrict__ out        = (proj == 0) ? g_q : (proj == 1) ? g_k : g_v;

    // A-tile load mapping: each thread one float4
    const int a_row = tid >> 1;             // 0..127
    const int a_col = (tid & 1) * 4;        // 0 or 4
    // B-tile load mapping
    const int b_row = tid >> 5;             // 0..7
    const int b_col = (tid & 31) * 4;       // 0..124
    const int nb    = (n0 + b_col) & 1023;  // col within this projection
    const int bh    = nb >> 6;              // head
    const int be    = nb & 63;              // within-head dim (multiple of 4)

    const float* aptr = X + (size_t)(m0 + a_row) * D_MODEL + a_col;
    const float* bptr = W + (size_t)bh * (D_MODEL * HEAD_DIM) + be + b_row * HEAD_DIM;

    float acc[8][8];
    #pragma unroll
    for (int i = 0; i < 8; i++)
        #pragma unroll
        for (int j = 0; j < 8; j++) acc[i][j] = 0.f;

    for (int k0 = 0; k0 < D_MODEL; k0 += 8) {
        float4 av = *reinterpret_cast<const float4*>(aptr + k0);
        float4 bv4 = *reinterpret_cast<const float4*>(bptr + (size_t)k0 * HEAD_DIM);
        As[a_col + 0][a_row] = av.x;
        As[a_col + 1][a_row] = av.y;
        As[a_col + 2][a_row] = av.z;
        As[a_col + 3][a_row] = av.w;
        *reinterpret_cast<float4*>(&Bs[b_row][b_col]) = bv4;
        __syncthreads();

        #pragma unroll
        for (int kk = 0; kk < 8; kk++) {
            float4 a0 = *reinterpret_cast<const float4*>(&As[kk][ty * 4]);
            float4 a1 = *reinterpret_cast<const float4*>(&As[kk][64 + ty * 4]);
            float4 b0 = *reinterpret_cast<const float4*>(&Bs[kk][tx * 4]);
            float4 b1 = *reinterpret_cast<const float4*>(&Bs[kk][64 + tx * 4]);
            float a[8] = {a0.x, a0.y, a0.z, a0.w, a1.x, a1.y, a1.z, a1.w};
            float b[8] = {b0.x, b0.y, b0.z, b0.w, b1.x, b1.y, b1.z, b1.w};
            #pragma unroll
            for (int i = 0; i < 8; i++)
                #pragma unroll
                for (int j = 0; j < 8; j++)
                    acc[i][j] = fmaf(a[i], b[j], acc[i][j]);
        }
        __syncthreads();
    }

    // Epilogue: scatter to [b,h,s,e] + bias
    #pragma unroll
    for (int ri = 0; ri < 2; ri++) {
        #pragma unroll
        for (int i = 0; i < 4; i++) {
            const int m = m0 + ri * 64 + ty * 4 + i;
            const int bb = m >> 11;          // batch
            const int ss = m & 2047;         // seq pos
            #pragma unroll
            for (int cj = 0; cj < 2; cj++) {
                #pragma unroll
                for (int j = 0; j < 4; j++) {
                    const int n  = n0 + cj * 64 + tx * 4 + j;
                    const int nc = n & 1023;
                    const int h  = nc >> 6;
                    const int e  = nc & 63;
                    out[(((size_t)(bb * NUM_HEADS + h)) * SEQ + ss) * HEAD_DIM + e]
                        = acc[ri * 4 + i][cj * 4 + j] + bias[nc];
                }
            }
        }
    }
}

// ---------------------------------------------------------------------------
// Kernel 2: flash attention per (b,h). Block = 64 queries x full 2048 keys
// streamed in 64-key tiles. 256 threads as 16x16; strided 4x4 microtiles
// (row r = ty+16i, col c = tx+16j) for conflict-free hot-loop LDS.
// smem: Qs[64][68] | KsP[64][65] (K tile, reused as P^T) | Vs[64][64]
// ---------------------------------------------------------------------------
#define QS_STRIDE 68
#define KS_STRIDE 65
#define ATTN_SMEM_BYTES ((64 * QS_STRIDE + 64 * KS_STRIDE + 64 * 64) * 4)

__global__ __launch_bounds__(256) void attn_kernel()
{
    extern __shared__ float smem[];
    float* Qs = smem;                      // [64][68]
    float* Ks = Qs + 64 * QS_STRIDE;       // [64][65], reused as P^T[key][q]
    float* Vs = Ks + 64 * KS_STRIDE;       // [64][64]

    const int tid = threadIdx.x;
    const int tx = tid & 15;
    const int ty = tid >> 4;

    const int q0 = blockIdx.x * 64;
    const int bh = blockIdx.y;             // b*16 + h
    const size_t base = (size_t)bh * SEQ * HEAD_DIM;
    const float* __restrict__ Qg = g_q + base;
    const float* __restrict__ Kg = g_k + base;
    const float* __restrict__ Vg = g_v + base;

    // Load + scale Q tile
    {
        const int r = tid >> 2;
        const int c = (tid & 3) * 16;
        #pragma unroll
        for (int i = 0; i < 16; i += 4) {
            float4 v = *reinterpret_cast<const float4*>(Qg + (size_t)(q0 + r) * 64 + c + i);
            v.x *= 0.125f; v.y *= 0.125f; v.z *= 0.125f; v.w *= 0.125f;
            *reinterpret_cast<float4*>(&Qs[r * QS_STRIDE + c + i]) = v;
        }
    }

    float m_run[4], l_run[4], o[4][4];
    #pragma unroll
    for (int i = 0; i < 4; i++) {
        m_run[i] = -INFINITY;
        l_run[i] = 0.f;
        #pragma unroll
        for (int j = 0; j < 4; j++) o[i][j] = 0.f;
    }
    __syncthreads();

    for (int t = 0; t < SEQ; t += 64) {
        // Load K (scalar, stride-65) and V (float4, stride-64) tiles
        {
            const int r = tid >> 2;
            const int c = (tid & 3) * 16;
            #pragma unroll
            for (int i = 0; i < 16; i += 4) {
                float4 kv = *reinterpret_cast<const float4*>(Kg + (size_t)(t + r) * 64 + c + i);
                Ks[r * KS_STRIDE + c + i + 0] = kv.x;
                Ks[r * KS_STRIDE + c + i + 1] = kv.y;
                Ks[r * KS_STRIDE + c + i + 2] = kv.z;
                Ks[r * KS_STRIDE + c + i + 3] = kv.w;
                float4 vv = *reinterpret_cast<const float4*>(Vg + (size_t)(t + r) * 64 + c + i);
                *reinterpret_cast<float4*>(&Vs[r * 64 + c + i]) = vv;
            }
        }
        __syncthreads();

        // Scores S = (Q/8) @ K^T   -> s[i][j], row q0+ty+16i, key t+tx+16j
        float s[4][4];
        #pragma unroll
        for (int i = 0; i < 4; i++)
            #pragma unroll
            for (int j = 0; j < 4; j++) s[i][j] = 0.f;

        for (int e = 0; e < 64; e++) {
            float qv[4], kv[4];
            #pragma unroll
            for (int i = 0; i < 4; i++) qv[i] = Qs[(ty + 16 * i) * QS_STRIDE + e];
            #pragma unroll
            for (int j = 0; j < 4; j++) kv[j] = Ks[(tx + 16 * j) * KS_STRIDE + e];
            #pragma unroll
            for (int i = 0; i < 4; i++)
                #pragma unroll
                for (int j = 0; j < 4; j++)
                    s[i][j] = fmaf(qv[i], kv[j], s[i][j]);
        }

        // Online softmax update (row reduce across the 16 tx lanes = half warp)
        #pragma unroll
        for (int i = 0; i < 4; i++) {
            float mx = fmaxf(fmaxf(s[i][0], s[i][1]), fmaxf(s[i][2], s[i][3]));
            #pragma unroll
            for (int off = 1; off < 16; off <<= 1)
                mx = fmaxf(mx, __shfl_xor_sync(0xffffffffu, mx, off));
            const float m_new = fmaxf(m_run[i], mx);
            const float alpha = __expf(m_run[i] - m_new);
            float sum = 0.f;
            #pragma unroll
            for (int j = 0; j < 4; j++) {
                s[i][j] = __expf(s[i][j] - m_new);
                sum += s[i][j];
            }
            #pragma unroll
            for (int off = 1; off < 16; off <<= 1)
                sum += __shfl_xor_sync(0xffffffffu, sum, off);
            l_run[i] = l_run[i] * alpha + sum;
            m_run[i] = m_new;
            #pragma unroll
            for (int j = 0; j < 4; j++) o[i][j] *= alpha;
        }
        __syncthreads();   // everyone done reading Ks

        // Write P^T[key][q] into the K buffer
        #pragma unroll
        for (int j = 0; j < 4; j++)
            #pragma unroll
            for (int i = 0; i < 4; i++)
                Ks[(tx + 16 * j) * KS_STRIDE + (ty + 16 * i)] = s[i][j];
        __syncthreads();

        // O += P @ V : o[i][j] row q=ty+16i, col e=tx+16j
        for (int kk = 0; kk < 64; kk++) {
            float pv[4], vv[4];
            #pragma unroll
            for (int i = 0; i < 4; i++) pv[i] = Ks[kk * KS_STRIDE + (ty + 16 * i)];
            #pragma unroll
            for (int j = 0; j < 4; j++) vv[j] = Vs[kk * 64 + (tx + 16 * j)];
            #pragma unroll
            for (int i = 0; i < 4; i++)
                #pragma unroll
                for (int j = 0; j < 4; j++)
                    o[i][j] = fmaf(pv[i], vv[j], o[i][j]);
        }
        __syncthreads();   // done with Ks/Vs before next tile load
    }

    // Epilogue: normalize and write concat layout [b, s, h*64 + e]
    const int bb = bh >> 4;
    const int h  = bh & 15;
    #pragma unroll
    for (int i = 0; i < 4; i++) {
        const float inv = 1.f / l_run[i];
        const int q = q0 + ty + 16 * i;
        #pragma unroll
        for (int j = 0; j < 4; j++) {
            const int e = tx + 16 * j;
            g_attn[((size_t)(bb * SEQ + q)) * D_MODEL + h * HEAD_DIM + e] = o[i][j] * inv;
        }
    }
}

// ---------------------------------------------------------------------------
// Kernel 3: output projection. g_attn[8192,1024] @ Wo[1024,1024] + bo -> d_out
// Same SGEMM structure as kernel 1 (plain row-major B).
// ---------------------------------------------------------------------------
__global__ __launch_bounds__(256) void out_gemm(
    const float* __restrict__ Wo, const float* __restrict__ bo,
    float* __restrict__ out)
{
    __shared__ float As[8][128];
    __shared__ float Bs[8][128];

    const int tid = threadIdx.x;
    const int tx = tid & 15;
    const int ty = tid >> 4;

    const int n0 = blockIdx.x * 128;
    const int m0 = blockIdx.y * 128;

    const int a_row = tid >> 1;
    const int a_col = (tid & 1) * 4;
    const int b_row = tid >> 5;
    const int b_col = (tid & 31) * 4;

    const float* aptr = g_attn + (size_t)(m0 + a_row) * D_MODEL + a_col;
    const float* bptr = Wo + (size_t)b_row * D_MODEL + n0 + b_col;

    float acc[8][8];
    #pragma unroll
    for (int i = 0; i < 8; i++)
        #pragma unroll
        for (int j = 0; j < 8; j++) acc[i][j] = 0.f;

    for (int k0 = 0; k0 < D_MODEL; k0 += 8) {
        float4 av = *reinterpret_cast<const float4*>(aptr + k0);
        float4 bv4 = *reinterpret_cast<const float4*>(bptr + (size_t)k0 * D_MODEL);
        As[a_col + 0][a_row] = av.x;
        As[a_col + 1][a_row] = av.y;
        As[a_col + 2][a_row] = av.z;
        As[a_col + 3][a_row] = av.w;
        *reinterpret_cast<float4*>(&Bs[b_row][b_col]) = bv4;
        __syncthreads();

        #pragma unroll
        for (int kk = 0; kk < 8; kk++) {
            float4 a0 = *reinterpret_cast<const float4*>(&As[kk][ty * 4]);
            float4 a1 = *reinterpret_cast<const float4*>(&As[kk][64 + ty * 4]);
            float4 b0 = *reinterpret_cast<const float4*>(&Bs[kk][tx * 4]);
            float4 b1 = *reinterpret_cast<const float4*>(&Bs[kk][64 + tx * 4]);
            float a[8] = {a0.x, a0.y, a0.z, a0.w, a1.x, a1.y, a1.z, a1.w};
            float b[8] = {b0.x, b0.y, b0.z, b0.w, b1.x, b1.y, b1.z, b1.w};
            #pragma unroll
            for (int i = 0; i < 8; i++)
                #pragma unroll
                for (int j = 0; j < 8; j++)
                    acc[i][j] = fmaf(a[i], b[j], acc[i][j]);
        }
        __syncthreads();
    }

    #pragma unroll
    for (int ri = 0; ri < 2; ri++) {
        #pragma unroll
        for (int i = 0; i < 4; i++) {
            const int m = m0 + ri * 64 + ty * 4 + i;
            #pragma unroll
            for (int cj = 0; cj < 2; cj++) {
                #pragma unroll
                for (int j = 0; j < 4; j++) {
                    const int n = n0 + cj * 64 + tx * 4 + j;
                    out[(size_t)m * D_MODEL + n] = acc[ri * 4 + i][cj * 4 + j] + bo[n];
                }
            }
        }
    }
}

// ---------------------------------------------------------------------------
extern "C" void kernel_launch(void* const* d_in, const int* in_sizes, int n_in,
                              void* d_out, int out_size)
{
    const float* x  = (const float*)d_in[0];
    const float* Wq = (const float*)d_in[1];
    const float* bq = (const float*)d_in[2];
    const float* Wk = (const float*)d_in[3];
    const float* bk = (const float*)d_in[4];
    const float* Wv = (const float*)d_in[5];
    const float* bv = (const float*)d_in[6];
    const float* Wo = (const float*)d_in[7];
    const float* bo = (const float*)d_in[8];
    float* out = (float*)d_out;

    cudaFuncSetAttribute(attn_kernel,
                         cudaFuncAttributeMaxDynamicSharedMemorySize,
                         ATTN_SMEM_BYTES);

    // 1) QKV projections: M=8192, N=3072
    qkv_gemm<<<dim3(3 * D_MODEL / 128, M_TOTAL / 128), 256>>>(x, Wq, bq, Wk, bk, Wv, bv);

    // 2) Flash attention: 32 q-tiles x 64 (b,h) pairs
    attn_kernel<<<dim3(SEQ / 64, BATCH * NUM_HEADS), 256, ATTN_SMEM_BYTES>>>();

    // 3) Output projection: M=8192, N=1024
    out_gemm<<<dim3(D_MODEL / 128, M_TOTAL / 128), 256>>>(Wo, bo, out);
}

// round 2
// speedup vs baseline: 1.1140x; 1.1140x over previous
#include <cuda_runtime.h>
#include <math.h>

// Problem constants
#define D_MODEL   1024
#define NUM_HEADS 16
#define HEAD_DIM  64
#define BATCH     4
#define SEQ       2048
#define M_TOTAL   (BATCH * SEQ)   // 8192

typedef unsigned long long u64t;

// ---- packed f32x2 helpers (sm_103a) --------------------------------------
__device__ __forceinline__ u64t fma2(u64t a, u64t b, u64t c) {
    u64t d;
    asm("fma.rn.f32x2 %0, %1, %2, %3;" : "=l"(d) : "l"(a), "l"(b), "l"(c));
    return d;
}
__device__ __forceinline__ u64t mul2(u64t a, u64t b) {
    u64t d;
    asm("mul.rn.f32x2 %0, %1, %2;" : "=l"(d) : "l"(a), "l"(b));
    return d;
}
__device__ __forceinline__ u64t dup2(float x) {
    u64t d; unsigned r = __float_as_uint(x);
    asm("mov.b64 %0, {%1, %1};" : "=l"(d) : "r"(r));
    return d;
}
__device__ __forceinline__ float2 unp2(u64t v) {
    unsigned a, b;
    asm("mov.b64 {%0, %1}, %2;" : "=r"(a), "=r"(b) : "l"(v));
    return make_float2(__uint_as_float(a), __uint_as_float(b));
}
__device__ __forceinline__ float fold2(u64t v) {
    float2 f = unp2(v); return f.x + f.y;
}

// Scratch (device globals: allocation-free rule)
__device__ float g_q[BATCH * NUM_HEADS * SEQ * HEAD_DIM];    // [b,h,s,e]
__device__ float g_k[BATCH * NUM_HEADS * SEQ * HEAD_DIM];
__device__ float g_v[BATCH * NUM_HEADS * SEQ * HEAD_DIM];
__device__ float g_attn[BATCH * SEQ * D_MODEL];              // [b,s,h*64+e]

// ---------------------------------------------------------------------------
// Kernel 1: fused QKV projection GEMM with packed FFMA2.
// Tiles: BM=128, BN=128, BK=8; 256 threads; 8x8 per-thread microtile,
// accumulated as 4 row-pairs x 8 cols in f32x2.
// ---------------------------------------------------------------------------
__global__ __launch_bounds__(256, 2) void qkv_gemm(
    const float* __restrict__ X,
    const float* __restrict__ Wq, const float* __restrict__ bq,
    const float* __restrict__ Wk, const float* __restrict__ bk,
    const float* __restrict__ Wv, const float* __restrict__ bv)
{
    __shared__ __align__(16) float As[8][128];   // transposed A tile [k][m]
    __shared__ __align__(16) float Bs[8][128];   // [k][n]

    const int tid = threadIdx.x;
    const int tx = tid & 15;
    const int ty = tid >> 4;

    const int n0 = blockIdx.x * 128;
    const int m0 = blockIdx.y * 128;

    const int proj = n0 >> 10;  // 0:q 1:k 2:v
    const float* __restrict__ W    = (proj == 0) ? Wq : (proj == 1) ? Wk : Wv;
    const float* __restrict__ bias = (proj == 0) ? bq : (proj == 1) ? bk : bv;
    float* __restrict__ out        = (proj == 0) ? g_q : (proj == 1) ? g_k : g_v;

    const int a_row = tid >> 1;
    const int a_col = (tid & 1) * 4;
    const int b_row = tid >> 5;
    const int b_col = (tid & 31) * 4;
    const int nb    = (n0 + b_col) & 1023;
    const int bh    = nb >> 6;
    const int be    = nb & 63;

    const float* aptr = X + (size_t)(m0 + a_row) * D_MODEL + a_col;
    const float* bptr = W + (size_t)bh * (D_MODEL * HEAD_DIM) + be + b_row * HEAD_DIM;

    u64t acc2[4][8];
    #pragma unroll
    for (int i = 0; i < 4; i++)
        #pragma unroll
        for (int j = 0; j < 8; j++) acc2[i][j] = 0ull;

    for (int k0 = 0; k0 < D_MODEL; k0 += 8) {
        float4 av  = *reinterpret_cast<const float4*>(aptr + k0);
        float4 bv4 = *reinterpret_cast<const float4*>(bptr + (size_t)k0 * HEAD_DIM);
        As[a_col + 0][a_row] = av.x;
        As[a_col + 1][a_row] = av.y;
        As[a_col + 2][a_row] = av.z;
        As[a_col + 3][a_row] = av.w;
        *reinterpret_cast<float4*>(&Bs[b_row][b_col]) = bv4;
        __syncthreads();

        #pragma unroll
        for (int kk = 0; kk < 8; kk++) {
            longlong2 A0 = *reinterpret_cast<const longlong2*>(&As[kk][ty * 4]);
            longlong2 A1 = *reinterpret_cast<const longlong2*>(&As[kk][64 + ty * 4]);
            float4 b0 = *reinterpret_cast<const float4*>(&Bs[kk][tx * 4]);
            float4 b1 = *reinterpret_cast<const float4*>(&Bs[kk][64 + tx * 4]);
            u64t a2[4] = {(u64t)A0.x, (u64t)A0.y, (u64t)A1.x, (u64t)A1.y};
            u64t bd[8] = {dup2(b0.x), dup2(b0.y), dup2(b0.z), dup2(b0.w),
                          dup2(b1.x), dup2(b1.y), dup2(b1.z), dup2(b1.w)};
            #pragma unroll
            for (int i = 0; i < 4; i++)
                #pragma unroll
                for (int j = 0; j < 8; j++)
                    acc2[i][j] = fma2(a2[i], bd[j], acc2[i][j]);
        }
        __syncthreads();
    }

    // Epilogue: scatter to [b,h,s,e] + bias. acc2[i2][j]: rows pair.
    #pragma unroll
    for (int i2 = 0; i2 < 4; i2++) {
        const int r0 = (i2 >> 1) * 64 + ty * 4 + (i2 & 1) * 2;
        #pragma unroll
        for (int j = 0; j < 8; j++) {
            const int n  = n0 + ((j < 4) ? (tx * 4 + j) : (64 + tx * 4 + j - 4));
            const int nc = n & 1023;
            const int h  = nc >> 6;
            const int e  = nc & 63;
            float2 v = unp2(acc2[i2][j]);
            #pragma unroll
            for (int dr = 0; dr < 2; dr++) {
                const int m  = m0 + r0 + dr;
                const int bb = m >> 11;
                const int ss = m & 2047;
                out[(((size_t)(bb * NUM_HEADS + h)) * SEQ + ss) * HEAD_DIM + e]
                    = ((dr == 0) ? v.x : v.y) + bias[nc];
            }
        }
    }
}

// ---------------------------------------------------------------------------
// Kernel 2: flash attention, 128q x 128k tiles, packed f32x2 dot-pairs.
// 256 threads as 16x16. QK^T: s2[8][8] pairs along e. PV: o2[8][4] pairs
// along kk (P stored [q][key], V stored transposed [e][key]).
// smem: Qs[128][64] | Ks[128][66] | Vt[64][130] | Ps[128][130]
// ---------------------------------------------------------------------------
#define QS_ST 64
#define KS_ST 66
#define VT_ST 130
#define PS_ST 130
#define SM_Q  0
#define SM_K  (128 * QS_ST)
#define SM_VT (SM_K + 128 * KS_ST)
#define SM_P  (SM_VT + 64 * VT_ST)
#define ATTN_SMEM_FLOATS (SM_P + 128 * PS_ST)
#define ATTN_SMEM_BYTES  (ATTN_SMEM_FLOATS * 4)

__global__ __launch_bounds__(256, 1) void attn_kernel()
{
    extern __shared__ __align__(16) float sm[];
    float* Qs = sm + SM_Q;
    float* Ks = sm + SM_K;
    float* Vt = sm + SM_VT;
    float* Ps = sm + SM_P;

    const int tid = threadIdx.x;
    const int tx = tid & 15;
    const int ty = tid >> 4;

    const int q0 = blockIdx.x * 128;
    const int bh = blockIdx.y;             // b*16 + h
    const size_t base = (size_t)bh * SEQ * HEAD_DIM;
    const float* __restrict__ Qg = g_q + base;
    const float* __restrict__ Kg = g_k + base;
    const float* __restrict__ Vg = g_v + base;

    // Load + scale Q tile (128 x 64)
    {
        const int r = tid >> 1;
        const int c = (tid & 1) * 32;
        #pragma unroll
        for (int i = 0; i < 32; i += 4) {
            float4 v = *reinterpret_cast<const float4*>(Qg + (size_t)(q0 + r) * 64 + c + i);
            v.x *= 0.125f; v.y *= 0.125f; v.z *= 0.125f; v.w *= 0.125f;
            *reinterpret_cast<float4*>(&Qs[r * QS_ST + c + i]) = v;
        }
    }

    float m_run[8], l_run[8], o_f[8][4];
    #pragma unroll
    for (int i = 0; i < 8; i++) {
        m_run[i] = -INFINITY;
        l_run[i] = 0.f;
        #pragma unroll
        for (int j = 0; j < 4; j++) o_f[i][j] = 0.f;
    }
    __syncthreads();

    for (int t = 0; t < SEQ; t += 128) {
        // Load K tile -> Ks[key][e] (stride 66, float2 stores)
        // Load V tile -> Vt[e][key] (transposed, scalar stores)
        {
            const int r = tid >> 1;
            const int c = (tid & 1) * 32;
            #pragma unroll
            for (int i = 0; i < 32; i += 4) {
                float4 kv = *reinterpret_cast<const float4*>(Kg + (size_t)(t + r) * 64 + c + i);
                *reinterpret_cast<float2*>(&Ks[r * KS_ST + c + i])     = make_float2(kv.x, kv.y);
                *reinterpret_cast<float2*>(&Ks[r * KS_ST + c + i + 2]) = make_float2(kv.z, kv.w);
                float4 vv = *reinterpret_cast<const float4*>(Vg + (size_t)(t + r) * 64 + c + i);
                Vt[(c + i + 0) * VT_ST + r] = vv.x;
                Vt[(c + i + 1) * VT_ST + r] = vv.y;
                Vt[(c + i + 2) * VT_ST + r] = vv.z;
                Vt[(c + i + 3) * VT_ST + r] = vv.w;
            }
        }
        __syncthreads();

        // --- QK^T: s2[i][j] packed pairs along e ---
        u64t s2[8][8];
        #pragma unroll
        for (int i = 0; i < 8; i++)
            #pragma unroll
            for (int j = 0; j < 8; j++) s2[i][j] = 0ull;

        #pragma unroll 1
        for (int e = 0; e < 64; e += 2) {
            u64t q2[8], k2[8];
            #pragma unroll
            for (int i = 0; i < 8; i++)
                q2[i] = *reinterpret_cast<const u64t*>(&Qs[(ty + 16 * i) * QS_ST + e]);
            #pragma unroll
            for (int j = 0; j < 8; j++)
                k2[j] = *reinterpret_cast<const u64t*>(&Ks[(tx + 16 * j) * KS_ST + e]);
            #pragma unroll
            for (int i = 0; i < 8; i++)
                #pragma unroll
                for (int j = 0; j < 8; j++)
                    s2[i][j] = fma2(q2[i], k2[j], s2[i][j]);
        }

        // Fold pairs, online softmax per row
        float s[8][8];
        #pragma unroll
        for (int i = 0; i < 8; i++) {
            #pragma unroll
            for (int j = 0; j < 8; j++) s[i][j] = fold2(s2[i][j]);

            float mx = s[i][0];
            #pragma unroll
            for (int j = 1; j < 8; j++) mx = fmaxf(mx, s[i][j]);
            #pragma unroll
            for (int off = 1; off < 16; off <<= 1)
                mx = fmaxf(mx, __shfl_xor_sync(0xffffffffu, mx, off));
            const float m_new = fmaxf(m_run[i], mx);
            const float alpha = __expf(m_run[i] - m_new);
            float sum = 0.f;
            #pragma unroll
            for (int j = 0; j < 8; j++) {
                s[i][j] = __expf(s[i][j] - m_new);
                sum += s[i][j];
            }
            #pragma unroll
            for (int off = 1; off < 16; off <<= 1)
                sum += __shfl_xor_sync(0xffffffffu, sum, off);
            l_run[i] = l_run[i] * alpha + sum;
            m_run[i] = m_new;
            #pragma unroll
            for (int j = 0; j < 4; j++) o_f[i][j] *= alpha;
        }

        // Store P[q][key] (pairs along key are contiguous for PV)
        #pragma unroll
        for (int i = 0; i < 8; i++)
            #pragma unroll
            for (int j = 0; j < 8; j++)
                Ps[(ty + 16 * i) * PS_ST + (tx + 16 * j)] = s[i][j];
        __syncthreads();

        // --- PV: o2[i][j] packed pairs along kk ---
        u64t o2[8][4];
        #pragma unroll
        for (int i = 0; i < 8; i++)
            #pragma unroll
            for (int j = 0; j < 4; j++) o2[i][j] = 0ull;

        #pragma unroll 1
        for (int kk = 0; kk < 128; kk += 2) {
            u64t p2[8], v2[4];
            #pragma unroll
            for (int i = 0; i < 8; i++)
                p2[i] = *reinterpret_cast<const u64t*>(&Ps[(ty + 16 * i) * PS_ST + kk]);
            #pragma unroll
            for (int j = 0; j < 4; j++)
                v2[j] = *reinterpret_cast<const u64t*>(&Vt[(tx + 16 * j) * VT_ST + kk]);
            #pragma unroll
            for (int i = 0; i < 8; i++)
                #pragma unroll
                for (int j = 0; j < 4; j++)
                    o2[i][j] = fma2(p2[i], v2[j], o2[i][j]);
        }
        #pragma unroll
        for (int i = 0; i < 8; i++)
            #pragma unroll
            for (int j = 0; j < 4; j++)
                o_f[i][j] += fold2(o2[i][j]);
        __syncthreads();   // done with Ks/Vt/Ps before next tile load
    }

    // Epilogue: normalize, write concat layout [b, s, h*64 + e]
    const int bb = bh >> 4;
    const int h  = bh & 15;
    #pragma unroll
    for (int i = 0; i < 8; i++) {
        const float inv = 1.f / l_run[i];
        const int q = q0 + ty + 16 * i;
        #pragma unroll
        for (int j = 0; j < 4; j++) {
            const int e = tx + 16 * j;
            g_attn[((size_t)(bb * SEQ + q)) * D_MODEL + h * HEAD_DIM + e] = o_f[i][j] * inv;
        }
    }
}

// ---------------------------------------------------------------------------
// Kernel 3: output projection with packed FFMA2. Same structure as kernel 1.
// ---------------------------------------------------------------------------
__global__ __launch_bounds__(256, 2) void out_gemm(
    const float* __restrict__ Wo, const float* __restrict__ bo,
    float* __restrict__ out)
{
    __shared__ __align__(16) float As[8][128];
    __shared__ __align__(16) float Bs[8][128];

    const int tid = threadIdx.x;
    const int tx = tid & 15;
    const int ty = tid >> 4;

    const int n0 = blockIdx.x * 128;
    const int m0 = blockIdx.y * 128;

    const int a_row = tid >> 1;
    const int a_col = (tid & 1) * 4;
    const int b_row = tid >> 5;
    const int b_col = (tid & 31) * 4;

    const float* aptr = g_attn + (size_t)(m0 + a_row) * D_MODEL + a_col;
    const float* bptr = Wo + (size_t)b_row * D_MODEL + n0 + b_col;

    u64t acc2[4][8];
    #pragma unroll
    for (int i = 0; i < 4; i++)
        #pragma unroll
        for (int j = 0; j < 8; j++) acc2[i][j] = 0ull;

    for (int k0 = 0; k0 < D_MODEL; k0 += 8) {
        float4 av  = *reinterpret_cast<const float4*>(aptr + k0);
        float4 bv4 = *reinterpret_cast<const float4*>(bptr + (size_t)k0 * D_MODEL);
        As[a_col + 0][a_row] = av.x;
        As[a_col + 1][a_row] = av.y;
        As[a_col + 2][a_row] = av.z;
        As[a_col + 3][a_row] = av.w;
        *reinterpret_cast<float4*>(&Bs[b_row][b_col]) = bv4;
        __syncthreads();

        #pragma unroll
        for (int kk = 0; kk < 8; kk++) {
            longlong2 A0 = *reinterpret_cast<const longlong2*>(&As[kk][ty * 4]);
            longlong2 A1 = *reinterpret_cast<const longlong2*>(&As[kk][64 + ty * 4]);
            float4 b0 = *reinterpret_cast<const float4*>(&Bs[kk][tx * 4]);
            float4 b1 = *reinterpret_cast<const float4*>(&Bs[kk][64 + tx * 4]);
            u64t a2[4] = {(u64t)A0.x, (u64t)A0.y, (u64t)A1.x, (u64t)A1.y};
            u64t bd[8] = {dup2(b0.x), dup2(b0.y), dup2(b0.z), dup2(b0.w),
                          dup2(b1.x), dup2(b1.y), dup2(b1.z), dup2(b1.w)};
            #pragma unroll
            for (int i = 0; i < 4; i++)
                #pragma unroll
                for (int j = 0; j < 8; j++)
                    acc2[i][j] = fma2(a2[i], bd[j], acc2[i][j]);
        }
        __syncthreads();
    }

    #pragma unroll
    for (int i2 = 0; i2 < 4; i2++) {
        const int r0 = (i2 >> 1) * 64 + ty * 4 + (i2 & 1) * 2;
        #pragma unroll
        for (int j = 0; j < 8; j++) {
            const int n = n0 + ((j < 4) ? (tx * 4 + j) : (64 + tx * 4 + j - 4));
            float2 v = unp2(acc2[i2][j]);
            out[(size_t)(m0 + r0 + 0) * D_MODEL + n] = v.x + bo[n];
            out[(size_t)(m0 + r0 + 1) * D_MODEL + n] = v.y + bo[n];
        }
    }
}

// ---------------------------------------------------------------------------
extern "C" void kernel_launch(void* const* d_in, const int* in_sizes, int n_in,
                              void* d_out, int out_size)
{
    const float* x  = (const float*)d_in[0];
    const float* Wq = (const float*)d_in[1];
    const float* bq = (const float*)d_in[2];
    const float* Wk = (const float*)d_in[3];
    const float* bk = (const float*)d_in[4];
    const float* Wv = (const float*)d_in[5];
    const float* bv = (const float*)d_in[6];
    const float* Wo = (const float*)d_in[7];
    const float* bo = (const float*)d_in[8];
    float* out = (float*)d_out;

    cudaFuncSetAttribute(attn_kernel,
                         cudaFuncAttributeMaxDynamicSharedMemorySize,
                         ATTN_SMEM_BYTES);

    // 1) QKV projections: M=8192, N=3072
    qkv_gemm<<<dim3(3 * D_MODEL / 128, M_TOTAL / 128), 256>>>(x, Wq, bq, Wk, bk, Wv, bv);

    // 2) Flash attention: 16 q-tiles x 64 (b,h) pairs
    attn_kernel<<<dim3(SEQ / 128, BATCH * NUM_HEADS), 256, ATTN_SMEM_BYTES>>>();

    // 3) Output projection: M=8192, N=1024
    out_gemm<<<dim3(D_MODEL / 128, M_TOTAL / 128), 256>>>(Wo, bo, out);
}

// round 4
// speedup vs baseline: 2.3432x; 2.1033x over previous
#include <cuda_runtime.h>
#include <cuda_bf16.h>
#include <math.h>

typedef __nv_bfloat16 bf16;

#define D_MODEL   1024
#define NUM_HEADS 16
#define HEAD_DIM  64
#define BATCH     4
#define SEQ       2048
#define M_TOTAL   (BATCH * SEQ)   // 8192
#define NQKV      (3 * D_MODEL)   // 3072
#define NBH       (BATCH * NUM_HEADS)  // 64

// ============================================================================
// Device global scratch (allocation-free rule)
// ============================================================================
__device__ bf16 g_Xh[M_TOTAL * D_MODEL], g_Xl[M_TOTAL * D_MODEL];
__device__ bf16 g_Bqkv_h[NQKV * D_MODEL], g_Bqkv_l[NQKV * D_MODEL];   // [n][k]
__device__ bf16 g_Wo_h[D_MODEL * D_MODEL], g_Wo_l[D_MODEL * D_MODEL]; // [n][k]
__device__ float g_bias_qkv[NQKV];
// attention operands, [bh][s][e] bf16 split
__device__ bf16 g_qh[NBH * SEQ * HEAD_DIM], g_ql[NBH * SEQ * HEAD_DIM];
__device__ bf16 g_kh[NBH * SEQ * HEAD_DIM], g_kl[NBH * SEQ * HEAD_DIM];
__device__ bf16 g_vh[NBH * SEQ * HEAD_DIM], g_vl[NBH * SEQ * HEAD_DIM];
// attention output (input to out-proj), [m][1024] bf16 split
__device__ bf16 g_A2h[M_TOTAL * D_MODEL], g_A2l[M_TOTAL * D_MODEL];

// ============================================================================
// mma.sync / ldmatrix helpers (portable PTX, works on compute_103)
// ============================================================================
__device__ __forceinline__ unsigned smem_u32(const void* p) {
    unsigned a;
    asm("{ .reg .u64 t; cvta.to.shared.u64 t, %1; cvt.u32.u64 %0, t; }"
        : "=r"(a) : "l"(p));
    return a;
}
__device__ __forceinline__ void ldm_x4(unsigned* r, unsigned addr) {
    asm volatile("ldmatrix.sync.aligned.m8n8.x4.shared.b16 {%0,%1,%2,%3}, [%4];"
        : "=r"(r[0]), "=r"(r[1]), "=r"(r[2]), "=r"(r[3]) : "r"(addr));
}
__device__ __forceinline__ void ldm_x4_t(unsigned* r, unsigned addr) {
    asm volatile("ldmatrix.sync.aligned.m8n8.x4.trans.shared.b16 {%0,%1,%2,%3}, [%4];"
        : "=r"(r[0]), "=r"(r[1]), "=r"(r[2]), "=r"(r[3]) : "r"(addr));
}
__device__ __forceinline__ void mma16816(float* c, const unsigned* a, const unsigned* b) {
    asm volatile("mma.sync.aligned.m16n8k16.row.col.f32.bf16.bf16.f32 "
        "{%0,%1,%2,%3}, {%4,%5,%6,%7}, {%8,%9}, {%0,%1,%2,%3};"
        : "+f"(c[0]), "+f"(c[1]), "+f"(c[2]), "+f"(c[3])
        : "r"(a[0]), "r"(a[1]), "r"(a[2]), "r"(a[3]), "r"(b[0]), "r"(b[1]));
}
// pack two floats into bf16x2 (lo -> low half)
__device__ __forceinline__ unsigned pack_bf2(float lo, float hi) {
    unsigned d;
    asm("cvt.rn.bf16x2.f32 %0, %1, %2;" : "=r"(d) : "f"(hi), "f"(lo));
    return d;
}
// split pair (v0, v1) into hi-pair and lo-pair bf16x2
__device__ __forceinline__ void split2(float v0, float v1, unsigned& ph, unsigned& pl) {
    float h0 = __bfloat162float(__float2bfloat16(v0));
    float h1 = __bfloat162float(__float2bfloat16(v1));
    ph = pack_bf2(v0, v1);
    pl = pack_bf2(v0 - h0, v1 - h1);
}

// ============================================================================
// Conversion kernels
// ============================================================================
__global__ __launch_bounds__(256) void split_x(const float* __restrict__ x) {
    size_t i = ((size_t)blockIdx.x * 256 + threadIdx.x) * 4;
    float4 v = *reinterpret_cast<const float4*>(x + i);
    float f[4] = {v.x, v.y, v.z, v.w};
    #pragma unroll
    for (int j = 0; j < 4; j++) {
        bf16 h = __float2bfloat16(f[j]);
        g_Xh[i + j] = h;
        g_Xl[i + j] = __float2bfloat16(f[j] - __bfloat162float(h));
    }
}

__global__ __launch_bounds__(256) void conv_wqkv(
    const float* __restrict__ Wq, const float* __restrict__ bq,
    const float* __restrict__ Wk, const float* __restrict__ bk,
    const float* __restrict__ Wv, const float* __restrict__ bv) {
    size_t idx = (size_t)blockIdx.x * 256 + threadIdx.x;  // n*1024 + k
    int n = (int)(idx >> 10), k = (int)(idx & 1023);
    int proj = n >> 10, nc = n & 1023, h = nc >> 6, e = nc & 63;
    const float* W = (proj == 0) ? Wq : (proj == 1) ? Wk : Wv;
    float v = W[((size_t)h * D_MODEL + k) * HEAD_DIM + e];
    bf16 hh = __float2bfloat16(v);
    g_Bqkv_h[idx] = hh;
    g_Bqkv_l[idx] = __float2bfloat16(v - __bfloat162float(hh));
    if (k == 0) {
        const float* b = (proj == 0) ? bq : (proj == 1) ? bk : bv;
        g_bias_qkv[n] = b[nc];
    }
}

__global__ __launch_bounds__(256) void conv_wo(const float* __restrict__ Wo) {
    size_t idx = (size_t)blockIdx.x * 256 + threadIdx.x;
    int n = (int)(idx >> 10), k = (int)(idx & 1023);
    float v = Wo[(size_t)k * D_MODEL + n];
    bf16 hh = __float2bfloat16(v);
    g_Wo_h[idx] = hh;
    g_Wo_l[idx] = __float2bfloat16(v - __bfloat162float(hh));
}

// ============================================================================
// GEMM on mma.sync: C[M,N] = A[M,K] * Bt[N,K]^T (+bias), fp32 acc, 3-pass split.
// CTA 128x128, 256 threads, warp grid 2(M)x4(N), warp tile 64x32.
// mode 1: A=g_X*, B=g_Bqkv*, bias=g_bias_qkv, epilogue scatters split-bf16
//         q (x0.125), k, v into [bh][s][e] arrays.
// mode 0: A=g_A2*, B=g_Wo*, bias=bias_ext, fp32 out.
// ============================================================================
#define TST 72          // smem tile stride (bf16): 144B, bank-rotating
#define MM_SA_H 0
#define MM_SA_L (128 * TST)
#define MM_SB_H (2 * 128 * TST)
#define MM_SB_L (3 * 128 * TST)
#define MM_SMEM (4 * 128 * TST * 2)   // 73728 B

__global__ __launch_bounds__(256) void mm_mma(const float* __restrict__ bias_ext,
                                              float* __restrict__ outp, int mode) {
    extern __shared__ __align__(16) bf16 smm[];
    const unsigned sbase = smem_u32(smm);
    const int tid = threadIdx.x;
    const int lane = tid & 31;
    const int w = tid >> 5;
    const int mw = w >> 2, nw = w & 3;
    const int n0 = blockIdx.x * 128;
    const int m0 = blockIdx.y * 128;

    const bf16* __restrict__ Ahg = (mode == 1) ? g_Xh : g_A2h;
    const bf16* __restrict__ Alg = (mode == 1) ? g_Xl : g_A2l;
    const bf16* __restrict__ Bhg = (mode == 1) ? g_Bqkv_h : g_Wo_h;
    const bf16* __restrict__ Blg = (mode == 1) ? g_Bqkv_l : g_Wo_l;
    const float* __restrict__ bias = (mode == 1) ? g_bias_qkv : bias_ext;

    float acc[4][4][4];
    #pragma unroll
    for (int a = 0; a < 4; a++)
        #pragma unroll
        for (int b = 0; b < 4; b++)
            #pragma unroll
            for (int c = 0; c < 4; c++) acc[a][b][c] = 0.f;

    for (int kc = 0; kc < 16; kc++) {
        const int k0 = kc * 64;
        // load A/B hi+lo tiles: 128 rows x 64 bf16 each
        #pragma unroll
        for (int i = 0; i < 4; i++) {
            const int t = tid + 256 * i;
            const int row = t >> 3, slot = t & 7;
            const int so = row * TST + slot * 8;
            const size_t ga = (size_t)(m0 + row) * D_MODEL + k0 + slot * 8;
            const size_t gb = (size_t)(n0 + row) * D_MODEL + k0 + slot * 8;
            *reinterpret_cast<float4*>(smm + MM_SA_H + so) = *reinterpret_cast<const float4*>(Ahg + ga);
            *reinterpret_cast<float4*>(smm + MM_SA_L + so) = *reinterpret_cast<const float4*>(Alg + ga);
            *reinterpret_cast<float4*>(smm + MM_SB_H + so) = *reinterpret_cast<const float4*>(Bhg + gb);
            *reinterpret_cast<float4*>(smm + MM_SB_L + so) = *reinterpret_cast<const float4*>(Blg + gb);
        }
        __syncthreads();

        #pragma unroll
        for (int ks = 0; ks < 4; ks++) {
            unsigned ah[4][4], al[4][4], bh[4][2], bl[4][2];
            const int arow = mw * 64 + (lane & 15);
            const int acol = ks * 16 + (lane >> 4) * 8;
            #pragma unroll
            for (int mt = 0; mt < 4; mt++) {
                const unsigned off = 2u * ((arow + mt * 16) * TST + acol);
                ldm_x4(ah[mt], sbase + 2 * MM_SA_H + off);
                ldm_x4(al[mt], sbase + 2 * MM_SA_L + off);
            }
            const int g = lane >> 3;
            const int browo = (g >> 1) * 8 + (lane & 7);
            const int bko = (g & 1) * 8;
            #pragma unroll
            for (int np = 0; np < 2; np++) {
                const unsigned off = 2u * ((nw * 32 + np * 16 + browo) * TST + ks * 16 + bko);
                ldm_x4(&bh[np * 2][0], sbase + 2 * MM_SB_H + off);
                ldm_x4(&bl[np * 2][0], sbase + 2 * MM_SB_L + off);
            }
            #pragma unroll
            for (int mt = 0; mt < 4; mt++)
                #pragma unroll
                for (int nt = 0; nt < 4; nt++) {
                    mma16816(acc[mt][nt], ah[mt], bh[nt]);
                    mma16816(acc[mt][nt], ah[mt], bl[nt]);
                    mma16816(acc[mt][nt], al[mt], bh[nt]);
                }
        }
        __syncthreads();
    }

    // Epilogue
    #pragma unroll
    for (int mt = 0; mt < 4; mt++) {
        const int r0 = m0 + mw * 64 + mt * 16 + (lane >> 2);
        #pragma unroll
        for (int nt = 0; nt < 4; nt++) {
            const int c = n0 + nw * 32 + nt * 8 + (lane & 3) * 2;
            const float b0 = bias[c], b1 = bias[c + 1];
            #pragma unroll
            for (int h2 = 0; h2 < 2; h2++) {
                const int r = r0 + h2 * 8;
                float v0 = acc[mt][nt][h2 * 2 + 0] + b0;
                float v1 = acc[mt][nt][h2 * 2 + 1] + b1;
                if (mode == 0) {
                    float2 vv = make_float2(v0, v1);
                    *reinterpret_cast<float2*>(outp + (size_t)r * D_MODEL + c) = vv;
                } else {
                    const int proj = c >> 10, nc = c & 1023, hh = nc >> 6, e = nc & 63;
                    if (proj == 0) { v0 *= 0.125f; v1 *= 0.125f; }
                    bf16* dh = (proj == 0) ? g_qh : (proj == 1) ? g_kh : g_vh;
                    bf16* dl = (proj == 0) ? g_ql : (proj == 1) ? g_kl : g_vl;
                    const size_t idx =
                        (((size_t)((r >> 11) * NUM_HEADS + hh)) * SEQ + (r & 2047)) * HEAD_DIM + e;
                    unsigned ph, pl;
                    split2(v0, v1, ph, pl);
                    *reinterpret_cast<unsigned*>(dh + idx) = ph;
                    *reinterpret_cast<unsigned*>(dl + idx) = pl;
                }
            }
        }
    }
}

// ============================================================================
// Flash attention on mma.sync, split-bf16 3-pass for QK^T and PV.
// CTA: 128 q x 128 k tile; 8 warps 2(M)x4(N).
// ============================================================================
#define PST 136   // P smem stride (272B, bank-rotating)
// bf16-element offsets in dynamic smem
#define AT_QH 0
#define AT_QL (128 * TST)
#define AT_KH (2 * 128 * TST)
#define AT_KL (3 * 128 * TST)
#define AT_VH (4 * 128 * TST)
#define AT_VL (5 * 128 * TST)
#define AT_PH (6 * 128 * TST)
#define AT_PL (AT_PH + 128 * PST)
#define AT_BF_END (AT_PL + 128 * PST)
// float arrays after the bf16 region
#define AT_FLT (AT_BF_END / 2)            // float index base (AT_BF_END is even)
#define ATF_M  (AT_FLT + 0)               // sm_m[128]
#define ATF_L  (AT_FLT + 128)             // sm_l[128]
#define ATF_RM (AT_FLT + 256)             // redm[128*4]
#define ATF_RS (AT_FLT + 768)             // reds[128*4]
#define ATTN_SMEM (AT_BF_END * 2 + 1280 * 4)

__global__ __launch_bounds__(256) void attn_mma() {
    extern __shared__ __align__(16) bf16 smm[];
    float* smf = reinterpret_cast<float*>(smm);
    const unsigned sbase = smem_u32(smm);
    const int tid = threadIdx.x;
    const int lane = tid & 31;
    const int w = tid >> 5;
    const int mw = w >> 2, nw = w & 3;
    const int q0 = blockIdx.x * 128;
    const int bh = blockIdx.y;
    const size_t gbase = (size_t)bh * SEQ * HEAD_DIM;

    // Load Q tile (hi+lo), init row state
    #pragma unroll
    for (int i = 0; i < 4; i++) {
        const int t = tid + 256 * i;
        const int row = t >> 3, slot = t & 7;
        const int so = row * TST + slot * 8;
        const size_t gq = gbase + (size_t)(q0 + row) * HEAD_DIM + slot * 8;
        *reinterpret_cast<float4*>(smm + AT_QH + so) = *reinterpret_cast<const float4*>(g_qh + gq);
        *reinterpret_cast<float4*>(smm + AT_QL + so) = *reinterpret_cast<const float4*>(g_ql + gq);
    }
    if (tid < 128) { smf[ATF_M + tid] = -INFINITY; smf[ATF_L + tid] = 0.f; }
    __syncthreads();

    float oacc[4][2][4];
    #pragma unroll
    for (int a = 0; a < 4; a++)
        #pragma unroll
        for (int b = 0; b < 2; b++)
            #pragma unroll
            for (int c = 0; c < 4; c++) oacc[a][b][c] = 0.f;

    const int rbase = mw * 64 + (lane >> 2);

    for (int kt = 0; kt < 16; kt++) {
        const int t0 = kt * 128;
        // load K & V tiles (hi+lo)
        #pragma unroll
        for (int i = 0; i < 4; i++) {
            const int t = tid + 256 * i;
            const int row = t >> 3, slot = t & 7;
            const int so = row * TST + slot * 8;
            const size_t gk = gbase + (size_t)(t0 + row) * HEAD_DIM + slot * 8;
            *reinterpret_cast<float4*>(smm + AT_KH + so) = *reinterpret_cast<const float4*>(g_kh + gk);
            *reinterpret_cast<float4*>(smm + AT_KL + so) = *reinterpret_cast<const float4*>(g_kl + gk);
            *reinterpret_cast<float4*>(smm + AT_VH + so) = *reinterpret_cast<const float4*>(g_vh + gk);
            *reinterpret_cast<float4*>(smm + AT_VL + so) = *reinterpret_cast<const float4*>(g_vl + gk);
        }
        __syncthreads();

        // ---- S = Q K^T (3-pass split) ----
        float sacc[4][4][4];
        #pragma unroll
        for (int a = 0; a < 4; a++)
            #pragma unroll
            for (int b = 0; b < 4; b++)
                #pragma unroll
                for (int c = 0; c < 4; c++) sacc[a][b][c] = 0.f;

        #pragma unroll
        for (int ks = 0; ks < 4; ks++) {
            unsigned qh[4][4], ql[4][4], kh[4][2], kl[4][2];
            const int arow = mw * 64 + (lane & 15);
            const int acol = ks * 16 + (lane >> 4) * 8;
            #pragma unroll
            for (int mt = 0; mt < 4; mt++) {
                const unsigned off = 2u * ((arow + mt * 16) * TST + acol);
                ldm_x4(qh[mt], sbase + 2 * AT_QH + off);
                ldm_x4(ql[mt], sbase + 2 * AT_QL + off);
            }
            const int g = lane >> 3;
            const int browo = (g >> 1) * 8 + (lane & 7);
            const int bko = (g & 1) * 8;
            #pragma unroll
            for (int np = 0; np < 2; np++) {
                const unsigned off = 2u * ((nw * 32 + np * 16 + browo) * TST + ks * 16 + bko);
                ldm_x4(&kh[np * 2][0], sbase + 2 * AT_KH + off);
                ldm_x4(&kl[np * 2][0], sbase + 2 * AT_KL + off);
            }
            #pragma unroll
            for (int mt = 0; mt < 4; mt++)
                #pragma unroll
                for (int nt = 0; nt < 4; nt++) {
                    mma16816(sacc[mt][nt], qh[mt], kh[nt]);
                    mma16816(sacc[mt][nt], qh[mt], kl[nt]);
                    mma16816(sacc[mt][nt], ql[mt], kh[nt]);
                }
        }

        // ---- online softmax ----
        // per-warp row max partials
        #pragma unroll
        for (int mt = 0; mt < 4; mt++) {
            float mx0 = -INFINITY, mx1 = -INFINITY;
            #pragma unroll
            for (int nt = 0; nt < 4; nt++) {
                mx0 = fmaxf(mx0, fmaxf(sacc[mt][nt][0], sacc[mt][nt][1]));
                mx1 = fmaxf(mx1, fmaxf(sacc[mt][nt][2], sacc[mt][nt][3]));
            }
            mx0 = fmaxf(mx0, __shfl_xor_sync(0xffffffffu, mx0, 1));
            mx0 = fmaxf(mx0, __shfl_xor_sync(0xffffffffu, mx0, 2));
            mx1 = fmaxf(mx1, __shfl_xor_sync(0xffffffffu, mx1, 1));
            mx1 = fmaxf(mx1, __shfl_xor_sync(0xffffffffu, mx1, 2));
            if ((lane & 3) == 0) {
                smf[ATF_RM + (rbase + mt * 16) * 4 + nw] = mx0;
                smf[ATF_RM + (rbase + mt * 16 + 8) * 4 + nw] = mx1;
            }
        }
        __syncthreads();

        float mnew[4][2], alpha[4][2];
        #pragma unroll
        for (int mt = 0; mt < 4; mt++)
            #pragma unroll
            for (int h2 = 0; h2 < 2; h2++) {
                const int r = rbase + mt * 16 + h2 * 8;
                const float* rm = smf + ATF_RM + r * 4;
                const float mx = fmaxf(fmaxf(rm[0], rm[1]), fmaxf(rm[2], rm[3]));
                const float mo = smf[ATF_M + r];
                const float mn = fmaxf(mo, mx);
                mnew[mt][h2] = mn;
                alpha[mt][h2] = __expf(mo - mn);
            }

        // P = exp(S - m), row-sum partials, store split P to smem
        float rs[4][2];
        #pragma unroll
        for (int mt = 0; mt < 4; mt++) { rs[mt][0] = 0.f; rs[mt][1] = 0.f; }
        #pragma unroll
        for (int mt = 0; mt < 4; mt++) {
            const int rA = rbase + mt * 16;
            #pragma unroll
            for (int nt = 0; nt < 4; nt++) {
                const int col = nw * 32 + nt * 8 + (lane & 3) * 2;
                const float p0 = __expf(sacc[mt][nt][0] - mnew[mt][0]);
                const float p1 = __expf(sacc[mt][nt][1] - mnew[mt][0]);
                const float p2 = __expf(sacc[mt][nt][2] - mnew[mt][1]);
                const float p3 = __expf(sacc[mt][nt][3] - mnew[mt][1]);
                rs[mt][0] += p0 + p1;
                rs[mt][1] += p2 + p3;
                unsigned ph, pl;
                split2(p0, p1, ph, pl);
                *reinterpret_cast<unsigned*>(smm + AT_PH + rA * PST + col) = ph;
                *reinterpret_cast<unsigned*>(smm + AT_PL + rA * PST + col) = pl;
                split2(p2, p3, ph, pl);
                *reinterpret_cast<unsigned*>(smm + AT_PH + (rA + 8) * PST + col) = ph;
                *reinterpret_cast<unsigned*>(smm + AT_PL + (rA + 8) * PST + col) = pl;
            }
        }
        #pragma unroll
        for (int mt = 0; mt < 4; mt++)
            #pragma unroll
            for (int h2 = 0; h2 < 2; h2++) {
                float v = rs[mt][h2];
                v += __shfl_xor_sync(0xffffffffu, v, 1);
                v += __shfl_xor_sync(0xffffffffu, v, 2);
                if ((lane & 3) == 0)
                    smf[ATF_RS + (rbase + mt * 16 + h2 * 8) * 4 + nw] = v;
            }
        // rescale O
        #pragma unroll
        for (int mt = 0; mt < 4; mt++)
            #pragma unroll
            for (int nt2 = 0; nt2 < 2; nt2++) {
                oacc[mt][nt2][0] *= alpha[mt][0];
                oacc[mt][nt2][1] *= alpha[mt][0];
                oacc[mt][nt2][2] *= alpha[mt][1];
                oacc[mt][nt2][3] *= alpha[mt][1];
            }
        __syncthreads();

        // row-state update (single owner per row)
        if (nw == 0 && (lane & 3) == 0) {
            #pragma unroll
            for (int mt = 0; mt < 4; mt++)
                #pragma unroll
                for (int h2 = 0; h2 < 2; h2++) {
                    const int r = rbase + mt * 16 + h2 * 8;
                    const float* rsm = smf + ATF_RS + r * 4;
                    smf[ATF_L + r] = smf[ATF_L + r] * alpha[mt][h2]
                                     + rsm[0] + rsm[1] + rsm[2] + rsm[3];
                    smf[ATF_M + r] = mnew[mt][h2];
                }
        }

        // ---- O += P V (3-pass split), K-dim = 128 keys ----
        #pragma unroll
        for (int ks = 0; ks < 8; ks++) {
            unsigned ph[4][4], pl[4][4], vh[2][2], vl[2][2];
            const int arow = mw * 64 + (lane & 15);
            const int acol = ks * 16 + (lane >> 4) * 8;
            #pragma unroll
            for (int mt = 0; mt < 4; mt++) {
                const unsigned off = 2u * ((arow + mt * 16) * PST + acol);
                ldm_x4(ph[mt], sbase + 2 * AT_PH + off);
                ldm_x4(pl[mt], sbase + 2 * AT_PL + off);
            }
            const int g = lane >> 3;
            const int kr = ks * 16 + (g & 1) * 8 + (lane & 7);
            const int ec = nw * 16 + (g >> 1) * 8;
            const unsigned voff = 2u * (kr * TST + ec);
            ldm_x4_t(&vh[0][0], sbase + 2 * AT_VH + voff);
            ldm_x4_t(&vl[0][0], sbase + 2 * AT_VL + voff);
            #pragma unroll
            for (int mt = 0; mt < 4; mt++)
                #pragma unroll
                for (int nt2 = 0; nt2 < 2; nt2++) {
                    mma16816(oacc[mt][nt2], ph[mt], vh[nt2]);
                    mma16816(oacc[mt][nt2], ph[mt], vl[nt2]);
                    mma16816(oacc[mt][nt2], pl[mt], vh[nt2]);
                }
        }
        __syncthreads();
    }

    // Epilogue: normalize, split to bf16, write g_A2 (concat layout)
    const int bb = bh >> 4, hh = bh & 15;
    #pragma unroll
    for (int mt = 0; mt < 4; mt++) {
        #pragma unroll
        for (int h2 = 0; h2 < 2; h2++) {
            const int r = rbase + mt * 16 + h2 * 8;
            const float inv = 1.f / smf[ATF_L + r];
            const size_t mrow = ((size_t)bb * SEQ + q0 + r) * D_MODEL + hh * HEAD_DIM;
            #pragma unroll
            for (int nt2 = 0; nt2 < 2; nt2++) {
                const int e = nw * 16 + nt2 * 8 + (lane & 3) * 2;
                const float v0 = oacc[mt][nt2][h2 * 2 + 0] * inv;
                const float v1 = oacc[mt][nt2][h2 * 2 + 1] * inv;
                unsigned ph, pl;
                split2(v0, v1, ph, pl);
                *reinterpret_cast<unsigned*>(g_A2h + mrow + e) = ph;
                *reinterpret_cast<unsigned*>(g_A2l + mrow + e) = pl;
            }
        }
    }
}

// ============================================================================
extern "C" void kernel_launch(void* const* d_in, const int* in_sizes, int n_in,
                              void* d_out, int out_size)
{
    const float* x  = (const float*)d_in[0];
    const float* Wq = (const float*)d_in[1];
    const float* bq = (const float*)d_in[2];
    const float* Wk = (const float*)d_in[3];
    const float* bk = (const float*)d_in[4];
    const float* Wv = (const float*)d_in[5];
    const float* bv = (const float*)d_in[6];
    const float* Wo = (const float*)d_in[7];
    const float* bo = (const float*)d_in[8];
    float* out = (float*)d_out;

    cudaFuncSetAttribute(mm_mma, cudaFuncAttributeMaxDynamicSharedMemorySize, MM_SMEM);
    cudaFuncSetAttribute(attn_mma, cudaFuncAttributeMaxDynamicSharedMemorySize, ATTN_SMEM);

    // conversions
    split_x<<<(M_TOTAL * D_MODEL) / 1024, 256>>>(x);
    conv_wqkv<<<(NQKV * D_MODEL) / 256, 256>>>(Wq, bq, Wk, bk, Wv, bv);
    conv_wo<<<(D_MODEL * D_MODEL) / 256, 256>>>(Wo);

    // QKV projection (M=8192, N=3072)
    mm_mma<<<dim3(NQKV / 128, M_TOTAL / 128), 256, MM_SMEM>>>(nullptr, nullptr, 1);

    // attention
    attn_mma<<<dim3(SEQ / 128, NBH), 256, ATTN_SMEM>>>();

    // output projection (N=1024)
    mm_mma<<<dim3(D_MODEL / 128, M_TOTAL / 128), 256, MM_SMEM>>>(bo, out, 0);
}

// round 5
// speedup vs baseline: 2.8594x; 1.2203x over previous
#include <cuda_runtime.h>
#include <cuda_bf16.h>
#include <math.h>

typedef __nv_bfloat16 bf16;

#define D_MODEL   1024
#define NUM_HEADS 16
#define HEAD_DIM  64
#define BATCH     4
#define SEQ       2048
#define M_TOTAL   (BATCH * SEQ)   // 8192
#define NQKV      (3 * D_MODEL)   // 3072
#define NBH       (BATCH * NUM_HEADS)  // 64

// ============================================================================
// Device global scratch (allocation-free rule)
// ============================================================================
__device__ bf16 g_Xh[M_TOTAL * D_MODEL], g_Xl[M_TOTAL * D_MODEL];
__device__ bf16 g_Bqkv_h[NQKV * D_MODEL], g_Bqkv_l[NQKV * D_MODEL];   // [n][k]
__device__ bf16 g_Wo_h[D_MODEL * D_MODEL], g_Wo_l[D_MODEL * D_MODEL]; // [n][k]
__device__ float g_bias_qkv[NQKV];
__device__ bf16 g_qh[NBH * SEQ * HEAD_DIM], g_ql[NBH * SEQ * HEAD_DIM];
__device__ bf16 g_kh[NBH * SEQ * HEAD_DIM], g_kl[NBH * SEQ * HEAD_DIM];
__device__ bf16 g_vh[NBH * SEQ * HEAD_DIM], g_vl[NBH * SEQ * HEAD_DIM];
__device__ bf16 g_A2h[M_TOTAL * D_MODEL], g_A2l[M_TOTAL * D_MODEL];

// ============================================================================
// PTX helpers (portable, compute_103-safe)
// ============================================================================
__device__ __forceinline__ unsigned smem_u32(const void* p) {
    unsigned a;
    asm("{ .reg .u64 t; cvta.to.shared.u64 t, %1; cvt.u32.u64 %0, t; }"
        : "=r"(a) : "l"(p));
    return a;
}
__device__ __forceinline__ void ldm_x4(unsigned* r, unsigned addr) {
    asm volatile("ldmatrix.sync.aligned.m8n8.x4.shared.b16 {%0,%1,%2,%3}, [%4];"
        : "=r"(r[0]), "=r"(r[1]), "=r"(r[2]), "=r"(r[3]) : "r"(addr));
}
__device__ __forceinline__ void ldm_x4_t(unsigned* r, unsigned addr) {
    asm volatile("ldmatrix.sync.aligned.m8n8.x4.trans.shared.b16 {%0,%1,%2,%3}, [%4];"
        : "=r"(r[0]), "=r"(r[1]), "=r"(r[2]), "=r"(r[3]) : "r"(addr));
}
__device__ __forceinline__ void mma16816(float* c, const unsigned* a, const unsigned* b) {
    asm volatile("mma.sync.aligned.m16n8k16.row.col.f32.bf16.bf16.f32 "
        "{%0,%1,%2,%3}, {%4,%5,%6,%7}, {%8,%9}, {%0,%1,%2,%3};"
        : "+f"(c[0]), "+f"(c[1]), "+f"(c[2]), "+f"(c[3])
        : "r"(a[0]), "r"(a[1]), "r"(a[2]), "r"(a[3]), "r"(b[0]), "r"(b[1]));
}
__device__ __forceinline__ void cp_async16(unsigned saddr, const void* gptr) {
    asm volatile("cp.async.cg.shared.global [%0], [%1], 16;"
                 :: "r"(saddr), "l"(gptr) : "memory");
}
#define CP_COMMIT() asm volatile("cp.async.commit_group;" ::: "memory")
#define CP_WAIT(N)  asm volatile("cp.async.wait_group %0;" :: "n"(N) : "memory")

__device__ __forceinline__ unsigned pack_bf2(float lo, float hi) {
    unsigned d;
    asm("cvt.rn.bf16x2.f32 %0, %1, %2;" : "=r"(d) : "f"(hi), "f"(lo));
    return d;
}
__device__ __forceinline__ void split2(float v0, float v1, unsigned& ph, unsigned& pl) {
    float h0 = __bfloat162float(__float2bfloat16(v0));
    float h1 = __bfloat162float(__float2bfloat16(v1));
    ph = pack_bf2(v0, v1);
    pl = pack_bf2(v0 - h0, v1 - h1);
}

// ============================================================================
// Conversion kernels
// ============================================================================
__global__ __launch_bounds__(256) void split_x(const float* __restrict__ x) {
    size_t i = ((size_t)blockIdx.x * 256 + threadIdx.x) * 4;
    float4 v = *reinterpret_cast<const float4*>(x + i);
    float f[4] = {v.x, v.y, v.z, v.w};
    #pragma unroll
    for (int j = 0; j < 4; j++) {
        bf16 h = __float2bfloat16(f[j]);
        g_Xh[i + j] = h;
        g_Xl[i + j] = __float2bfloat16(f[j] - __bfloat162float(h));
    }
}

__global__ __launch_bounds__(256) void conv_wqkv(
    const float* __restrict__ Wq, const float* __restrict__ bq,
    const float* __restrict__ Wk, const float* __restrict__ bk,
    const float* __restrict__ Wv, const float* __restrict__ bv) {
    size_t idx = (size_t)blockIdx.x * 256 + threadIdx.x;  // n*1024 + k
    int n = (int)(idx >> 10), k = (int)(idx & 1023);
    int proj = n >> 10, nc = n & 1023, h = nc >> 6, e = nc & 63;
    const float* W = (proj == 0) ? Wq : (proj == 1) ? Wk : Wv;
    float v = W[((size_t)h * D_MODEL + k) * HEAD_DIM + e];
    bf16 hh = __float2bfloat16(v);
    g_Bqkv_h[idx] = hh;
    g_Bqkv_l[idx] = __float2bfloat16(v - __bfloat162float(hh));
    if (k == 0) {
        const float* b = (proj == 0) ? bq : (proj == 1) ? bk : bv;
        g_bias_qkv[n] = b[nc];
    }
}

__global__ __launch_bounds__(256) void conv_wo(const float* __restrict__ Wo) {
    size_t idx = (size_t)blockIdx.x * 256 + threadIdx.x;
    int n = (int)(idx >> 10), k = (int)(idx & 1023);
    float v = Wo[(size_t)k * D_MODEL + n];
    bf16 hh = __float2bfloat16(v);
    g_Wo_h[idx] = hh;
    g_Wo_l[idx] = __float2bfloat16(v - __bfloat162float(hh));
}

// ============================================================================
// GEMM on mma.sync with cp.async 2-stage pipeline.
// CTA 128x128, 256 threads, warps 2(M)x4(N), warp tile 64x32, 3-pass split.
// ============================================================================
#define TST 72
#define MM_SA_H 0
#define MM_SA_L (128 * TST)
#define MM_SB_H (2 * 128 * TST)
#define MM_SB_L (3 * 128 * TST)
#define STAGE_EL (4 * 128 * TST)          // 36864 elements / 73728 B
#define MM_SMEM  (2 * STAGE_EL * 2)       // 147456 B

__global__ __launch_bounds__(256) void mm_mma(const float* __restrict__ bias_ext,
                                              float* __restrict__ outp, int mode) {
    extern __shared__ __align__(16) bf16 smm[];
    const unsigned sbase = smem_u32(smm);
    const int tid = threadIdx.x;
    const int lane = tid & 31;
    const int w = tid >> 5;
    const int mw = w >> 2, nw = w & 3;
    const int n0 = blockIdx.x * 128;
    const int m0 = blockIdx.y * 128;

    const bf16* __restrict__ Ahg = (mode == 1) ? g_Xh : g_A2h;
    const bf16* __restrict__ Alg = (mode == 1) ? g_Xl : g_A2l;
    const bf16* __restrict__ Bhg = (mode == 1) ? g_Bqkv_h : g_Wo_h;
    const bf16* __restrict__ Blg = (mode == 1) ? g_Bqkv_l : g_Wo_l;
    const float* __restrict__ bias = (mode == 1) ? g_bias_qkv : bias_ext;

    float acc[4][4][4];
    #pragma unroll
    for (int a = 0; a < 4; a++)
        #pragma unroll
        for (int b = 0; b < 4; b++)
            #pragma unroll
            for (int c = 0; c < 4; c++) acc[a][b][c] = 0.f;

    // per-thread load coords (row, slot) reused every chunk
    auto issue = [&](int kc, int st) {
        const int k0 = kc * 64;
        const unsigned sst = sbase + (unsigned)(2 * STAGE_EL) * st;
        #pragma unroll
        for (int i = 0; i < 4; i++) {
            const int t = tid + 256 * i;
            const int row = t >> 3, slot = t & 7;
            const unsigned so = 2u * (row * TST + slot * 8);
            const size_t ga = (size_t)(m0 + row) * D_MODEL + k0 + slot * 8;
            const size_t gb = (size_t)(n0 + row) * D_MODEL + k0 + slot * 8;
            cp_async16(sst + 2u * MM_SA_H + so, Ahg + ga);
            cp_async16(sst + 2u * MM_SA_L + so, Alg + ga);
            cp_async16(sst + 2u * MM_SB_H + so, Bhg + gb);
            cp_async16(sst + 2u * MM_SB_L + so, Blg + gb);
        }
    };

    issue(0, 0);
    CP_COMMIT();

    for (int kc = 0; kc < 16; kc++) {
        if (kc < 15) { issue(kc + 1, (kc + 1) & 1); CP_COMMIT(); }
        if (kc < 15) { CP_WAIT(1); } else { CP_WAIT(0); }
        __syncthreads();

        const unsigned sst = sbase + (unsigned)(2 * STAGE_EL) * (kc & 1);
        #pragma unroll
        for (int ks = 0; ks < 4; ks++) {
            unsigned ah[4][4], al[4][4], bh[4][2], bl[4][2];
            const int arow = mw * 64 + (lane & 15);
            const int acol = ks * 16 + (lane >> 4) * 8;
            #pragma unroll
            for (int mt = 0; mt < 4; mt++) {
                const unsigned off = 2u * ((arow + mt * 16) * TST + acol);
                ldm_x4(ah[mt], sst + 2 * MM_SA_H + off);
                ldm_x4(al[mt], sst + 2 * MM_SA_L + off);
            }
            const int g = lane >> 3;
            const int browo = (g >> 1) * 8 + (lane & 7);
            const int bko = (g & 1) * 8;
            #pragma unroll
            for (int np = 0; np < 2; np++) {
                const unsigned off = 2u * ((nw * 32 + np * 16 + browo) * TST + ks * 16 + bko);
                ldm_x4(&bh[np * 2][0], sst + 2 * MM_SB_H + off);
                ldm_x4(&bl[np * 2][0], sst + 2 * MM_SB_L + off);
            }
            #pragma unroll
            for (int mt = 0; mt < 4; mt++)
                #pragma unroll
                for (int nt = 0; nt < 4; nt++) {
                    mma16816(acc[mt][nt], ah[mt], bh[nt]);
                    mma16816(acc[mt][nt], ah[mt], bl[nt]);
                    mma16816(acc[mt][nt], al[mt], bh[nt]);
                }
        }
        __syncthreads();
    }

    // Epilogue
    #pragma unroll
    for (int mt = 0; mt < 4; mt++) {
        const int r0 = m0 + mw * 64 + mt * 16 + (lane >> 2);
        #pragma unroll
        for (int nt = 0; nt < 4; nt++) {
            const int c = n0 + nw * 32 + nt * 8 + (lane & 3) * 2;
            const float b0 = bias[c], b1 = bias[c + 1];
            #pragma unroll
            for (int h2 = 0; h2 < 2; h2++) {
                const int r = r0 + h2 * 8;
                float v0 = acc[mt][nt][h2 * 2 + 0] + b0;
                float v1 = acc[mt][nt][h2 * 2 + 1] + b1;
                if (mode == 0) {
                    float2 vv = make_float2(v0, v1);
                    *reinterpret_cast<float2*>(outp + (size_t)r * D_MODEL + c) = vv;
                } else {
                    const int proj = c >> 10, nc = c & 1023, hh = nc >> 6, e = nc & 63;
                    if (proj == 0) { v0 *= 0.125f; v1 *= 0.125f; }
                    bf16* dh = (proj == 0) ? g_qh : (proj == 1) ? g_kh : g_vh;
                    bf16* dl = (proj == 0) ? g_ql : (proj == 1) ? g_kl : g_vl;
                    const size_t idx =
                        (((size_t)((r >> 11) * NUM_HEADS + hh)) * SEQ + (r & 2047)) * HEAD_DIM + e;
                    unsigned ph, pl;
                    split2(v0, v1, ph, pl);
                    *reinterpret_cast<unsigned*>(dh + idx) = ph;
                    *reinterpret_cast<unsigned*>(dl + idx) = pl;
                }
            }
        }
    }
}

// ============================================================================
// Flash attention on mma.sync with cp.async pipelining.
// K double-buffered (prefetch next tile); V async, hidden under S+softmax.
// ============================================================================
#define PST 136
// bf16-element offsets
#define AT_QH 0
#define AT_QL 9216
#define AT_KH(s) (18432 + (s) * 18432)
#define AT_KL(s) (27648 + (s) * 18432)
#define AT_VH 55296
#define AT_VL 64512
#define AT_PH 73728
#define AT_PL 91136
#define AT_BF_END 108544
// float indices
#define AT_FLT (AT_BF_END / 2)
#define ATF_M  (AT_FLT + 0)
#define ATF_L  (AT_FLT + 128)
#define ATF_RM (AT_FLT + 256)
#define ATF_RS (AT_FLT + 768)
#define ATTN_SMEM (AT_BF_END * 2 + 1280 * 4)   // 222208 B

__global__ __launch_bounds__(256) void attn_mma() {
    extern __shared__ __align__(16) bf16 smm[];
    float* smf = reinterpret_cast<float*>(smm);
    const unsigned sbase = smem_u32(smm);
    const int tid = threadIdx.x;
    const int lane = tid & 31;
    const int w = tid >> 5;
    const int mw = w >> 2, nw = w & 3;
    const int q0 = blockIdx.x * 128;
    const int bh = blockIdx.y;
    const size_t gbase = (size_t)bh * SEQ * HEAD_DIM;

    auto issueK = [&](int kt2, int st) {
        const int t0 = kt2 * 128;
        #pragma unroll
        for (int i = 0; i < 4; i++) {
            const int t = tid + 256 * i;
            const int row = t >> 3, slot = t & 7;
            const unsigned so = 2u * (row * TST + slot * 8);
            const size_t gk = gbase + (size_t)(t0 + row) * HEAD_DIM + slot * 8;
            cp_async16(sbase + 2u * AT_KH(st) + so, g_kh + gk);
            cp_async16(sbase + 2u * AT_KL(st) + so, g_kl + gk);
        }
    };
    auto issueV = [&](int kt2) {
        const int t0 = kt2 * 128;
        #pragma unroll
        for (int i = 0; i < 4; i++) {
            const int t = tid + 256 * i;
            const int row = t >> 3, slot = t & 7;
            const unsigned so = 2u * (row * TST + slot * 8);
            const size_t gk = gbase + (size_t)(t0 + row) * HEAD_DIM + slot * 8;
            cp_async16(sbase + 2u * AT_VH + so, g_vh + gk);
            cp_async16(sbase + 2u * AT_VL + so, g_vl + gk);
        }
    };

    // prefetch K tile 0
    issueK(0, 0);
    CP_COMMIT();

    // load Q tile (hi+lo), init row state
    #pragma unroll
    for (int i = 0; i < 4; i++) {
        const int t = tid + 256 * i;
        const int row = t >> 3, slot = t & 7;
        const int so = row * TST + slot * 8;
        const size_t gq = gbase + (size_t)(q0 + row) * HEAD_DIM + slot * 8;
        *reinterpret_cast<float4*>(smm + AT_QH + so) = *reinterpret_cast<const float4*>(g_qh + gq);
        *reinterpret_cast<float4*>(smm + AT_QL + so) = *reinterpret_cast<const float4*>(g_ql + gq);
    }
    if (tid < 128) { smf[ATF_M + tid] = -INFINITY; smf[ATF_L + tid] = 0.f; }

    float oacc[4][2][4];
    #pragma unroll
    for (int a = 0; a < 4; a++)
        #pragma unroll
        for (int b = 0; b < 2; b++)
            #pragma unroll
            for (int c = 0; c < 4; c++) oacc[a][b][c] = 0.f;

    const int rbase = mw * 64 + (lane >> 2);

    for (int kt = 0; kt < 16; kt++) {
        // async: V of this tile + K of next tile
        issueV(kt);
        CP_COMMIT();
        if (kt < 15) { issueK(kt + 1, (kt + 1) & 1); CP_COMMIT(); }
        // wait for K[kt] (leave V, K-next in flight)
        if (kt < 15) { CP_WAIT(2); } else { CP_WAIT(1); }
        __syncthreads();

        const unsigned skh = sbase + 2u * AT_KH(kt & 1);
        const unsigned skl = sbase + 2u * AT_KL(kt & 1);

        // ---- S = Q K^T (3-pass split) ----
        float sacc[4][4][4];
        #pragma unroll
        for (int a = 0; a < 4; a++)
            #pragma unroll
            for (int b = 0; b < 4; b++)
                #pragma unroll
                for (int c = 0; c < 4; c++) sacc[a][b][c] = 0.f;

        #pragma unroll
        for (int ks = 0; ks < 4; ks++) {
            unsigned qh[4][4], ql[4][4], kh[4][2], kl[4][2];
            const int arow = mw * 64 + (lane & 15);
            const int acol = ks * 16 + (lane >> 4) * 8;
            #pragma unroll
            for (int mt = 0; mt < 4; mt++) {
                const unsigned off = 2u * ((arow + mt * 16) * TST + acol);
                ldm_x4(qh[mt], sbase + 2 * AT_QH + off);
                ldm_x4(ql[mt], sbase + 2 * AT_QL + off);
            }
            const int g = lane >> 3;
            const int browo = (g >> 1) * 8 + (lane & 7);
            const int bko = (g & 1) * 8;
            #pragma unroll
            for (int np = 0; np < 2; np++) {
                const unsigned off = 2u * ((nw * 32 + np * 16 + browo) * TST + ks * 16 + bko);
                ldm_x4(&kh[np * 2][0], skh + off);
                ldm_x4(&kl[np * 2][0], skl + off);
            }
            #pragma unroll
            for (int mt = 0; mt < 4; mt++)
                #pragma unroll
                for (int nt = 0; nt < 4; nt++) {
                    mma16816(sacc[mt][nt], qh[mt], kh[nt]);
                    mma16816(sacc[mt][nt], qh[mt], kl[nt]);
                    mma16816(sacc[mt][nt], ql[mt], kh[nt]);
                }
        }

        // ---- online softmax ----
        #pragma unroll
        for (int mt = 0; mt < 4; mt++) {
            float mx0 = -INFINITY, mx1 = -INFINITY;
            #pragma unroll
            for (int nt = 0; nt < 4; nt++) {
                mx0 = fmaxf(mx0, fmaxf(sacc[mt][nt][0], sacc[mt][nt][1]));
                mx1 = fmaxf(mx1, fmaxf(sacc[mt][nt][2], sacc[mt][nt][3]));
            }
            mx0 = fmaxf(mx0, __shfl_xor_sync(0xffffffffu, mx0, 1));
            mx0 = fmaxf(mx0, __shfl_xor_sync(0xffffffffu, mx0, 2));
            mx1 = fmaxf(mx1, __shfl_xor_sync(0xffffffffu, mx1, 1));
            mx1 = fmaxf(mx1, __shfl_xor_sync(0xffffffffu, mx1, 2));
            if ((lane & 3) == 0) {
                smf[ATF_RM + (rbase + mt * 16) * 4 + nw] = mx0;
                smf[ATF_RM + (rbase + mt * 16 + 8) * 4 + nw] = mx1;
            }
        }
        __syncthreads();

        float mnew[4][2], alpha[4][2];
        #pragma unroll
        for (int mt = 0; mt < 4; mt++)
            #pragma unroll
            for (int h2 = 0; h2 < 2; h2++) {
                const int r = rbase + mt * 16 + h2 * 8;
                const float* rm = smf + ATF_RM + r * 4;
                const float mx = fmaxf(fmaxf(rm[0], rm[1]), fmaxf(rm[2], rm[3]));
                const float mo = smf[ATF_M + r];
                const float mn = fmaxf(mo, mx);
                mnew[mt][h2] = mn;
                alpha[mt][h2] = __expf(mo - mn);
            }

        float rs[4][2];
        #pragma unroll
        for (int mt = 0; mt < 4; mt++) { rs[mt][0] = 0.f; rs[mt][1] = 0.f; }
        #pragma unroll
        for (int mt = 0; mt < 4; mt++) {
            const int rA = rbase + mt * 16;
            #pragma unroll
            for (int nt = 0; nt < 4; nt++) {
                const int col = nw * 32 + nt * 8 + (lane & 3) * 2;
                const float p0 = __expf(sacc[mt][nt][0] - mnew[mt][0]);
                const float p1 = __expf(sacc[mt][nt][1] - mnew[mt][0]);
                const float p2 = __expf(sacc[mt][nt][2] - mnew[mt][1]);
                const float p3 = __expf(sacc[mt][nt][3] - mnew[mt][1]);
                rs[mt][0] += p0 + p1;
                rs[mt][1] += p2 + p3;
                unsigned ph, pl;
                split2(p0, p1, ph, pl);
                *reinterpret_cast<unsigned*>(smm + AT_PH + rA * PST + col) = ph;
                *reinterpret_cast<unsigned*>(smm + AT_PL + rA * PST + col) = pl;
                split2(p2, p3, ph, pl);
                *reinterpret_cast<unsigned*>(smm + AT_PH + (rA + 8) * PST + col) = ph;
                *reinterpret_cast<unsigned*>(smm + AT_PL + (rA + 8) * PST + col) = pl;
            }
        }
        #pragma unroll
        for (int mt = 0; mt < 4; mt++)
            #pragma unroll
            for (int h2 = 0; h2 < 2; h2++) {
                float v = rs[mt][h2];
                v += __shfl_xor_sync(0xffffffffu, v, 1);
                v += __shfl_xor_sync(0xffffffffu, v, 2);
                if ((lane & 3) == 0)
                    smf[ATF_RS + (rbase + mt * 16 + h2 * 8) * 4 + nw] = v;
            }
        #pragma unroll
        for (int mt = 0; mt < 4; mt++)
            #pragma unroll
            for (int nt2 = 0; nt2 < 2; nt2++) {
                oacc[mt][nt2][0] *= alpha[mt][0];
                oacc[mt][nt2][1] *= alpha[mt][0];
                oacc[mt][nt2][2] *= alpha[mt][1];
                oacc[mt][nt2][3] *= alpha[mt][1];
            }

        // wait for V (and K-next) before the PV phase
        CP_WAIT(0);
        __syncthreads();

        if (nw == 0 && (lane & 3) == 0) {
            #pragma unroll
            for (int mt = 0; mt < 4; mt++)
                #pragma unroll
                for (int h2 = 0; h2 < 2; h2++) {
                    const int r = rbase + mt * 16 + h2 * 8;
                    const float* rsm = smf + ATF_RS + r * 4;
                    smf[ATF_L + r] = smf[ATF_L + r] * alpha[mt][h2]
                                     + rsm[0] + rsm[1] + rsm[2] + rsm[3];
                    smf[ATF_M + r] = mnew[mt][h2];
                }
        }

        // ---- O += P V (3-pass split) ----
        #pragma unroll
        for (int ks = 0; ks < 8; ks++) {
            unsigned ph[4][4], pl[4][4], vh[2][2], vl[2][2];
            const int arow = mw * 64 + (lane & 15);
            const int acol = ks * 16 + (lane >> 4) * 8;
            #pragma unroll
            for (int mt = 0; mt < 4; mt++) {
                const unsigned off = 2u * ((arow + mt * 16) * PST + acol);
                ldm_x4(ph[mt], sbase + 2 * AT_PH + off);
                ldm_x4(pl[mt], sbase + 2 * AT_PL + off);
            }
            const int g = lane >> 3;
            const int kr = ks * 16 + (g & 1) * 8 + (lane & 7);
            const int ec = nw * 16 + (g >> 1) * 8;
            const unsigned voff = 2u * (kr * TST + ec);
            ldm_x4_t(&vh[0][0], sbase + 2 * AT_VH + voff);
            ldm_x4_t(&vl[0][0], sbase + 2 * AT_VL + voff);
            #pragma unroll
            for (int mt = 0; mt < 4; mt++)
                #pragma unroll
                for (int nt2 = 0; nt2 < 2; nt2++) {
                    mma16816(oacc[mt][nt2], ph[mt], vh[nt2]);
                    mma16816(oacc[mt][nt2], ph[mt], vl[nt2]);
                    mma16816(oacc[mt][nt2], pl[mt], vh[nt2]);
                }
        }
        __syncthreads();
    }

    // Epilogue: normalize, split to bf16, write g_A2 (concat layout)
    const int bb = bh >> 4, hh = bh & 15;
    #pragma unroll
    for (int mt = 0; mt < 4; mt++) {
        #pragma unroll
        for (int h2 = 0; h2 < 2; h2++) {
            const int r = rbase + mt * 16 + h2 * 8;
            const float inv = 1.f / smf[ATF_L + r];
            const size_t mrow = ((size_t)bb * SEQ + q0 + r) * D_MODEL + hh * HEAD_DIM;
            #pragma unroll
            for (int nt2 = 0; nt2 < 2; nt2++) {
                const int e = nw * 16 + nt2 * 8 + (lane & 3) * 2;
                const float v0 = oacc[mt][nt2][h2 * 2 + 0] * inv;
                const float v1 = oacc[mt][nt2][h2 * 2 + 1] * inv;
                unsigned ph, pl;
                split2(v0, v1, ph, pl);
                *reinterpret_cast<unsigned*>(g_A2h + mrow + e) = ph;
                *reinterpret_cast<unsigned*>(g_A2l + mrow + e) = pl;
            }
        }
    }
}

// ============================================================================
extern "C" void kernel_launch(void* const* d_in, const int* in_sizes, int n_in,
                              void* d_out, int out_size)
{
    const float* x  = (const float*)d_in[0];
    const float* Wq = (const float*)d_in[1];
    const float* bq = (const float*)d_in[2];
    const float* Wk = (const float*)d_in[3];
    const float* bk = (const float*)d_in[4];
    const float* Wv = (const float*)d_in[5];
    const float* bv = (const float*)d_in[6];
    const float* Wo = (const float*)d_in[7];
    const float* bo = (const float*)d_in[8];
    float* out = (float*)d_out;

    cudaFuncSetAttribute(mm_mma, cudaFuncAttributeMaxDynamicSharedMemorySize, MM_SMEM);
    cudaFuncSetAttribute(attn_mma, cudaFuncAttributeMaxDynamicSharedMemorySize, ATTN_SMEM);

    split_x<<<(M_TOTAL * D_MODEL) / 1024, 256>>>(x);
    conv_wqkv<<<(NQKV * D_MODEL) / 256, 256>>>(Wq, bq, Wk, bk, Wv, bv);
    conv_wo<<<(D_MODEL * D_MODEL) / 256, 256>>>(Wo);

    mm_mma<<<dim3(NQKV / 128, M_TOTAL / 128), 256, MM_SMEM>>>(nullptr, nullptr, 1);
    attn_mma<<<dim3(SEQ / 128, NBH), 256, ATTN_SMEM>>>();
    mm_mma<<<dim3(D_MODEL / 128, M_TOTAL / 128), 256, MM_SMEM>>>(bo, out, 0);
}

// round 6
// speedup vs baseline: 3.0168x; 1.0550x over previous
#include <cuda_runtime.h>
#include <cuda_bf16.h>
#include <math.h>

typedef __nv_bfloat16 bf16;

#define D_MODEL   1024
#define NUM_HEADS 16
#define HEAD_DIM  64
#define BATCH     4
#define SEQ       2048
#define M_TOTAL   (BATCH * SEQ)   // 8192
#define NQKV      (3 * D_MODEL)   // 3072
#define NBH       (BATCH * NUM_HEADS)  // 64

// ============================================================================
// Device global scratch (allocation-free rule)
// ============================================================================
__device__ bf16 g_Xh[M_TOTAL * D_MODEL], g_Xl[M_TOTAL * D_MODEL];
__device__ bf16 g_Bqkv_h[NQKV * D_MODEL], g_Bqkv_l[NQKV * D_MODEL];   // [n][k]
__device__ bf16 g_Wo_h[D_MODEL * D_MODEL], g_Wo_l[D_MODEL * D_MODEL]; // [n][k]
__device__ float g_bias_qkv[NQKV];
__device__ bf16 g_qh[NBH * SEQ * HEAD_DIM], g_ql[NBH * SEQ * HEAD_DIM];
__device__ bf16 g_kh[NBH * SEQ * HEAD_DIM], g_kl[NBH * SEQ * HEAD_DIM];
__device__ bf16 g_vh[NBH * SEQ * HEAD_DIM], g_vl[NBH * SEQ * HEAD_DIM];
__device__ bf16 g_A2h[M_TOTAL * D_MODEL], g_A2l[M_TOTAL * D_MODEL];

// ============================================================================
// PTX helpers (portable, compute_103-safe)
// ============================================================================
__device__ __forceinline__ unsigned smem_u32(const void* p) {
    unsigned a;
    asm("{ .reg .u64 t; cvta.to.shared.u64 t, %1; cvt.u32.u64 %0, t; }"
        : "=r"(a) : "l"(p));
    return a;
}
__device__ __forceinline__ void ldm_x4(unsigned* r, unsigned addr) {
    asm volatile("ldmatrix.sync.aligned.m8n8.x4.shared.b16 {%0,%1,%2,%3}, [%4];"
        : "=r"(r[0]), "=r"(r[1]), "=r"(r[2]), "=r"(r[3]) : "r"(addr));
}
__device__ __forceinline__ void ldm_x4_t(unsigned* r, unsigned addr) {
    asm volatile("ldmatrix.sync.aligned.m8n8.x4.trans.shared.b16 {%0,%1,%2,%3}, [%4];"
        : "=r"(r[0]), "=r"(r[1]), "=r"(r[2]), "=r"(r[3]) : "r"(addr));
}
__device__ __forceinline__ void mma16816(float* c, const unsigned* a, const unsigned* b) {
    asm volatile("mma.sync.aligned.m16n8k16.row.col.f32.bf16.bf16.f32 "
        "{%0,%1,%2,%3}, {%4,%5,%6,%7}, {%8,%9}, {%0,%1,%2,%3};"
        : "+f"(c[0]), "+f"(c[1]), "+f"(c[2]), "+f"(c[3])
        : "r"(a[0]), "r"(a[1]), "r"(a[2]), "r"(a[3]), "r"(b[0]), "r"(b[1]));
}
__device__ __forceinline__ void cp_async16(unsigned saddr, const void* gptr) {
    asm volatile("cp.async.cg.shared.global [%0], [%1], 16;"
                 :: "r"(saddr), "l"(gptr) : "memory");
}
#define CP_COMMIT() asm volatile("cp.async.commit_group;" ::: "memory")
#define CP_WAIT(N)  asm volatile("cp.async.wait_group %0;" :: "n"(N) : "memory")

__device__ __forceinline__ unsigned pack_bf2(float lo, float hi) {
    unsigned d;
    asm("cvt.rn.bf16x2.f32 %0, %1, %2;" : "=r"(d) : "f"(hi), "f"(lo));
    return d;
}
__device__ __forceinline__ void split2(float v0, float v1, unsigned& ph, unsigned& pl) {
    float h0 = __bfloat162float(__float2bfloat16(v0));
    float h1 = __bfloat162float(__float2bfloat16(v1));
    ph = pack_bf2(v0, v1);
    pl = pack_bf2(v0 - h0, v1 - h1);
}

// ============================================================================
// Conversion kernels
// ============================================================================
__global__ __launch_bounds__(256) void split_x(const float* __restrict__ x) {
    size_t i = ((size_t)blockIdx.x * 256 + threadIdx.x) * 4;
    float4 v = *reinterpret_cast<const float4*>(x + i);
    float f[4] = {v.x, v.y, v.z, v.w};
    #pragma unroll
    for (int j = 0; j < 4; j++) {
        bf16 h = __float2bfloat16(f[j]);
        g_Xh[i + j] = h;
        g_Xl[i + j] = __float2bfloat16(f[j] - __bfloat162float(h));
    }
}

__global__ __launch_bounds__(256) void conv_wqkv(
    const float* __restrict__ Wq, const float* __restrict__ bq,
    const float* __restrict__ Wk, const float* __restrict__ bk,
    const float* __restrict__ Wv, const float* __restrict__ bv) {
    size_t idx = (size_t)blockIdx.x * 256 + threadIdx.x;  // n*1024 + k
    int n = (int)(idx >> 10), k = (int)(idx & 1023);
    int proj = n >> 10, nc = n & 1023, h = nc >> 6, e = nc & 63;
    const float* W = (proj == 0) ? Wq : (proj == 1) ? Wk : Wv;
    float v = W[((size_t)h * D_MODEL + k) * HEAD_DIM + e];
    bf16 hh = __float2bfloat16(v);
    g_Bqkv_h[idx] = hh;
    g_Bqkv_l[idx] = __float2bfloat16(v - __bfloat162float(hh));
    if (k == 0) {
        const float* b = (proj == 0) ? bq : (proj == 1) ? bk : bv;
        g_bias_qkv[n] = b[nc];
    }
}

__global__ __launch_bounds__(256) void conv_wo(const float* __restrict__ Wo) {
    size_t idx = (size_t)blockIdx.x * 256 + threadIdx.x;
    int n = (int)(idx >> 10), k = (int)(idx & 1023);
    float v = Wo[(size_t)k * D_MODEL + n];
    bf16 hh = __float2bfloat16(v);
    g_Wo_h[idx] = hh;
    g_Wo_l[idx] = __float2bfloat16(v - __bfloat162float(hh));
}

// ============================================================================
// GEMM on mma.sync with cp.async 3-stage pipeline, one barrier per chunk.
// CTA 128x128, 256 threads, warps 2(M)x4(N), warp tile 64x32, 3-pass split.
// ============================================================================
#define TST 72
#define MM_SA_H 0
#define MM_SA_L (128 * TST)
#define MM_SB_H (2 * 128 * TST)
#define MM_SB_L (3 * 128 * TST)
#define STAGE_EL (4 * 128 * TST)          // 36864 el / 73728 B
#define MM_SMEM  (3 * STAGE_EL * 2)       // 221184 B

__global__ __launch_bounds__(256) void mm_mma(const float* __restrict__ bias_ext,
                                              float* __restrict__ outp, int mode) {
    extern __shared__ __align__(16) bf16 smm[];
    const unsigned sbase = smem_u32(smm);
    const int tid = threadIdx.x;
    const int lane = tid & 31;
    const int w = tid >> 5;
    const int mw = w >> 2, nw = w & 3;
    const int n0 = blockIdx.x * 128;
    const int m0 = blockIdx.y * 128;

    const bf16* __restrict__ Ahg = (mode == 1) ? g_Xh : g_A2h;
    const bf16* __restrict__ Alg = (mode == 1) ? g_Xl : g_A2l;
    const bf16* __restrict__ Bhg = (mode == 1) ? g_Bqkv_h : g_Wo_h;
    const bf16* __restrict__ Blg = (mode == 1) ? g_Bqkv_l : g_Wo_l;
    const float* __restrict__ bias = (mode == 1) ? g_bias_qkv : bias_ext;

    float acc[4][4][4];
    #pragma unroll
    for (int a = 0; a < 4; a++)
        #pragma unroll
        for (int b = 0; b < 4; b++)
            #pragma unroll
            for (int c = 0; c < 4; c++) acc[a][b][c] = 0.f;

    auto issue = [&](int kc) {
        const int k0 = kc * 64;
        const unsigned sst = sbase + (unsigned)(2 * STAGE_EL) * (kc % 3);
        #pragma unroll
        for (int i = 0; i < 4; i++) {
            const int t = tid + 256 * i;
            const int row = t >> 3, slot = t & 7;
            const unsigned so = 2u * (row * TST + slot * 8);
            const size_t ga = (size_t)(m0 + row) * D_MODEL + k0 + slot * 8;
            const size_t gb = (size_t)(n0 + row) * D_MODEL + k0 + slot * 8;
            cp_async16(sst + 2u * MM_SA_H + so, Ahg + ga);
            cp_async16(sst + 2u * MM_SA_L + so, Alg + ga);
            cp_async16(sst + 2u * MM_SB_H + so, Bhg + gb);
            cp_async16(sst + 2u * MM_SB_L + so, Blg + gb);
        }
        CP_COMMIT();
    };

    issue(0);
    issue(1);

    for (int kc = 0; kc < 16; kc++) {
        if (kc < 15) { CP_WAIT(1); } else { CP_WAIT(0); }
        __syncthreads();
        if (kc + 2 < 16) issue(kc + 2);

        const unsigned sst = sbase + (unsigned)(2 * STAGE_EL) * (kc % 3);
        #pragma unroll
        for (int ks = 0; ks < 4; ks++) {
            unsigned ah[4][4], al[4][4], bh[4][2], bl[4][2];
            const int arow = mw * 64 + (lane & 15);
            const int acol = ks * 16 + (lane >> 4) * 8;
            #pragma unroll
            for (int mt = 0; mt < 4; mt++) {
                const unsigned off = 2u * ((arow + mt * 16) * TST + acol);
                ldm_x4(ah[mt], sst + 2 * MM_SA_H + off);
                ldm_x4(al[mt], sst + 2 * MM_SA_L + off);
            }
            const int g = lane >> 3;
            const int browo = (g >> 1) * 8 + (lane & 7);
            const int bko = (g & 1) * 8;
            #pragma unroll
            for (int np = 0; np < 2; np++) {
                const unsigned off = 2u * ((nw * 32 + np * 16 + browo) * TST + ks * 16 + bko);
                ldm_x4(&bh[np * 2][0], sst + 2 * MM_SB_H + off);
                ldm_x4(&bl[np * 2][0], sst + 2 * MM_SB_L + off);
            }
            #pragma unroll
            for (int mt = 0; mt < 4; mt++)
                #pragma unroll
                for (int nt = 0; nt < 4; nt++) {
                    mma16816(acc[mt][nt], ah[mt], bh[nt]);
                    mma16816(acc[mt][nt], ah[mt], bl[nt]);
                    mma16816(acc[mt][nt], al[mt], bh[nt]);
                }
        }
    }

    // Epilogue
    #pragma unroll
    for (int mt = 0; mt < 4; mt++) {
        const int r0 = m0 + mw * 64 + mt * 16 + (lane >> 2);
        #pragma unroll
        for (int nt = 0; nt < 4; nt++) {
            const int c = n0 + nw * 32 + nt * 8 + (lane & 3) * 2;
            const float b0 = bias[c], b1 = bias[c + 1];
            #pragma unroll
            for (int h2 = 0; h2 < 2; h2++) {
                const int r = r0 + h2 * 8;
                float v0 = acc[mt][nt][h2 * 2 + 0] + b0;
                float v1 = acc[mt][nt][h2 * 2 + 1] + b1;
                if (mode == 0) {
                    float2 vv = make_float2(v0, v1);
                    *reinterpret_cast<float2*>(outp + (size_t)r * D_MODEL + c) = vv;
                } else {
                    const int proj = c >> 10, nc = c & 1023, hh = nc >> 6, e = nc & 63;
                    if (proj == 0) { v0 *= 0.125f; v1 *= 0.125f; }
                    bf16* dh = (proj == 0) ? g_qh : (proj == 1) ? g_kh : g_vh;
                    bf16* dl = (proj == 0) ? g_ql : (proj == 1) ? g_kl : g_vl;
                    const size_t idx =
                        (((size_t)((r >> 11) * NUM_HEADS + hh)) * SEQ + (r & 2047)) * HEAD_DIM + e;
                    unsigned ph, pl;
                    split2(v0, v1, ph, pl);
                    *reinterpret_cast<unsigned*>(dh + idx) = ph;
                    *reinterpret_cast<unsigned*>(dl + idx) = pl;
                }
            }
        }
    }
}

// ============================================================================
// Flash attention, FA2-style: warp owns 16 q-rows x all 128 keys.
// Softmax fully in registers (quad shuffles). P stays in registers
// (C-fragment -> A-fragment conversion). K and V double-buffered cp.async.
// ============================================================================
// bf16-element offsets
#define AQ_H 0
#define AQ_L 9216
#define AK(s)  (18432 + (s) * 18432)      // KH at +0, KL at +9216
#define AV(s)  (55296 + (s) * 18432)      // VH at +0, VL at +9216
#define ATTN_SMEM ((55296 + 2 * 18432) * 2)   // 184320 B

__global__ __launch_bounds__(256) void attn_mma() {
    extern __shared__ __align__(16) bf16 smm[];
    const unsigned sbase = smem_u32(smm);
    const int tid = threadIdx.x;
    const int lane = tid & 31;
    const int w = tid >> 5;
    const int q0 = blockIdx.x * 128;
    const int bh = blockIdx.y;
    const size_t gbase = (size_t)bh * SEQ * HEAD_DIM;

    const int g = lane >> 3;
    const int browo = (g >> 1) * 8 + (lane & 7);
    const int bko = (g & 1) * 8;

    auto issueK = [&](int kt2) {
        const int t0 = kt2 * 128;
        const unsigned sk = sbase + 2u * AK(kt2 & 1);
        #pragma unroll
        for (int i = 0; i < 4; i++) {
            const int t = tid + 256 * i;
            const int row = t >> 3, slot = t & 7;
            const unsigned so = 2u * (row * TST + slot * 8);
            const size_t gk = gbase + (size_t)(t0 + row) * HEAD_DIM + slot * 8;
            cp_async16(sk + so, g_kh + gk);
            cp_async16(sk + 2u * 9216 + so, g_kl + gk);
        }
        CP_COMMIT();
    };
    auto issueV = [&](int kt2) {
        const int t0 = kt2 * 128;
        const unsigned sv = sbase + 2u * AV(kt2 & 1);
        #pragma unroll
        for (int i = 0; i < 4; i++) {
            const int t = tid + 256 * i;
            const int row = t >> 3, slot = t & 7;
            const unsigned so = 2u * (row * TST + slot * 8);
            const size_t gv = gbase + (size_t)(t0 + row) * HEAD_DIM + slot * 8;
            cp_async16(sv + so, g_vh + gv);
            cp_async16(sv + 2u * 9216 + so, g_vl + gv);
        }
        CP_COMMIT();
    };

    issueK(0);
    issueV(0);

    // stage Q, then pull the warp's 16 rows into register fragments
    #pragma unroll
    for (int i = 0; i < 4; i++) {
        const int t = tid + 256 * i;
        const int row = t >> 3, slot = t & 7;
        const int so = row * TST + slot * 8;
        const size_t gq = gbase + (size_t)(q0 + row) * HEAD_DIM + slot * 8;
        *reinterpret_cast<float4*>(smm + AQ_H + so) = *reinterpret_cast<const float4*>(g_qh + gq);
        *reinterpret_cast<float4*>(smm + AQ_L + so) = *reinterpret_cast<const float4*>(g_ql + gq);
    }
    __syncthreads();

    unsigned qh[4][4], ql[4][4];
    {
        const int arow = w * 16 + (lane & 15);
        #pragma unroll
        for (int ks = 0; ks < 4; ks++) {
            const unsigned off = 2u * (arow * TST + ks * 16 + (lane >> 4) * 8);
            ldm_x4(qh[ks], sbase + 2 * AQ_H + off);
            ldm_x4(ql[ks], sbase + 2 * AQ_L + off);
        }
    }

    float m_run[2] = {-INFINITY, -INFINITY};
    float l_run[2] = {0.f, 0.f};
    float oacc[8][4];
    #pragma unroll
    for (int a = 0; a < 8; a++)
        #pragma unroll
        for (int c = 0; c < 4; c++) oacc[a][c] = 0.f;

    for (int kt = 0; kt < 16; kt++) {
        // in flight: K[kt], V[kt]
        if (kt < 15) { CP_WAIT(1); } else { CP_WAIT(1); }
        __syncthreads();   // K[kt] visible to all

        const unsigned skh = sbase + 2u * AK(kt & 1);
        const unsigned skl = skh + 2u * 9216;

        // ---- S = Q K^T (3-pass split): 16 n8-tiles of keys ----
        float sacc[16][4];
        #pragma unroll
        for (int a = 0; a < 16; a++)
            #pragma unroll
            for (int c = 0; c < 4; c++) sacc[a][c] = 0.f;

        #pragma unroll
        for (int ks = 0; ks < 4; ks++) {
            #pragma unroll
            for (int kb = 0; kb < 8; kb++) {
                unsigned kh4[4], kl4[4];
                const unsigned off = 2u * ((kb * 16 + browo) * TST + ks * 16 + bko);
                ldm_x4(kh4, skh + off);
                ldm_x4(kl4, skl + off);
                #pragma unroll
                for (int j = 0; j < 2; j++) {
                    const int nt = kb * 2 + j;
                    mma16816(sacc[nt], qh[ks], &kh4[2 * j]);
                    mma16816(sacc[nt], qh[ks], &kl4[2 * j]);
                    mma16816(sacc[nt], ql[ks], &kh4[2 * j]);
                }
            }
        }

        // ---- softmax (registers + quad shuffles only) ----
        float mx0 = -INFINITY, mx1 = -INFINITY;
        #pragma unroll
        for (int nt = 0; nt < 16; nt++) {
            mx0 = fmaxf(mx0, fmaxf(sacc[nt][0], sacc[nt][1]));
            mx1 = fmaxf(mx1, fmaxf(sacc[nt][2], sacc[nt][3]));
        }
        mx0 = fmaxf(mx0, __shfl_xor_sync(0xffffffffu, mx0, 1));
        mx0 = fmaxf(mx0, __shfl_xor_sync(0xffffffffu, mx0, 2));
        mx1 = fmaxf(mx1, __shfl_xor_sync(0xffffffffu, mx1, 1));
        mx1 = fmaxf(mx1, __shfl_xor_sync(0xffffffffu, mx1, 2));
        const float mn0 = fmaxf(m_run[0], mx0);
        const float mn1 = fmaxf(m_run[1], mx1);
        const float al0 = __expf(m_run[0] - mn0);
        const float al1 = __expf(m_run[1] - mn1);
        m_run[0] = mn0; m_run[1] = mn1;

        unsigned ph[8][4], pl[8][4];
        float s0 = 0.f, s1 = 0.f;
        #pragma unroll
        for (int kb = 0; kb < 8; kb++) {
            #pragma unroll
            for (int j = 0; j < 2; j++) {
                const int nt = kb * 2 + j;
                const float p0 = __expf(sacc[nt][0] - mn0);
                const float p1 = __expf(sacc[nt][1] - mn0);
                const float p2 = __expf(sacc[nt][2] - mn1);
                const float p3 = __expf(sacc[nt][3] - mn1);
                s0 += p0 + p1;
                s1 += p2 + p3;
                split2(p0, p1, ph[kb][2 * j + 0], pl[kb][2 * j + 0]);
                split2(p2, p3, ph[kb][2 * j + 1], pl[kb][2 * j + 1]);
            }
        }
        s0 += __shfl_xor_sync(0xffffffffu, s0, 1);
        s0 += __shfl_xor_sync(0xffffffffu, s0, 2);
        s1 += __shfl_xor_sync(0xffffffffu, s1, 1);
        s1 += __shfl_xor_sync(0xffffffffu, s1, 2);
        l_run[0] = l_run[0] * al0 + s0;
        l_run[1] = l_run[1] * al1 + s1;
        #pragma unroll
        for (int ot = 0; ot < 8; ot++) {
            oacc[ot][0] *= al0; oacc[ot][1] *= al0;
            oacc[ot][2] *= al1; oacc[ot][3] *= al1;
        }

        // prefetch next tile, then wait for V[kt]
        if (kt < 15) { issueK(kt + 1); issueV(kt + 1); CP_WAIT(2); }
        else         { CP_WAIT(0); }
        __syncthreads();   // V[kt] visible to all

        const unsigned svh = sbase + 2u * AV(kt & 1);
        const unsigned svl = svh + 2u * 9216;

        // ---- O += P V (3-pass split) ----
        #pragma unroll
        for (int ks = 0; ks < 8; ks++) {
            const int kr = ks * 16 + (g & 1) * 8 + (lane & 7);
            #pragma unroll
            for (int eb = 0; eb < 4; eb++) {
                unsigned vh4[4], vl4[4];
                const unsigned voff = 2u * (kr * TST + eb * 16 + (g >> 1) * 8);
                ldm_x4_t(vh4, svh + voff);
                ldm_x4_t(vl4, svl + voff);
                #pragma unroll
                for (int j = 0; j < 2; j++) {
                    const int ot = eb * 2 + j;
                    mma16816(oacc[ot], ph[ks], &vh4[2 * j]);
                    mma16816(oacc[ot], ph[ks], &vl4[2 * j]);
                    mma16816(oacc[ot], pl[ks], &vh4[2 * j]);
                }
            }
        }
        // no trailing barrier: next iteration's top barrier orders buffer reuse
    }

    // Epilogue: normalize, split to bf16, write g_A2 (concat layout)
    const int bb = bh >> 4, hh = bh & 15;
    const int r0 = w * 16 + (lane >> 2);
    const float inv0 = 1.f / l_run[0];
    const float inv1 = 1.f / l_run[1];
    const size_t mrow0 = ((size_t)bb * SEQ + q0 + r0) * D_MODEL + hh * HEAD_DIM;
    const size_t mrow1 = ((size_t)bb * SEQ + q0 + r0 + 8) * D_MODEL + hh * HEAD_DIM;
    #pragma unroll
    for (int ot = 0; ot < 8; ot++) {
        const int e = ot * 8 + (lane & 3) * 2;
        unsigned ph, pl;
        split2(oacc[ot][0] * inv0, oacc[ot][1] * inv0, ph, pl);
        *reinterpret_cast<unsigned*>(g_A2h + mrow0 + e) = ph;
        *reinterpret_cast<unsigned*>(g_A2l + mrow0 + e) = pl;
        split2(oacc[ot][2] * inv1, oacc[ot][3] * inv1, ph, pl);
        *reinterpret_cast<unsigned*>(g_A2h + mrow1 + e) = ph;
        *reinterpret_cast<unsigned*>(g_A2l + mrow1 + e) = pl;
    }
}

// ============================================================================
extern "C" void kernel_launch(void* const* d_in, const int* in_sizes, int n_in,
                              void* d_out, int out_size)
{
    const float* x  = (const float*)d_in[0];
    const float* Wq = (const float*)d_in[1];
    const float* bq = (const float*)d_in[2];
    const float* Wk = (const float*)d_in[3];
    const float* bk = (const float*)d_in[4];
    const float* Wv = (const float*)d_in[5];
    const float* bv = (const float*)d_in[6];
    const float* Wo = (const float*)d_in[7];
    const float* bo = (const float*)d_in[8];
    float* out = (float*)d_out;

    cudaFuncSetAttribute(mm_mma, cudaFuncAttributeMaxDynamicSharedMemorySize, MM_SMEM);
    cudaFuncSetAttribute(attn_mma, cudaFuncAttributeMaxDynamicSharedMemorySize, ATTN_SMEM);

    split_x<<<(M_TOTAL * D_MODEL) / 1024, 256>>>(x);
    conv_wqkv<<<(NQKV * D_MODEL) / 256, 256>>>(Wq, bq, Wk, bk, Wv, bv);
    conv_wo<<<(D_MODEL * D_MODEL) / 256, 256>>>(Wo);

    mm_mma<<<dim3(NQKV / 128, M_TOTAL / 128), 256, MM_SMEM>>>(nullptr, nullptr, 1);
    attn_mma<<<dim3(SEQ / 128, NBH), 256, ATTN_SMEM>>>();
    mm_mma<<<dim3(D_MODEL / 128, M_TOTAL / 128), 256, MM_SMEM>>>(bo, out, 0);
}

// round 7
// speedup vs baseline: 3.0887x; 1.0239x over previous
#include <cuda_runtime.h>
#include <cuda_bf16.h>
#include <math.h>

typedef __nv_bfloat16 bf16;

#define D_MODEL   1024
#define NUM_HEADS 16
#define HEAD_DIM  64
#define BATCH     4
#define SEQ       2048
#define M_TOTAL   (BATCH * SEQ)   // 8192
#define NQKV      (3 * D_MODEL)   // 3072
#define NBH       (BATCH * NUM_HEADS)  // 64

// ============================================================================
// Device global scratch (allocation-free rule)
// ============================================================================
__device__ bf16 g_Xh[M_TOTAL * D_MODEL], g_Xl[M_TOTAL * D_MODEL];
__device__ bf16 g_Bqkv_h[NQKV * D_MODEL], g_Bqkv_l[NQKV * D_MODEL];   // [n][k]
__device__ bf16 g_Wo_h[D_MODEL * D_MODEL], g_Wo_l[D_MODEL * D_MODEL]; // [n][k]
__device__ float g_bias_qkv[NQKV];
__device__ bf16 g_qh[NBH * SEQ * HEAD_DIM], g_ql[NBH * SEQ * HEAD_DIM];
__device__ bf16 g_kh[NBH * SEQ * HEAD_DIM], g_kl[NBH * SEQ * HEAD_DIM];
__device__ bf16 g_vh[NBH * SEQ * HEAD_DIM], g_vl[NBH * SEQ * HEAD_DIM];
__device__ bf16 g_A2h[M_TOTAL * D_MODEL], g_A2l[M_TOTAL * D_MODEL];

// ============================================================================
// PTX helpers (portable, compute_103-safe)
// ============================================================================
__device__ __forceinline__ unsigned smem_u32(const void* p) {
    unsigned a;
    asm("{ .reg .u64 t; cvta.to.shared.u64 t, %1; cvt.u32.u64 %0, t; }"
        : "=r"(a) : "l"(p));
    return a;
}
__device__ __forceinline__ void ldm_x4(unsigned* r, unsigned addr) {
    asm volatile("ldmatrix.sync.aligned.m8n8.x4.shared.b16 {%0,%1,%2,%3}, [%4];"
        : "=r"(r[0]), "=r"(r[1]), "=r"(r[2]), "=r"(r[3]) : "r"(addr));
}
__device__ __forceinline__ void ldm_x4_t(unsigned* r, unsigned addr) {
    asm volatile("ldmatrix.sync.aligned.m8n8.x4.trans.shared.b16 {%0,%1,%2,%3}, [%4];"
        : "=r"(r[0]), "=r"(r[1]), "=r"(r[2]), "=r"(r[3]) : "r"(addr));
}
__device__ __forceinline__ void mma16816(float* c, const unsigned* a, const unsigned* b) {
    asm volatile("mma.sync.aligned.m16n8k16.row.col.f32.bf16.bf16.f32 "
        "{%0,%1,%2,%3}, {%4,%5,%6,%7}, {%8,%9}, {%0,%1,%2,%3};"
        : "+f"(c[0]), "+f"(c[1]), "+f"(c[2]), "+f"(c[3])
        : "r"(a[0]), "r"(a[1]), "r"(a[2]), "r"(a[3]), "r"(b[0]), "r"(b[1]));
}
__device__ __forceinline__ void cp_async16(unsigned saddr, const void* gptr) {
    asm volatile("cp.async.cg.shared.global [%0], [%1], 16;"
                 :: "r"(saddr), "l"(gptr) : "memory");
}
#define CP_COMMIT() asm volatile("cp.async.commit_group;" ::: "memory")
#define CP_WAIT(N)  asm volatile("cp.async.wait_group %0;" :: "n"(N) : "memory")

__device__ __forceinline__ unsigned pack_bf2(float lo, float hi) {
    unsigned d;
    asm("cvt.rn.bf16x2.f32 %0, %1, %2;" : "=r"(d) : "f"(hi), "f"(lo));
    return d;
}
__device__ __forceinline__ void split2(float v0, float v1, unsigned& ph, unsigned& pl) {
    float h0 = __bfloat162float(__float2bfloat16(v0));
    float h1 = __bfloat162float(__float2bfloat16(v1));
    ph = pack_bf2(v0, v1);
    pl = pack_bf2(v0 - h0, v1 - h1);
}

// ============================================================================
// Conversion kernels
// ============================================================================
__global__ __launch_bounds__(256) void split_x(const float* __restrict__ x) {
    size_t i = ((size_t)blockIdx.x * 256 + threadIdx.x) * 4;
    float4 v = *reinterpret_cast<const float4*>(x + i);
    float f[4] = {v.x, v.y, v.z, v.w};
    #pragma unroll
    for (int j = 0; j < 4; j++) {
        bf16 h = __float2bfloat16(f[j]);
        g_Xh[i + j] = h;
        g_Xl[i + j] = __float2bfloat16(f[j] - __bfloat162float(h));
    }
}

__global__ __launch_bounds__(256) void conv_wqkv(
    const float* __restrict__ Wq, const float* __restrict__ bq,
    const float* __restrict__ Wk, const float* __restrict__ bk,
    const float* __restrict__ Wv, const float* __restrict__ bv) {
    size_t idx = (size_t)blockIdx.x * 256 + threadIdx.x;  // n*1024 + k
    int n = (int)(idx >> 10), k = (int)(idx & 1023);
    int proj = n >> 10, nc = n & 1023, h = nc >> 6, e = nc & 63;
    const float* W = (proj == 0) ? Wq : (proj == 1) ? Wk : Wv;
    float v = W[((size_t)h * D_MODEL + k) * HEAD_DIM + e];
    bf16 hh = __float2bfloat16(v);
    g_Bqkv_h[idx] = hh;
    g_Bqkv_l[idx] = __float2bfloat16(v - __bfloat162float(hh));
    if (k == 0) {
        const float* b = (proj == 0) ? bq : (proj == 1) ? bk : bv;
        g_bias_qkv[n] = b[nc];
    }
}

__global__ __launch_bounds__(256) void conv_wo(const float* __restrict__ Wo) {
    size_t idx = (size_t)blockIdx.x * 256 + threadIdx.x;
    int n = (int)(idx >> 10), k = (int)(idx & 1023);
    float v = Wo[(size_t)k * D_MODEL + n];
    bf16 hh = __float2bfloat16(v);
    g_Wo_h[idx] = hh;
    g_Wo_l[idx] = __float2bfloat16(v - __bfloat162float(hh));
}

// ============================================================================
// GEMM on mma.sync, 2 CTAs/SM: BK=32, 2-stage cp.async, stride 40 el (80 B).
// CTA 128x128, 256 threads, warps 2(M)x4(N), warp tile 64x32, 3-pass split.
// ============================================================================
#define AST 40
#define MMS_A_H 0
#define MMS_A_L (128 * AST)
#define MMS_B_H (2 * 128 * AST)
#define MMS_B_L (3 * 128 * AST)
#define STAGE_EL (4 * 128 * AST)          // 20480 el = 40960 B
#define MM_SMEM  (2 * STAGE_EL * 2)       // 81920 B per CTA

__global__ __launch_bounds__(256, 2) void mm_mma(const float* __restrict__ bias_ext,
                                                 float* __restrict__ outp, int mode) {
    extern __shared__ __align__(16) bf16 smm[];
    const unsigned sbase = smem_u32(smm);
    const int tid = threadIdx.x;
    const int lane = tid & 31;
    const int w = tid >> 5;
    const int mw = w >> 2, nw = w & 3;
    const int n0 = blockIdx.x * 128;
    const int m0 = blockIdx.y * 128;

    const bf16* __restrict__ Ahg = (mode == 1) ? g_Xh : g_A2h;
    const bf16* __restrict__ Alg = (mode == 1) ? g_Xl : g_A2l;
    const bf16* __restrict__ Bhg = (mode == 1) ? g_Bqkv_h : g_Wo_h;
    const bf16* __restrict__ Blg = (mode == 1) ? g_Bqkv_l : g_Wo_l;
    const float* __restrict__ bias = (mode == 1) ? g_bias_qkv : bias_ext;

    float acc[4][4][4];
    #pragma unroll
    for (int a = 0; a < 4; a++)
        #pragma unroll
        for (int b = 0; b < 4; b++)
            #pragma unroll
            for (int c = 0; c < 4; c++) acc[a][b][c] = 0.f;

    auto issue = [&](int kc) {
        const int k0 = kc * 32;
        const unsigned sst = sbase + (unsigned)(2 * STAGE_EL) * (kc & 1);
        #pragma unroll
        for (int i = 0; i < 2; i++) {
            const int t = tid + 256 * i;
            const int row = t >> 2, slot = t & 3;          // 128 rows x 4 slots of 8 el
            const unsigned so = 2u * (row * AST + slot * 8);
            const size_t ga = (size_t)(m0 + row) * D_MODEL + k0 + slot * 8;
            const size_t gb = (size_t)(n0 + row) * D_MODEL + k0 + slot * 8;
            cp_async16(sst + 2u * MMS_A_H + so, Ahg + ga);
            cp_async16(sst + 2u * MMS_A_L + so, Alg + ga);
            cp_async16(sst + 2u * MMS_B_H + so, Bhg + gb);
            cp_async16(sst + 2u * MMS_B_L + so, Blg + gb);
        }
        CP_COMMIT();
    };

    issue(0);

    for (int kc = 0; kc < 32; kc++) {
        CP_WAIT(0);
        __syncthreads();          // stage kc ready; prev stage fully consumed
        if (kc + 1 < 32) issue(kc + 1);

        const unsigned sst = sbase + (unsigned)(2 * STAGE_EL) * (kc & 1);
        #pragma unroll
        for (int ks = 0; ks < 2; ks++) {
            unsigned ah[4][4], al[4][4], bh[4][2], bl[4][2];
            const int arow = mw * 64 + (lane & 15);
            const int acol = ks * 16 + (lane >> 4) * 8;
            #pragma unroll
            for (int mt = 0; mt < 4; mt++) {
                const unsigned off = 2u * ((arow + mt * 16) * AST + acol);
                ldm_x4(ah[mt], sst + 2 * MMS_A_H + off);
                ldm_x4(al[mt], sst + 2 * MMS_A_L + off);
            }
            const int g = lane >> 3;
            const int browo = (g >> 1) * 8 + (lane & 7);
            const int bko = (g & 1) * 8;
            #pragma unroll
            for (int np = 0; np < 2; np++) {
                const unsigned off = 2u * ((nw * 32 + np * 16 + browo) * AST + ks * 16 + bko);
                ldm_x4(&bh[np * 2][0], sst + 2 * MMS_B_H + off);
                ldm_x4(&bl[np * 2][0], sst + 2 * MMS_B_L + off);
            }
            #pragma unroll
            for (int mt = 0; mt < 4; mt++)
                #pragma unroll
                for (int nt = 0; nt < 4; nt++) {
                    mma16816(acc[mt][nt], ah[mt], bh[nt]);
                    mma16816(acc[mt][nt], ah[mt], bl[nt]);
                    mma16816(acc[mt][nt], al[mt], bh[nt]);
                }
        }
    }

    // Epilogue
    #pragma unroll
    for (int mt = 0; mt < 4; mt++) {
        const int r0 = m0 + mw * 64 + mt * 16 + (lane >> 2);
        #pragma unroll
        for (int nt = 0; nt < 4; nt++) {
            const int c = n0 + nw * 32 + nt * 8 + (lane & 3) * 2;
            const float b0 = bias[c], b1 = bias[c + 1];
            #pragma unroll
            for (int h2 = 0; h2 < 2; h2++) {
                const int r = r0 + h2 * 8;
                float v0 = acc[mt][nt][h2 * 2 + 0] + b0;
                float v1 = acc[mt][nt][h2 * 2 + 1] + b1;
                if (mode == 0) {
                    float2 vv = make_float2(v0, v1);
                    *reinterpret_cast<float2*>(outp + (size_t)r * D_MODEL + c) = vv;
                } else {
                    const int proj = c >> 10, nc = c & 1023, hh = nc >> 6, e = nc & 63;
                    if (proj == 0) { v0 *= 0.125f; v1 *= 0.125f; }
                    bf16* dh = (proj == 0) ? g_qh : (proj == 1) ? g_kh : g_vh;
                    bf16* dl = (proj == 0) ? g_ql : (proj == 1) ? g_kl : g_vl;
                    const size_t idx =
                        (((size_t)((r >> 11) * NUM_HEADS + hh)) * SEQ + (r & 2047)) * HEAD_DIM + e;
                    unsigned ph, pl;
                    split2(v0, v1, ph, pl);
                    *reinterpret_cast<unsigned*>(dh + idx) = ph;
                    *reinterpret_cast<unsigned*>(dl + idx) = pl;
                }
            }
        }
    }
}

// ============================================================================
// Flash attention, FA2-style: warp owns 16 q-rows x all 128 keys.
// Softmax in registers (quad shuffles). P stays in registers. K/V double-
// buffered cp.async; next-tile loads issued BEFORE the S phase.
// ============================================================================
#define TST 72
#define AQ_H 0
#define AQ_L 9216
#define AK(s)  (18432 + (s) * 18432)      // KH at +0, KL at +9216
#define AV(s)  (55296 + (s) * 18432)      // VH at +0, VL at +9216
#define ATTN_SMEM ((55296 + 2 * 18432) * 2)   // 184320 B

__global__ __launch_bounds__(256) void attn_mma() {
    extern __shared__ __align__(16) bf16 smm[];
    const unsigned sbase = smem_u32(smm);
    const int tid = threadIdx.x;
    const int lane = tid & 31;
    const int w = tid >> 5;
    const int q0 = blockIdx.x * 128;
    const int bh = blockIdx.y;
    const size_t gbase = (size_t)bh * SEQ * HEAD_DIM;

    const int g = lane >> 3;
    const int browo = (g >> 1) * 8 + (lane & 7);
    const int bko = (g & 1) * 8;

    auto issueK = [&](int kt2) {
        const int t0 = kt2 * 128;
        const unsigned sk = sbase + 2u * AK(kt2 & 1);
        #pragma unroll
        for (int i = 0; i < 4; i++) {
            const int t = tid + 256 * i;
            const int row = t >> 3, slot = t & 7;
            const unsigned so = 2u * (row * TST + slot * 8);
            const size_t gk = gbase + (size_t)(t0 + row) * HEAD_DIM + slot * 8;
            cp_async16(sk + so, g_kh + gk);
            cp_async16(sk + 2u * 9216 + so, g_kl + gk);
        }
        CP_COMMIT();
    };
    auto issueV = [&](int kt2) {
        const int t0 = kt2 * 128;
        const unsigned sv = sbase + 2u * AV(kt2 & 1);
        #pragma unroll
        for (int i = 0; i < 4; i++) {
            const int t = tid + 256 * i;
            const int row = t >> 3, slot = t & 7;
            const unsigned so = 2u * (row * TST + slot * 8);
            const size_t gv = gbase + (size_t)(t0 + row) * HEAD_DIM + slot * 8;
            cp_async16(sv + so, g_vh + gv);
            cp_async16(sv + 2u * 9216 + so, g_vl + gv);
        }
        CP_COMMIT();
    };

    issueK(0);
    issueV(0);

    // stage Q, then pull the warp's 16 rows into register fragments
    #pragma unroll
    for (int i = 0; i < 4; i++) {
        const int t = tid + 256 * i;
        const int row = t >> 3, slot = t & 7;
        const int so = row * TST + slot * 8;
        const size_t gq = gbase + (size_t)(q0 + row) * HEAD_DIM + slot * 8;
        *reinterpret_cast<float4*>(smm + AQ_H + so) = *reinterpret_cast<const float4*>(g_qh + gq);
        *reinterpret_cast<float4*>(smm + AQ_L + so) = *reinterpret_cast<const float4*>(g_ql + gq);
    }
    __syncthreads();

    unsigned qh[4][4], ql[4][4];
    {
        const int arow = w * 16 + (lane & 15);
        #pragma unroll
        for (int ks = 0; ks < 4; ks++) {
            const unsigned off = 2u * (arow * TST + ks * 16 + (lane >> 4) * 8);
            ldm_x4(qh[ks], sbase + 2 * AQ_H + off);
            ldm_x4(ql[ks], sbase + 2 * AQ_L + off);
        }
    }

    float m_run[2] = {-INFINITY, -INFINITY};
    float l_run[2] = {0.f, 0.f};
    float oacc[8][4];
    #pragma unroll
    for (int a = 0; a < 8; a++)
        #pragma unroll
        for (int c = 0; c < 4; c++) oacc[a][c] = 0.f;

    for (int kt = 0; kt < 16; kt++) {
        // in flight at top: {K[kt], V[kt]}
        CP_WAIT(1);        // K[kt] landed
        __syncthreads();   // K[kt] visible; prev-tile smem fully consumed

        // issue next tile NOW so it overlaps S + softmax + PV
        if (kt < 15) { issueK(kt + 1); issueV(kt + 1); }

        const unsigned skh = sbase + 2u * AK(kt & 1);
        const unsigned skl = skh + 2u * 9216;

        // ---- S = Q K^T (3-pass split): 16 n8-tiles of keys ----
        float sacc[16][4];
        #pragma unroll
        for (int a = 0; a < 16; a++)
            #pragma unroll
            for (int c = 0; c < 4; c++) sacc[a][c] = 0.f;

        #pragma unroll
        for (int ks = 0; ks < 4; ks++) {
            #pragma unroll
            for (int kb = 0; kb < 8; kb++) {
                unsigned kh4[4], kl4[4];
                const unsigned off = 2u * ((kb * 16 + browo) * TST + ks * 16 + bko);
                ldm_x4(kh4, skh + off);
                ldm_x4(kl4, skl + off);
                #pragma unroll
                for (int j = 0; j < 2; j++) {
                    const int nt = kb * 2 + j;
                    mma16816(sacc[nt], qh[ks], &kh4[2 * j]);
                    mma16816(sacc[nt], qh[ks], &kl4[2 * j]);
                    mma16816(sacc[nt], ql[ks], &kh4[2 * j]);
                }
            }
        }

        // ---- softmax (registers + quad shuffles only) ----
        float mx0 = -INFINITY, mx1 = -INFINITY;
        #pragma unroll
        for (int nt = 0; nt < 16; nt++) {
            mx0 = fmaxf(mx0, fmaxf(sacc[nt][0], sacc[nt][1]));
            mx1 = fmaxf(mx1, fmaxf(sacc[nt][2], sacc[nt][3]));
        }
        mx0 = fmaxf(mx0, __shfl_xor_sync(0xffffffffu, mx0, 1));
        mx0 = fmaxf(mx0, __shfl_xor_sync(0xffffffffu, mx0, 2));
        mx1 = fmaxf(mx1, __shfl_xor_sync(0xffffffffu, mx1, 1));
        mx1 = fmaxf(mx1, __shfl_xor_sync(0xffffffffu, mx1, 2));
        const float mn0 = fmaxf(m_run[0], mx0);
        const float mn1 = fmaxf(m_run[1], mx1);
        const float al0 = __expf(m_run[0] - mn0);
        const float al1 = __expf(m_run[1] - mn1);
        m_run[0] = mn0; m_run[1] = mn1;

        unsigned ph[8][4], pl[8][4];
        float s0 = 0.f, s1 = 0.f;
        #pragma unroll
        for (int kb = 0; kb < 8; kb++) {
            #pragma unroll
            for (int j = 0; j < 2; j++) {
                const int nt = kb * 2 + j;
                const float p0 = __expf(sacc[nt][0] - mn0);
                const float p1 = __expf(sacc[nt][1] - mn0);
                const float p2 = __expf(sacc[nt][2] - mn1);
                const float p3 = __expf(sacc[nt][3] - mn1);
                s0 += p0 + p1;
                s1 += p2 + p3;
                split2(p0, p1, ph[kb][2 * j + 0], pl[kb][2 * j + 0]);
                split2(p2, p3, ph[kb][2 * j + 1], pl[kb][2 * j + 1]);
            }
        }
        s0 += __shfl_xor_sync(0xffffffffu, s0, 1);
        s0 += __shfl_xor_sync(0xffffffffu, s0, 2);
        s1 += __shfl_xor_sync(0xffffffffu, s1, 1);
        s1 += __shfl_xor_sync(0xffffffffu, s1, 2);
        l_run[0] = l_run[0] * al0 + s0;
        l_run[1] = l_run[1] * al1 + s1;
        #pragma unroll
        for (int ot = 0; ot < 8; ot++) {
            oacc[ot][0] *= al0; oacc[ot][1] *= al0;
            oacc[ot][2] *= al1; oacc[ot][3] *= al1;
        }

        // wait for V[kt] (leave next-tile K/V in flight)
        if (kt < 15) { CP_WAIT(2); } else { CP_WAIT(0); }
        __syncthreads();   // V[kt] visible to all

        const unsigned svh = sbase + 2u * AV(kt & 1);
        const unsigned svl = svh + 2u * 9216;

        // ---- O += P V (3-pass split) ----
        #pragma unroll
        for (int ks = 0; ks < 8; ks++) {
            const int kr = ks * 16 + (g & 1) * 8 + (lane & 7);
            #pragma unroll
            for (int eb = 0; eb < 4; eb++) {
                unsigned vh4[4], vl4[4];
                const unsigned voff = 2u * (kr * TST + eb * 16 + (g >> 1) * 8);
                ldm_x4_t(vh4, svh + voff);
                ldm_x4_t(vl4, svl + voff);
                #pragma unroll
                for (int j = 0; j < 2; j++) {
                    const int ot = eb * 2 + j;
                    mma16816(oacc[ot], ph[ks], &vh4[2 * j]);
                    mma16816(oacc[ot], ph[ks], &vl4[2 * j]);
                    mma16816(oacc[ot], pl[ks], &vh4[2 * j]);
                }
            }
        }
        // next iteration's top barrier orders buffer reuse
    }

    // Epilogue: normalize, split to bf16, write g_A2 (concat layout)
    const int bb = bh >> 4, hh = bh & 15;
    const int r0 = w * 16 + (lane >> 2);
    const float inv0 = 1.f / l_run[0];
    const float inv1 = 1.f / l_run[1];
    const size_t mrow0 = ((size_t)bb * SEQ + q0 + r0) * D_MODEL + hh * HEAD_DIM;
    const size_t mrow1 = ((size_t)bb * SEQ + q0 + r0 + 8) * D_MODEL + hh * HEAD_DIM;
    #pragma unroll
    for (int ot = 0; ot < 8; ot++) {
        const int e = ot * 8 + (lane & 3) * 2;
        unsigned ph, pl;
        split2(oacc[ot][0] * inv0, oacc[ot][1] * inv0, ph, pl);
        *reinterpret_cast<unsigned*>(g_A2h + mrow0 + e) = ph;
        *reinterpret_cast<unsigned*>(g_A2l + mrow0 + e) = pl;
        split2(oacc[ot][2] * inv1, oacc[ot][3] * inv1, ph, pl);
        *reinterpret_cast<unsigned*>(g_A2h + mrow1 + e) = ph;
        *reinterpret_cast<unsigned*>(g_A2l + mrow1 + e) = pl;
    }
}

// ============================================================================
extern "C" void kernel_launch(void* const* d_in, const int* in_sizes, int n_in,
                              void* d_out, int out_size)
{
    const float* x  = (const float*)d_in[0];
    const float* Wq = (const float*)d_in[1];
    const float* bq = (const float*)d_in[2];
    const float* Wk = (const float*)d_in[3];
    const float* bk = (const float*)d_in[4];
    const float* Wv = (const float*)d_in[5];
    const float* bv = (const float*)d_in[6];
    const float* Wo = (const float*)d_in[7];
    const float* bo = (const float*)d_in[8];
    float* out = (float*)d_out;

    cudaFuncSetAttribute(mm_mma, cudaFuncAttributeMaxDynamicSharedMemorySize, MM_SMEM);
    cudaFuncSetAttribute(attn_mma, cudaFuncAttributeMaxDynamicSharedMemorySize, ATTN_SMEM);

    split_x<<<(M_TOTAL * D_MODEL) / 1024, 256>>>(x);
    conv_wqkv<<<(NQKV * D_MODEL) / 256, 256>>>(Wq, bq, Wk, bk, Wv, bv);
    conv_wo<<<(D_MODEL * D_MODEL) / 256, 256>>>(Wo);

    mm_mma<<<dim3(NQKV / 128, M_TOTAL / 128), 256, MM_SMEM>>>(nullptr, nullptr, 1);
    attn_mma<<<dim3(SEQ / 128, NBH), 256, ATTN_SMEM>>>();
    mm_mma<<<dim3(D_MODEL / 128, M_TOTAL / 128), 256, MM_SMEM>>>(bo, out, 0);
}

// round 8
// speedup vs baseline: 3.2846x; 1.0634x over previous
#include <cuda_runtime.h>
#include <cuda_bf16.h>
#include <math.h>

typedef __nv_bfloat16 bf16;

#define D_MODEL   1024
#define NUM_HEADS 16
#define HEAD_DIM  64
#define BATCH     4
#define SEQ       2048
#define M_TOTAL   (BATCH * SEQ)   // 8192
#define NQKV      (3 * D_MODEL)   // 3072
#define NBH       (BATCH * NUM_HEADS)  // 64

// ============================================================================
// Device global scratch (allocation-free rule)
// ============================================================================
__device__ bf16 g_Xh[M_TOTAL * D_MODEL], g_Xl[M_TOTAL * D_MODEL];
__device__ bf16 g_Bqkv_h[NQKV * D_MODEL], g_Bqkv_l[NQKV * D_MODEL];   // [n][k]
__device__ bf16 g_Wo_h[D_MODEL * D_MODEL], g_Wo_l[D_MODEL * D_MODEL]; // [n][k]
__device__ float g_bias_qkv[NQKV];
__device__ bf16 g_qh[NBH * SEQ * HEAD_DIM], g_ql[NBH * SEQ * HEAD_DIM];
__device__ bf16 g_kh[NBH * SEQ * HEAD_DIM], g_kl[NBH * SEQ * HEAD_DIM];
__device__ bf16 g_vh[NBH * SEQ * HEAD_DIM], g_vl[NBH * SEQ * HEAD_DIM];
__device__ bf16 g_A2h[M_TOTAL * D_MODEL], g_A2l[M_TOTAL * D_MODEL];

// ============================================================================
// PTX helpers (portable, compute_103-safe)
// ============================================================================
__device__ __forceinline__ unsigned smem_u32(const void* p) {
    unsigned a;
    asm("{ .reg .u64 t; cvta.to.shared.u64 t, %1; cvt.u32.u64 %0, t; }"
        : "=r"(a) : "l"(p));
    return a;
}
__device__ __forceinline__ void ldm_x4(unsigned* r, unsigned addr) {
    asm volatile("ldmatrix.sync.aligned.m8n8.x4.shared.b16 {%0,%1,%2,%3}, [%4];"
        : "=r"(r[0]), "=r"(r[1]), "=r"(r[2]), "=r"(r[3]) : "r"(addr));
}
__device__ __forceinline__ void ldm_x4_t(unsigned* r, unsigned addr) {
    asm volatile("ldmatrix.sync.aligned.m8n8.x4.trans.shared.b16 {%0,%1,%2,%3}, [%4];"
        : "=r"(r[0]), "=r"(r[1]), "=r"(r[2]), "=r"(r[3]) : "r"(addr));
}
__device__ __forceinline__ void mma16816(float* c, const unsigned* a, const unsigned* b) {
    asm volatile("mma.sync.aligned.m16n8k16.row.col.f32.bf16.bf16.f32 "
        "{%0,%1,%2,%3}, {%4,%5,%6,%7}, {%8,%9}, {%0,%1,%2,%3};"
        : "+f"(c[0]), "+f"(c[1]), "+f"(c[2]), "+f"(c[3])
        : "r"(a[0]), "r"(a[1]), "r"(a[2]), "r"(a[3]), "r"(b[0]), "r"(b[1]));
}
__device__ __forceinline__ void cp_async16(unsigned saddr, const void* gptr) {
    asm volatile("cp.async.cg.shared.global [%0], [%1], 16;"
                 :: "r"(saddr), "l"(gptr) : "memory");
}
#define CP_COMMIT() asm volatile("cp.async.commit_group;" ::: "memory")
#define CP_WAIT(N)  asm volatile("cp.async.wait_group %0;" :: "n"(N) : "memory")

__device__ __forceinline__ unsigned pack_bf2(float lo, float hi) {
    unsigned d;
    asm("cvt.rn.bf16x2.f32 %0, %1, %2;" : "=r"(d) : "f"(hi), "f"(lo));
    return d;
}
__device__ __forceinline__ void split2(float v0, float v1, unsigned& ph, unsigned& pl) {
    float h0 = __bfloat162float(__float2bfloat16(v0));
    float h1 = __bfloat162float(__float2bfloat16(v1));
    ph = pack_bf2(v0, v1);
    pl = pack_bf2(v0 - h0, v1 - h1);
}

// ============================================================================
// Conversion kernels
// ============================================================================
__global__ __launch_bounds__(256) void split_x(const float* __restrict__ x) {
    size_t i = ((size_t)blockIdx.x * 256 + threadIdx.x) * 4;
    float4 v = *reinterpret_cast<const float4*>(x + i);
    float f[4] = {v.x, v.y, v.z, v.w};
    #pragma unroll
    for (int j = 0; j < 4; j++) {
        bf16 h = __float2bfloat16(f[j]);
        g_Xh[i + j] = h;
        g_Xl[i + j] = __float2bfloat16(f[j] - __bfloat162float(h));
    }
}

__global__ __launch_bounds__(256) void conv_wqkv(
    const float* __restrict__ Wq, const float* __restrict__ bq,
    const float* __restrict__ Wk, const float* __restrict__ bk,
    const float* __restrict__ Wv, const float* __restrict__ bv) {
    size_t idx = (size_t)blockIdx.x * 256 + threadIdx.x;  // n*1024 + k
    int n = (int)(idx >> 10), k = (int)(idx & 1023);
    int proj = n >> 10, nc = n & 1023, h = nc >> 6, e = nc & 63;
    const float* W = (proj == 0) ? Wq : (proj == 1) ? Wk : Wv;
    float v = W[((size_t)h * D_MODEL + k) * HEAD_DIM + e];
    bf16 hh = __float2bfloat16(v);
    g_Bqkv_h[idx] = hh;
    g_Bqkv_l[idx] = __float2bfloat16(v - __bfloat162float(hh));
    if (k == 0) {
        const float* b = (proj == 0) ? bq : (proj == 1) ? bk : bv;
        g_bias_qkv[n] = b[nc];
    }
}

__global__ __launch_bounds__(256) void conv_wo(const float* __restrict__ Wo) {
    size_t idx = (size_t)blockIdx.x * 256 + threadIdx.x;
    int n = (int)(idx >> 10), k = (int)(idx & 1023);
    float v = Wo[(size_t)k * D_MODEL + n];
    bf16 hh = __float2bfloat16(v);
    g_Wo_h[idx] = hh;
    g_Wo_l[idx] = __float2bfloat16(v - __bfloat162float(hh));
}

// ============================================================================
// GEMM on mma.sync, 2 CTAs/SM: BK=32, 2-stage cp.async, stride 40 el (80 B).
// CTA 128x128, 256 threads, warps 2(M)x4(N), warp tile 64x32, 3-pass split.
// (unchanged from R7)
// ============================================================================
#define AST 40
#define MMS_A_H 0
#define MMS_A_L (128 * AST)
#define MMS_B_H (2 * 128 * AST)
#define MMS_B_L (3 * 128 * AST)
#define STAGE_EL (4 * 128 * AST)          // 20480 el = 40960 B
#define MM_SMEM  (2 * STAGE_EL * 2)       // 81920 B per CTA

__global__ __launch_bounds__(256, 2) void mm_mma(const float* __restrict__ bias_ext,
                                                 float* __restrict__ outp, int mode) {
    extern __shared__ __align__(16) bf16 smm[];
    const unsigned sbase = smem_u32(smm);
    const int tid = threadIdx.x;
    const int lane = tid & 31;
    const int w = tid >> 5;
    const int mw = w >> 2, nw = w & 3;
    const int n0 = blockIdx.x * 128;
    const int m0 = blockIdx.y * 128;

    const bf16* __restrict__ Ahg = (mode == 1) ? g_Xh : g_A2h;
    const bf16* __restrict__ Alg = (mode == 1) ? g_Xl : g_A2l;
    const bf16* __restrict__ Bhg = (mode == 1) ? g_Bqkv_h : g_Wo_h;
    const bf16* __restrict__ Blg = (mode == 1) ? g_Bqkv_l : g_Wo_l;
    const float* __restrict__ bias = (mode == 1) ? g_bias_qkv : bias_ext;

    float acc[4][4][4];
    #pragma unroll
    for (int a = 0; a < 4; a++)
        #pragma unroll
        for (int b = 0; b < 4; b++)
            #pragma unroll
            for (int c = 0; c < 4; c++) acc[a][b][c] = 0.f;

    auto issue = [&](int kc) {
        const int k0 = kc * 32;
        const unsigned sst = sbase + (unsigned)(2 * STAGE_EL) * (kc & 1);
        #pragma unroll
        for (int i = 0; i < 2; i++) {
            const int t = tid + 256 * i;
            const int row = t >> 2, slot = t & 3;
            const unsigned so = 2u * (row * AST + slot * 8);
            const size_t ga = (size_t)(m0 + row) * D_MODEL + k0 + slot * 8;
            const size_t gb = (size_t)(n0 + row) * D_MODEL + k0 + slot * 8;
            cp_async16(sst + 2u * MMS_A_H + so, Ahg + ga);
            cp_async16(sst + 2u * MMS_A_L + so, Alg + ga);
            cp_async16(sst + 2u * MMS_B_H + so, Bhg + gb);
            cp_async16(sst + 2u * MMS_B_L + so, Blg + gb);
        }
        CP_COMMIT();
    };

    issue(0);

    for (int kc = 0; kc < 32; kc++) {
        CP_WAIT(0);
        __syncthreads();
        if (kc + 1 < 32) issue(kc + 1);

        const unsigned sst = sbase + (unsigned)(2 * STAGE_EL) * (kc & 1);
        #pragma unroll
        for (int ks = 0; ks < 2; ks++) {
            unsigned ah[4][4], al[4][4], bh[4][2], bl[4][2];
            const int arow = mw * 64 + (lane & 15);
            const int acol = ks * 16 + (lane >> 4) * 8;
            #pragma unroll
            for (int mt = 0; mt < 4; mt++) {
                const unsigned off = 2u * ((arow + mt * 16) * AST + acol);
                ldm_x4(ah[mt], sst + 2 * MMS_A_H + off);
                ldm_x4(al[mt], sst + 2 * MMS_A_L + off);
            }
            const int g = lane >> 3;
            const int browo = (g >> 1) * 8 + (lane & 7);
            const int bko = (g & 1) * 8;
            #pragma unroll
            for (int np = 0; np < 2; np++) {
                const unsigned off = 2u * ((nw * 32 + np * 16 + browo) * AST + ks * 16 + bko);
                ldm_x4(&bh[np * 2][0], sst + 2 * MMS_B_H + off);
                ldm_x4(&bl[np * 2][0], sst + 2 * MMS_B_L + off);
            }
            #pragma unroll
            for (int mt = 0; mt < 4; mt++)
                #pragma unroll
                for (int nt = 0; nt < 4; nt++) {
                    mma16816(acc[mt][nt], ah[mt], bh[nt]);
                    mma16816(acc[mt][nt], ah[mt], bl[nt]);
                    mma16816(acc[mt][nt], al[mt], bh[nt]);
                }
        }
    }

    // Epilogue
    #pragma unroll
    for (int mt = 0; mt < 4; mt++) {
        const int r0 = m0 + mw * 64 + mt * 16 + (lane >> 2);
        #pragma unroll
        for (int nt = 0; nt < 4; nt++) {
            const int c = n0 + nw * 32 + nt * 8 + (lane & 3) * 2;
            const float b0 = bias[c], b1 = bias[c + 1];
            #pragma unroll
            for (int h2 = 0; h2 < 2; h2++) {
                const int r = r0 + h2 * 8;
                float v0 = acc[mt][nt][h2 * 2 + 0] + b0;
                float v1 = acc[mt][nt][h2 * 2 + 1] + b1;
                if (mode == 0) {
                    float2 vv = make_float2(v0, v1);
                    *reinterpret_cast<float2*>(outp + (size_t)r * D_MODEL + c) = vv;
                } else {
                    const int proj = c >> 10, nc = c & 1023, hh = nc >> 6, e = nc & 63;
                    if (proj == 0) { v0 *= 0.125f; v1 *= 0.125f; }
                    bf16* dh = (proj == 0) ? g_qh : (proj == 1) ? g_kh : g_vh;
                    bf16* dl = (proj == 0) ? g_ql : (proj == 1) ? g_kl : g_vl;
                    const size_t idx =
                        (((size_t)((r >> 11) * NUM_HEADS + hh)) * SEQ + (r & 2047)) * HEAD_DIM + e;
                    unsigned ph, pl;
                    split2(v0, v1, ph, pl);
                    *reinterpret_cast<unsigned*>(dh + idx) = ph;
                    *reinterpret_cast<unsigned*>(dl + idx) = pl;
                }
            }
        }
    }
}

// ============================================================================
// Flash attention, FA2-style, 2 CTAs/SM: 128 q-rows x 64-key tiles.
// 8 warps; warp owns 16 q-rows. Q fragments re-LDSM'd from smem each tile
// (register cap 128 for 2-CTA residency). K/V double-buffered, issued early.
// smem: Q(hi,lo) 36.9KB + K 2x18.4KB + V 2x18.4KB = 110.6KB per CTA.
// ============================================================================
#define TST 72
#define AQ_H 0
#define AQ_L 9216
#define AKH(s) (18432 + (s) * 9216)
#define AKL(s) (18432 + (s) * 9216 + 4608)
#define AVH(s) (36864 + (s) * 9216)
#define AVL(s) (36864 + (s) * 9216 + 4608)
#define ATTN_SMEM (55296 * 2)   // 110592 B

__global__ __launch_bounds__(256, 2) void attn_mma() {
    extern __shared__ __align__(16) bf16 smm[];
    const unsigned sbase = smem_u32(smm);
    const int tid = threadIdx.x;
    const int lane = tid & 31;
    const int w = tid >> 5;
    const int q0 = blockIdx.x * 128;
    const int bh = blockIdx.y;
    const size_t gbase = (size_t)bh * SEQ * HEAD_DIM;

    const int g = lane >> 3;
    const int browo = (g >> 1) * 8 + (lane & 7);
    const int bko = (g & 1) * 8;

    auto issueK = [&](int kt2) {
        const int t0 = kt2 * 64;
        const int s = kt2 & 1;
        #pragma unroll
        for (int i = 0; i < 2; i++) {
            const int t = tid + 256 * i;
            const int row = t >> 3, slot = t & 7;
            const unsigned so = 2u * (row * TST + slot * 8);
            const size_t gk = gbase + (size_t)(t0 + row) * HEAD_DIM + slot * 8;
            cp_async16(sbase + 2u * AKH(s) + so, g_kh + gk);
            cp_async16(sbase + 2u * AKL(s) + so, g_kl + gk);
        }
        CP_COMMIT();
    };
    auto issueV = [&](int kt2) {
        const int t0 = kt2 * 64;
        const int s = kt2 & 1;
        #pragma unroll
        for (int i = 0; i < 2; i++) {
            const int t = tid + 256 * i;
            const int row = t >> 3, slot = t & 7;
            const unsigned so = 2u * (row * TST + slot * 8);
            const size_t gv = gbase + (size_t)(t0 + row) * HEAD_DIM + slot * 8;
            cp_async16(sbase + 2u * AVH(s) + so, g_vh + gv);
            cp_async16(sbase + 2u * AVL(s) + so, g_vl + gv);
        }
        CP_COMMIT();
    };

    issueK(0);
    issueV(0);

    // stage Q (hi+lo) into smem
    #pragma unroll
    for (int i = 0; i < 4; i++) {
        const int t = tid + 256 * i;
        const int row = t >> 3, slot = t & 7;
        const int so = row * TST + slot * 8;
        const size_t gq = gbase + (size_t)(q0 + row) * HEAD_DIM + slot * 8;
        *reinterpret_cast<float4*>(smm + AQ_H + so) = *reinterpret_cast<const float4*>(g_qh + gq);
        *reinterpret_cast<float4*>(smm + AQ_L + so) = *reinterpret_cast<const float4*>(g_ql + gq);
    }
    __syncthreads();

    float m_run[2] = {-INFINITY, -INFINITY};
    float l_run[2] = {0.f, 0.f};
    float oacc[8][4];
    #pragma unroll
    for (int a = 0; a < 8; a++)
        #pragma unroll
        for (int c = 0; c < 4; c++) oacc[a][c] = 0.f;

    for (int kt = 0; kt < 32; kt++) {
        // in flight at top: {K[kt], V[kt]}
        CP_WAIT(1);        // K[kt] landed
        __syncthreads();   // K[kt] visible; prev-tile smem fully consumed

        if (kt < 31) { issueK(kt + 1); issueV(kt + 1); }

        const unsigned skh = sbase + 2u * AKH(kt & 1);
        const unsigned skl = sbase + 2u * AKL(kt & 1);

        // ---- S = Q K^T (3-pass split): 8 n8-tiles of keys ----
        float sacc[8][4];
        #pragma unroll
        for (int a = 0; a < 8; a++)
            #pragma unroll
            for (int c = 0; c < 4; c++) sacc[a][c] = 0.f;

        #pragma unroll
        for (int ks = 0; ks < 4; ks++) {
            unsigned qh4[4], ql4[4];
            const int arow = w * 16 + (lane & 15);
            const unsigned qoff = 2u * (arow * TST + ks * 16 + (lane >> 4) * 8);
            ldm_x4(qh4, sbase + 2 * AQ_H + qoff);
            ldm_x4(ql4, sbase + 2 * AQ_L + qoff);
            #pragma unroll
            for (int kb = 0; kb < 4; kb++) {
                unsigned kh4[4], kl4[4];
                const unsigned off = 2u * ((kb * 16 + browo) * TST + ks * 16 + bko);
                ldm_x4(kh4, skh + off);
                ldm_x4(kl4, skl + off);
                #pragma unroll
                for (int j = 0; j < 2; j++) {
                    const int nt = kb * 2 + j;
                    mma16816(sacc[nt], qh4, &kh4[2 * j]);
                    mma16816(sacc[nt], qh4, &kl4[2 * j]);
                    mma16816(sacc[nt], ql4, &kh4[2 * j]);
                }
            }
        }

        // ---- softmax (registers + quad shuffles only) ----
        float mx0 = -INFINITY, mx1 = -INFINITY;
        #pragma unroll
        for (int nt = 0; nt < 8; nt++) {
            mx0 = fmaxf(mx0, fmaxf(sacc[nt][0], sacc[nt][1]));
            mx1 = fmaxf(mx1, fmaxf(sacc[nt][2], sacc[nt][3]));
        }
        mx0 = fmaxf(mx0, __shfl_xor_sync(0xffffffffu, mx0, 1));
        mx0 = fmaxf(mx0, __shfl_xor_sync(0xffffffffu, mx0, 2));
        mx1 = fmaxf(mx1, __shfl_xor_sync(0xffffffffu, mx1, 1));
        mx1 = fmaxf(mx1, __shfl_xor_sync(0xffffffffu, mx1, 2));
        const float mn0 = fmaxf(m_run[0], mx0);
        const float mn1 = fmaxf(m_run[1], mx1);
        const float al0 = __expf(m_run[0] - mn0);
        const float al1 = __expf(m_run[1] - mn1);
        m_run[0] = mn0; m_run[1] = mn1;

        unsigned ph[4][4], pl[4][4];
        float s0 = 0.f, s1 = 0.f;
        #pragma unroll
        for (int kb = 0; kb < 4; kb++) {
            #pragma unroll
            for (int j = 0; j < 2; j++) {
                const int nt = kb * 2 + j;
                const float p0 = __expf(sacc[nt][0] - mn0);
                const float p1 = __expf(sacc[nt][1] - mn0);
                const float p2 = __expf(sacc[nt][2] - mn1);
                const float p3 = __expf(sacc[nt][3] - mn1);
                s0 += p0 + p1;
                s1 += p2 + p3;
                split2(p0, p1, ph[kb][2 * j + 0], pl[kb][2 * j + 0]);
                split2(p2, p3, ph[kb][2 * j + 1], pl[kb][2 * j + 1]);
            }
        }
        s0 += __shfl_xor_sync(0xffffffffu, s0, 1);
        s0 += __shfl_xor_sync(0xffffffffu, s0, 2);
        s1 += __shfl_xor_sync(0xffffffffu, s1, 1);
        s1 += __shfl_xor_sync(0xffffffffu, s1, 2);
        l_run[0] = l_run[0] * al0 + s0;
        l_run[1] = l_run[1] * al1 + s1;
        #pragma unroll
        for (int ot = 0; ot < 8; ot++) {
            oacc[ot][0] *= al0; oacc[ot][1] *= al0;
            oacc[ot][2] *= al1; oacc[ot][3] *= al1;
        }

        // wait for V[kt] (leave next-tile K/V in flight)
        if (kt < 31) { CP_WAIT(2); } else { CP_WAIT(0); }
        __syncthreads();   // V[kt] visible

        const unsigned svh = sbase + 2u * AVH(kt & 1);
        const unsigned svl = sbase + 2u * AVL(kt & 1);

        // ---- O += P V (3-pass split): contraction = 64 keys ----
        #pragma unroll
        for (int ks = 0; ks < 4; ks++) {
            const int kr = ks * 16 + (g & 1) * 8 + (lane & 7);
            #pragma unroll
            for (int eb = 0; eb < 4; eb++) {
                unsigned vh4[4], vl4[4];
                const unsigned voff = 2u * (kr * TST + eb * 16 + (g >> 1) * 8);
                ldm_x4_t(vh4, svh + voff);
                ldm_x4_t(vl4, svl + voff);
                #pragma unroll
                for (int j = 0; j < 2; j++) {
                    const int ot = eb * 2 + j;
                    mma16816(oacc[ot], ph[ks], &vh4[2 * j]);
                    mma16816(oacc[ot], ph[ks], &vl4[2 * j]);
                    mma16816(oacc[ot], pl[ks], &vh4[2 * j]);
                }
            }
        }
        // next iteration's top barrier orders buffer reuse
    }

    // Epilogue: normalize, split to bf16, write g_A2 (concat layout)
    const int bb = bh >> 4, hh = bh & 15;
    const int r0 = w * 16 + (lane >> 2);
    const float inv0 = 1.f / l_run[0];
    const float inv1 = 1.f / l_run[1];
    const size_t mrow0 = ((size_t)bb * SEQ + q0 + r0) * D_MODEL + hh * HEAD_DIM;
    const size_t mrow1 = ((size_t)bb * SEQ + q0 + r0 + 8) * D_MODEL + hh * HEAD_DIM;
    #pragma unroll
    for (int ot = 0; ot < 8; ot++) {
        const int e = ot * 8 + (lane & 3) * 2;
        unsigned ph, pl;
        split2(oacc[ot][0] * inv0, oacc[ot][1] * inv0, ph, pl);
        *reinterpret_cast<unsigned*>(g_A2h + mrow0 + e) = ph;
        *reinterpret_cast<unsigned*>(g_A2l + mrow0 + e) = pl;
        split2(oacc[ot][2] * inv1, oacc[ot][3] * inv1, ph, pl);
        *reinterpret_cast<unsigned*>(g_A2h + mrow1 + e) = ph;
        *reinterpret_cast<unsigned*>(g_A2l + mrow1 + e) = pl;
    }
}

// ============================================================================
extern "C" void kernel_launch(void* const* d_in, const int* in_sizes, int n_in,
                              void* d_out, int out_size)
{
    const float* x  = (const float*)d_in[0];
    const float* Wq = (const float*)d_in[1];
    const float* bq = (const float*)d_in[2];
    const float* Wk = (const float*)d_in[3];
    const float* bk = (const float*)d_in[4];
    const float* Wv = (const float*)d_in[5];
    const float* bv = (const float*)d_in[6];
    const float* Wo = (const float*)d_in[7];
    const float* bo = (const float*)d_in[8];
    float* out = (float*)d_out;

    cudaFuncSetAttribute(mm_mma, cudaFuncAttributeMaxDynamicSharedMemorySize, MM_SMEM);
    cudaFuncSetAttribute(attn_mma, cudaFuncAttributeMaxDynamicSharedMemorySize, ATTN_SMEM);

    split_x<<<(M_TOTAL * D_MODEL) / 1024, 256>>>(x);
    conv_wqkv<<<(NQKV * D_MODEL) / 256, 256>>>(Wq, bq, Wk, bk, Wv, bv);
    conv_wo<<<(D_MODEL * D_MODEL) / 256, 256>>>(Wo);

    mm_mma<<<dim3(NQKV / 128, M_TOTAL / 128), 256, MM_SMEM>>>(nullptr, nullptr, 1);
    attn_mma<<<dim3(SEQ / 128, NBH), 256, ATTN_SMEM>>>();
    mm_mma<<<dim3(D_MODEL / 128, M_TOTAL / 128), 256, MM_SMEM>>>(bo, out, 0);
}

// round 9
// speedup vs baseline: 3.8047x; 1.1584x over previous
#include <cuda_runtime.h>
#include <cuda_bf16.h>
#include <cuda_fp16.h>
#include <math.h>

typedef __nv_bfloat16 bf16;

#define D_MODEL   1024
#define NUM_HEADS 16
#define HEAD_DIM  64
#define BATCH     4
#define SEQ       2048
#define M_TOTAL   (BATCH * SEQ)   // 8192
#define NQKV      (3 * D_MODEL)   // 3072
#define NBH       (BATCH * NUM_HEADS)  // 64

// ============================================================================
// Device global scratch (allocation-free rule)
// ============================================================================
__device__ bf16 g_Xh[M_TOTAL * D_MODEL], g_Xl[M_TOTAL * D_MODEL];
__device__ bf16 g_Bqkv_h[NQKV * D_MODEL], g_Bqkv_l[NQKV * D_MODEL];   // [n][k]
__device__ bf16 g_Wo_h[D_MODEL * D_MODEL], g_Wo_l[D_MODEL * D_MODEL]; // [n][k]
__device__ float g_bias_qkv[NQKV];
__device__ bf16 g_qh[NBH * SEQ * HEAD_DIM], g_ql[NBH * SEQ * HEAD_DIM];
__device__ bf16 g_kh[NBH * SEQ * HEAD_DIM], g_kl[NBH * SEQ * HEAD_DIM];
__device__ __half g_vh[NBH * SEQ * HEAD_DIM];     // V single fp16
__device__ bf16 g_A2h[M_TOTAL * D_MODEL], g_A2l[M_TOTAL * D_MODEL];

// ============================================================================
// PTX helpers (portable, compute_103-safe)
// ============================================================================
__device__ __forceinline__ unsigned smem_u32(const void* p) {
    unsigned a;
    asm("{ .reg .u64 t; cvta.to.shared.u64 t, %1; cvt.u32.u64 %0, t; }"
        : "=r"(a) : "l"(p));
    return a;
}
__device__ __forceinline__ void ldm_x4(unsigned* r, unsigned addr) {
    asm volatile("ldmatrix.sync.aligned.m8n8.x4.shared.b16 {%0,%1,%2,%3}, [%4];"
        : "=r"(r[0]), "=r"(r[1]), "=r"(r[2]), "=r"(r[3]) : "r"(addr));
}
__device__ __forceinline__ void ldm_x4_t(unsigned* r, unsigned addr) {
    asm volatile("ldmatrix.sync.aligned.m8n8.x4.trans.shared.b16 {%0,%1,%2,%3}, [%4];"
        : "=r"(r[0]), "=r"(r[1]), "=r"(r[2]), "=r"(r[3]) : "r"(addr));
}
__device__ __forceinline__ void mma16816(float* c, const unsigned* a, const unsigned* b) {
    asm volatile("mma.sync.aligned.m16n8k16.row.col.f32.bf16.bf16.f32 "
        "{%0,%1,%2,%3}, {%4,%5,%6,%7}, {%8,%9}, {%0,%1,%2,%3};"
        : "+f"(c[0]), "+f"(c[1]), "+f"(c[2]), "+f"(c[3])
        : "r"(a[0]), "r"(a[1]), "r"(a[2]), "r"(a[3]), "r"(b[0]), "r"(b[1]));
}
__device__ __forceinline__ void mma16816h(float* c, const unsigned* a, const unsigned* b) {
    asm volatile("mma.sync.aligned.m16n8k16.row.col.f32.f16.f16.f32 "
        "{%0,%1,%2,%3}, {%4,%5,%6,%7}, {%8,%9}, {%0,%1,%2,%3};"
        : "+f"(c[0]), "+f"(c[1]), "+f"(c[2]), "+f"(c[3])
        : "r"(a[0]), "r"(a[1]), "r"(a[2]), "r"(a[3]), "r"(b[0]), "r"(b[1]));
}
__device__ __forceinline__ void cp_async16(unsigned saddr, const void* gptr) {
    asm volatile("cp.async.cg.shared.global [%0], [%1], 16;"
                 :: "r"(saddr), "l"(gptr) : "memory");
}
#define CP_COMMIT() asm volatile("cp.async.commit_group;" ::: "memory")
#define CP_WAIT(N)  asm volatile("cp.async.wait_group %0;" :: "n"(N) : "memory")

__device__ __forceinline__ unsigned pack_bf2(float lo, float hi) {
    unsigned d;
    asm("cvt.rn.bf16x2.f32 %0, %1, %2;" : "=r"(d) : "f"(hi), "f"(lo));
    return d;
}
__device__ __forceinline__ void split2(float v0, float v1, unsigned& ph, unsigned& pl) {
    float h0 = __bfloat162float(__float2bfloat16(v0));
    float h1 = __bfloat162float(__float2bfloat16(v1));
    ph = pack_bf2(v0, v1);
    pl = pack_bf2(v0 - h0, v1 - h1);
}
__device__ __forceinline__ unsigned pack_h2(float lo, float hi) {
    __half2 h = __floats2half2_rn(lo, hi);
    return *reinterpret_cast<unsigned*>(&h);
}

// ============================================================================
// Conversion kernels
// ============================================================================
__global__ __launch_bounds__(256) void split_x(const float* __restrict__ x) {
    size_t i = ((size_t)blockIdx.x * 256 + threadIdx.x) * 4;
    float4 v = *reinterpret_cast<const float4*>(x + i);
    float f[4] = {v.x, v.y, v.z, v.w};
    #pragma unroll
    for (int j = 0; j < 4; j++) {
        bf16 h = __float2bfloat16(f[j]);
        g_Xh[i + j] = h;
        g_Xl[i + j] = __float2bfloat16(f[j] - __bfloat162float(h));
    }
}

__global__ __launch_bounds__(256) void conv_wqkv(
    const float* __restrict__ Wq, const float* __restrict__ bq,
    const float* __restrict__ Wk, const float* __restrict__ bk,
    const float* __restrict__ Wv, const float* __restrict__ bv) {
    size_t idx = (size_t)blockIdx.x * 256 + threadIdx.x;  // n*1024 + k
    int n = (int)(idx >> 10), k = (int)(idx & 1023);
    int proj = n >> 10, nc = n & 1023, h = nc >> 6, e = nc & 63;
    const float* W = (proj == 0) ? Wq : (proj == 1) ? Wk : Wv;
    float v = W[((size_t)h * D_MODEL + k) * HEAD_DIM + e];
    bf16 hh = __float2bfloat16(v);
    g_Bqkv_h[idx] = hh;
    g_Bqkv_l[idx] = __float2bfloat16(v - __bfloat162float(hh));
    if (k == 0) {
        const float* b = (proj == 0) ? bq : (proj == 1) ? bk : bv;
        g_bias_qkv[n] = b[nc];
    }
}

__global__ __launch_bounds__(256) void conv_wo(const float* __restrict__ Wo) {
    size_t idx = (size_t)blockIdx.x * 256 + threadIdx.x;
    int n = (int)(idx >> 10), k = (int)(idx & 1023);
    float v = Wo[(size_t)k * D_MODEL + n];
    bf16 hh = __float2bfloat16(v);
    g_Wo_h[idx] = hh;
    g_Wo_l[idx] = __float2bfloat16(v - __bfloat162float(hh));
}

// ============================================================================
// GEMM on mma.sync, 2 CTAs/SM: BK=32, 2-stage cp.async, stride 40 el (80 B).
// CTA 128x128, 256 threads, warps 2(M)x4(N), warp tile 64x32, 3-pass split.
// mode 1 epilogue: q/k scattered as split-bf16; v as single fp16.
// ============================================================================
#define AST 40
#define MMS_A_H 0
#define MMS_A_L (128 * AST)
#define MMS_B_H (2 * 128 * AST)
#define MMS_B_L (3 * 128 * AST)
#define STAGE_EL (4 * 128 * AST)          // 20480 el = 40960 B
#define MM_SMEM  (2 * STAGE_EL * 2)       // 81920 B per CTA

__global__ __launch_bounds__(256, 2) void mm_mma(const float* __restrict__ bias_ext,
                                                 float* __restrict__ outp, int mode) {
    extern __shared__ __align__(16) bf16 smm[];
    const unsigned sbase = smem_u32(smm);
    const int tid = threadIdx.x;
    const int lane = tid & 31;
    const int w = tid >> 5;
    const int mw = w >> 2, nw = w & 3;
    const int n0 = blockIdx.x * 128;
    const int m0 = blockIdx.y * 128;

    const bf16* __restrict__ Ahg = (mode == 1) ? g_Xh : g_A2h;
    const bf16* __restrict__ Alg = (mode == 1) ? g_Xl : g_A2l;
    const bf16* __restrict__ Bhg = (mode == 1) ? g_Bqkv_h : g_Wo_h;
    const bf16* __restrict__ Blg = (mode == 1) ? g_Bqkv_l : g_Wo_l;
    const float* __restrict__ bias = (mode == 1) ? g_bias_qkv : bias_ext;

    float acc[4][4][4];
    #pragma unroll
    for (int a = 0; a < 4; a++)
        #pragma unroll
        for (int b = 0; b < 4; b++)
            #pragma unroll
            for (int c = 0; c < 4; c++) acc[a][b][c] = 0.f;

    auto issue = [&](int kc) {
        const int k0 = kc * 32;
        const unsigned sst = sbase + (unsigned)(2 * STAGE_EL) * (kc & 1);
        #pragma unroll
        for (int i = 0; i < 2; i++) {
            const int t = tid + 256 * i;
            const int row = t >> 2, slot = t & 3;
            const unsigned so = 2u * (row * AST + slot * 8);
            const size_t ga = (size_t)(m0 + row) * D_MODEL + k0 + slot * 8;
            const size_t gb = (size_t)(n0 + row) * D_MODEL + k0 + slot * 8;
            cp_async16(sst + 2u * MMS_A_H + so, Ahg + ga);
            cp_async16(sst + 2u * MMS_A_L + so, Alg + ga);
            cp_async16(sst + 2u * MMS_B_H + so, Bhg + gb);
            cp_async16(sst + 2u * MMS_B_L + so, Blg + gb);
        }
        CP_COMMIT();
    };

    issue(0);

    for (int kc = 0; kc < 32; kc++) {
        CP_WAIT(0);
        __syncthreads();
        if (kc + 1 < 32) issue(kc + 1);

        const unsigned sst = sbase + (unsigned)(2 * STAGE_EL) * (kc & 1);
        #pragma unroll
        for (int ks = 0; ks < 2; ks++) {
            unsigned ah[4][4], al[4][4], bh[4][2], bl[4][2];
            const int arow = mw * 64 + (lane & 15);
            const int acol = ks * 16 + (lane >> 4) * 8;
            #pragma unroll
            for (int mt = 0; mt < 4; mt++) {
                const unsigned off = 2u * ((arow + mt * 16) * AST + acol);
                ldm_x4(ah[mt], sst + 2 * MMS_A_H + off);
                ldm_x4(al[mt], sst + 2 * MMS_A_L + off);
            }
            const int g = lane >> 3;
            const int browo = (g >> 1) * 8 + (lane & 7);
            const int bko = (g & 1) * 8;
            #pragma unroll
            for (int np = 0; np < 2; np++) {
                const unsigned off = 2u * ((nw * 32 + np * 16 + browo) * AST + ks * 16 + bko);
                ldm_x4(&bh[np * 2][0], sst + 2 * MMS_B_H + off);
                ldm_x4(&bl[np * 2][0], sst + 2 * MMS_B_L + off);
            }
            #pragma unroll
            for (int mt = 0; mt < 4; mt++)
                #pragma unroll
                for (int nt = 0; nt < 4; nt++) {
                    mma16816(acc[mt][nt], ah[mt], bh[nt]);
                    mma16816(acc[mt][nt], ah[mt], bl[nt]);
                    mma16816(acc[mt][nt], al[mt], bh[nt]);
                }
        }
    }

    // Epilogue
    #pragma unroll
    for (int mt = 0; mt < 4; mt++) {
        const int r0 = m0 + mw * 64 + mt * 16 + (lane >> 2);
        #pragma unroll
        for (int nt = 0; nt < 4; nt++) {
            const int c = n0 + nw * 32 + nt * 8 + (lane & 3) * 2;
            const float b0 = bias[c], b1 = bias[c + 1];
            #pragma unroll
            for (int h2 = 0; h2 < 2; h2++) {
                const int r = r0 + h2 * 8;
                float v0 = acc[mt][nt][h2 * 2 + 0] + b0;
                float v1 = acc[mt][nt][h2 * 2 + 1] + b1;
                if (mode == 0) {
                    float2 vv = make_float2(v0, v1);
                    *reinterpret_cast<float2*>(outp + (size_t)r * D_MODEL + c) = vv;
                } else {
                    const int proj = c >> 10, nc = c & 1023, hh = nc >> 6, e = nc & 63;
                    const size_t idx =
                        (((size_t)((r >> 11) * NUM_HEADS + hh)) * SEQ + (r & 2047)) * HEAD_DIM + e;
                    if (proj == 2) {
                        *reinterpret_cast<unsigned*>(g_vh + idx) = pack_h2(v0, v1);
                    } else {
                        if (proj == 0) { v0 *= 0.125f; v1 *= 0.125f; }
                        bf16* dh = (proj == 0) ? g_qh : g_kh;
                        bf16* dl = (proj == 0) ? g_ql : g_kl;
                        unsigned ph, pl;
                        split2(v0, v1, ph, pl);
                        *reinterpret_cast<unsigned*>(dh + idx) = ph;
                        *reinterpret_cast<unsigned*>(dl + idx) = pl;
                    }
                }
            }
        }
    }
}

// ============================================================================
// Flash attention, FA2-style, 2 CTAs/SM: 128 q-rows x 64-key tiles.
// QK^T: split-bf16 3-pass. PV: fp16 P (single) x fp16 V (single), 1 pass.
// smem: Q(hi,lo) 36.9KB + K(hi,lo) 2x18.4KB + V(fp16) 2x9.2KB = 92.2KB/CTA.
// ============================================================================
#define TST 72
#define AQ_H 0
#define AQ_L 9216
#define AKH(s) (18432 + (s) * 9216)
#define AKL(s) (18432 + (s) * 9216 + 4608)
#define AVH(s) (36864 + (s) * 4608)
#define ATTN_SMEM (46080 * 2)   // 92160 B

__global__ __launch_bounds__(256, 2) void attn_mma() {
    extern __shared__ __align__(16) bf16 smm[];
    const unsigned sbase = smem_u32(smm);
    const int tid = threadIdx.x;
    const int lane = tid & 31;
    const int w = tid >> 5;
    const int q0 = blockIdx.x * 128;
    const int bh = blockIdx.y;
    const size_t gbase = (size_t)bh * SEQ * HEAD_DIM;

    const int g = lane >> 3;
    const int browo = (g >> 1) * 8 + (lane & 7);
    const int bko = (g & 1) * 8;

    auto issueK = [&](int kt2) {
        const int t0 = kt2 * 64;
        const int s = kt2 & 1;
        #pragma unroll
        for (int i = 0; i < 2; i++) {
            const int t = tid + 256 * i;
            const int row = t >> 3, slot = t & 7;
            const unsigned so = 2u * (row * TST + slot * 8);
            const size_t gk = gbase + (size_t)(t0 + row) * HEAD_DIM + slot * 8;
            cp_async16(sbase + 2u * AKH(s) + so, g_kh + gk);
            cp_async16(sbase + 2u * AKL(s) + so, g_kl + gk);
        }
        CP_COMMIT();
    };
    auto issueV = [&](int kt2) {
        const int t0 = kt2 * 64;
        const int s = kt2 & 1;
        #pragma unroll
        for (int i = 0; i < 2; i++) {
            const int t = tid + 256 * i;
            const int row = t >> 3, slot = t & 7;
            const unsigned so = 2u * (row * TST + slot * 8);
            const size_t gv = gbase + (size_t)(t0 + row) * HEAD_DIM + slot * 8;
            cp_async16(sbase + 2u * AVH(s) + so, g_vh + gv);
        }
        CP_COMMIT();
    };

    issueK(0);
    issueV(0);

    // stage Q (hi+lo) into smem
    #pragma unroll
    for (int i = 0; i < 4; i++) {
        const int t = tid + 256 * i;
        const int row = t >> 3, slot = t & 7;
        const int so = row * TST + slot * 8;
        const size_t gq = gbase + (size_t)(q0 + row) * HEAD_DIM + slot * 8;
        *reinterpret_cast<float4*>(smm + AQ_H + so) = *reinterpret_cast<const float4*>(g_qh + gq);
        *reinterpret_cast<float4*>(smm + AQ_L + so) = *reinterpret_cast<const float4*>(g_ql + gq);
    }
    __syncthreads();

    float m_run[2] = {-INFINITY, -INFINITY};
    float l_run[2] = {0.f, 0.f};
    float oacc[8][4];
    #pragma unroll
    for (int a = 0; a < 8; a++)
        #pragma unroll
        for (int c = 0; c < 4; c++) oacc[a][c] = 0.f;

    for (int kt = 0; kt < 32; kt++) {
        // in flight at top: {K[kt], V[kt]}
        CP_WAIT(1);        // K[kt] landed
        __syncthreads();   // K[kt] visible; prev-tile smem fully consumed

        if (kt < 31) { issueK(kt + 1); issueV(kt + 1); }

        const unsigned skh = sbase + 2u * AKH(kt & 1);
        const unsigned skl = sbase + 2u * AKL(kt & 1);

        // ---- S = Q K^T (split-bf16 3-pass): 8 n8-tiles of keys ----
        float sacc[8][4];
        #pragma unroll
        for (int a = 0; a < 8; a++)
            #pragma unroll
            for (int c = 0; c < 4; c++) sacc[a][c] = 0.f;

        #pragma unroll
        for (int ks = 0; ks < 4; ks++) {
            unsigned qh4[4], ql4[4];
            const int arow = w * 16 + (lane & 15);
            const unsigned qoff = 2u * (arow * TST + ks * 16 + (lane >> 4) * 8);
            ldm_x4(qh4, sbase + 2 * AQ_H + qoff);
            ldm_x4(ql4, sbase + 2 * AQ_L + qoff);
            #pragma unroll
            for (int kb = 0; kb < 4; kb++) {
                unsigned kh4[4], kl4[4];
                const unsigned off = 2u * ((kb * 16 + browo) * TST + ks * 16 + bko);
                ldm_x4(kh4, skh + off);
                ldm_x4(kl4, skl + off);
                #pragma unroll
                for (int j = 0; j < 2; j++) {
                    const int nt = kb * 2 + j;
                    mma16816(sacc[nt], qh4, &kh4[2 * j]);
                    mma16816(sacc[nt], qh4, &kl4[2 * j]);
                    mma16816(sacc[nt], ql4, &kh4[2 * j]);
                }
            }
        }

        // ---- softmax (registers + quad shuffles only) ----
        float mx0 = -INFINITY, mx1 = -INFINITY;
        #pragma unroll
        for (int nt = 0; nt < 8; nt++) {
            mx0 = fmaxf(mx0, fmaxf(sacc[nt][0], sacc[nt][1]));
            mx1 = fmaxf(mx1, fmaxf(sacc[nt][2], sacc[nt][3]));
        }
        mx0 = fmaxf(mx0, __shfl_xor_sync(0xffffffffu, mx0, 1));
        mx0 = fmaxf(mx0, __shfl_xor_sync(0xffffffffu, mx0, 2));
        mx1 = fmaxf(mx1, __shfl_xor_sync(0xffffffffu, mx1, 1));
        mx1 = fmaxf(mx1, __shfl_xor_sync(0xffffffffu, mx1, 2));
        const float mn0 = fmaxf(m_run[0], mx0);
        const float mn1 = fmaxf(m_run[1], mx1);
        const float al0 = __expf(m_run[0] - mn0);
        const float al1 = __expf(m_run[1] - mn1);
        m_run[0] = mn0; m_run[1] = mn1;

        unsigned ph[4][4];
        float s0 = 0.f, s1 = 0.f;
        #pragma unroll
        for (int kb = 0; kb < 4; kb++) {
            #pragma unroll
            for (int j = 0; j < 2; j++) {
                const int nt = kb * 2 + j;
                const float p0 = __expf(sacc[nt][0] - mn0);
                const float p1 = __expf(sacc[nt][1] - mn0);
                const float p2 = __expf(sacc[nt][2] - mn1);
                const float p3 = __expf(sacc[nt][3] - mn1);
                s0 += p0 + p1;
                s1 += p2 + p3;
                ph[kb][2 * j + 0] = pack_h2(p0, p1);
                ph[kb][2 * j + 1] = pack_h2(p2, p3);
            }
        }
        s0 += __shfl_xor_sync(0xffffffffu, s0, 1);
        s0 += __shfl_xor_sync(0xffffffffu, s0, 2);
        s1 += __shfl_xor_sync(0xffffffffu, s1, 1);
        s1 += __shfl_xor_sync(0xffffffffu, s1, 2);
        l_run[0] = l_run[0] * al0 + s0;
        l_run[1] = l_run[1] * al1 + s1;
        #pragma unroll
        for (int ot = 0; ot < 8; ot++) {
            oacc[ot][0] *= al0; oacc[ot][1] *= al0;
            oacc[ot][2] *= al1; oacc[ot][3] *= al1;
        }

        // wait for V[kt] (leave next-tile K/V in flight)
        if (kt < 31) { CP_WAIT(2); } else { CP_WAIT(0); }
        __syncthreads();   // V[kt] visible

        const unsigned svh = sbase + 2u * AVH(kt & 1);

        // ---- O += P V (fp16 x fp16, single pass): contraction = 64 keys ----
        #pragma unroll
        for (int ks = 0; ks < 4; ks++) {
            const int kr = ks * 16 + (g & 1) * 8 + (lane & 7);
            #pragma unroll
            for (int eb = 0; eb < 4; eb++) {
                unsigned vh4[4];
                const unsigned voff = 2u * (kr * TST + eb * 16 + (g >> 1) * 8);
                ldm_x4_t(vh4, svh + voff);
                #pragma unroll
                for (int j = 0; j < 2; j++) {
                    mma16816h(oacc[eb * 2 + j], ph[ks], &vh4[2 * j]);
                }
            }
        }
        // next iteration's top barrier orders buffer reuse
    }

    // Epilogue: normalize, split to bf16, write g_A2 (concat layout)
    const int bb = bh >> 4, hh = bh & 15;
    const int r0 = w * 16 + (lane >> 2);
    const float inv0 = 1.f / l_run[0];
    const float inv1 = 1.f / l_run[1];
    const size_t mrow0 = ((size_t)bb * SEQ + q0 + r0) * D_MODEL + hh * HEAD_DIM;
    const size_t mrow1 = ((size_t)bb * SEQ + q0 + r0 + 8) * D_MODEL + hh * HEAD_DIM;
    #pragma unroll
    for (int ot = 0; ot < 8; ot++) {
        const int e = ot * 8 + (lane & 3) * 2;
        unsigned ph, pl;
        split2(oacc[ot][0] * inv0, oacc[ot][1] * inv0, ph, pl);
        *reinterpret_cast<unsigned*>(g_A2h + mrow0 + e) = ph;
        *reinterpret_cast<unsigned*>(g_A2l + mrow0 + e) = pl;
        split2(oacc[ot][2] * inv1, oacc[ot][3] * inv1, ph, pl);
        *reinterpret_cast<unsigned*>(g_A2h + mrow1 + e) = ph;
        *reinterpret_cast<unsigned*>(g_A2l + mrow1 + e) = pl;
    }
}

// ============================================================================
extern "C" void kernel_launch(void* const* d_in, const int* in_sizes, int n_in,
                              void* d_out, int out_size)
{
    const float* x  = (const float*)d_in[0];
    const float* Wq = (const float*)d_in[1];
    const float* bq = (const float*)d_in[2];
    const float* Wk = (const float*)d_in[3];
    const float* bk = (const float*)d_in[4];
    const float* Wv = (const float*)d_in[5];
    const float* bv = (const float*)d_in[6];
    const float* Wo = (const float*)d_in[7];
    const float* bo = (const float*)d_in[8];
    float* out = (float*)d_out;

    cudaFuncSetAttribute(mm_mma, cudaFuncAttributeMaxDynamicSharedMemorySize, MM_SMEM);
    cudaFuncSetAttribute(attn_mma, cudaFuncAttributeMaxDynamicSharedMemorySize, ATTN_SMEM);

    split_x<<<(M_TOTAL * D_MODEL) / 1024, 256>>>(x);
    conv_wqkv<<<(NQKV * D_MODEL) / 256, 256>>>(Wq, bq, Wk, bk, Wv, bv);
    conv_wo<<<(D_MODEL * D_MODEL) / 256, 256>>>(Wo);

    mm_mma<<<dim3(NQKV / 128, M_TOTAL / 128), 256, MM_SMEM>>>(nullptr, nullptr, 1);
    attn_mma<<<dim3(SEQ / 128, NBH), 256, ATTN_SMEM>>>();
    mm_mma<<<dim3(D_MODEL / 128, M_TOTAL / 128), 256, MM_SMEM>>>(bo, out, 0);
}

// round 11
// speedup vs baseline: 4.6508x; 1.2224x over previous
#include <cuda_runtime.h>
#include <cuda_bf16.h>
#include <cuda_fp16.h>
#include <math.h>

typedef __nv_bfloat16 bf16;

#define D_MODEL   1024
#define NUM_HEADS 16
#define HEAD_DIM  64
#define BATCH     4
#define SEQ       2048
#define M_TOTAL   (BATCH * SEQ)   // 8192
#define NQKV      (3 * D_MODEL)   // 3072
#define NBH       (BATCH * NUM_HEADS)  // 64

// ============================================================================
// Device global scratch (allocation-free rule)
// ============================================================================
__device__ __half g_Xh[M_TOTAL * D_MODEL], g_Xl[M_TOTAL * D_MODEL];  // X fp16 split
__device__ __half g_Bqkv[NQKV * D_MODEL];                            // [n][k] fp16
__device__ __half g_Wo[D_MODEL * D_MODEL];                           // [n][k] fp16
__device__ float g_bias_qkv[NQKV];
__device__ bf16 g_qh[NBH * SEQ * HEAD_DIM], g_ql[NBH * SEQ * HEAD_DIM];
__device__ bf16 g_kh[NBH * SEQ * HEAD_DIM], g_kl[NBH * SEQ * HEAD_DIM];
__device__ __half g_vh[NBH * SEQ * HEAD_DIM];                        // V fp16
__device__ __half g_A2h[M_TOTAL * D_MODEL], g_A2l[M_TOTAL * D_MODEL]; // attn out fp16 split

// ============================================================================
// PTX helpers (portable, compute_103-safe)
// ============================================================================
__device__ __forceinline__ unsigned smem_u32(const void* p) {
    unsigned a;
    asm("{ .reg .u64 t; cvta.to.shared.u64 t, %1; cvt.u32.u64 %0, t; }"
        : "=r"(a) : "l"(p));
    return a;
}
__device__ __forceinline__ void ldm_x4(unsigned* r, unsigned addr) {
    asm volatile("ldmatrix.sync.aligned.m8n8.x4.shared.b16 {%0,%1,%2,%3}, [%4];"
        : "=r"(r[0]), "=r"(r[1]), "=r"(r[2]), "=r"(r[3]) : "r"(addr));
}
__device__ __forceinline__ void ldm_x4_t(unsigned* r, unsigned addr) {
    asm volatile("ldmatrix.sync.aligned.m8n8.x4.trans.shared.b16 {%0,%1,%2,%3}, [%4];"
        : "=r"(r[0]), "=r"(r[1]), "=r"(r[2]), "=r"(r[3]) : "r"(addr));
}
__device__ __forceinline__ void mma16816(float* c, const unsigned* a, const unsigned* b) {
    asm volatile("mma.sync.aligned.m16n8k16.row.col.f32.bf16.bf16.f32 "
        "{%0,%1,%2,%3}, {%4,%5,%6,%7}, {%8,%9}, {%0,%1,%2,%3};"
        : "+f"(c[0]), "+f"(c[1]), "+f"(c[2]), "+f"(c[3])
        : "r"(a[0]), "r"(a[1]), "r"(a[2]), "r"(a[3]), "r"(b[0]), "r"(b[1]));
}
__device__ __forceinline__ void mma16816h(float* c, const unsigned* a, const unsigned* b) {
    asm volatile("mma.sync.aligned.m16n8k16.row.col.f32.f16.f16.f32 "
        "{%0,%1,%2,%3}, {%4,%5,%6,%7}, {%8,%9}, {%0,%1,%2,%3};"
        : "+f"(c[0]), "+f"(c[1]), "+f"(c[2]), "+f"(c[3])
        : "r"(a[0]), "r"(a[1]), "r"(a[2]), "r"(a[3]), "r"(b[0]), "r"(b[1]));
}
__device__ __forceinline__ void cp_async16(unsigned saddr, const void* gptr) {
    asm volatile("cp.async.cg.shared.global [%0], [%1], 16;"
                 :: "r"(saddr), "l"(gptr) : "memory");
}
#define CP_COMMIT() asm volatile("cp.async.commit_group;" ::: "memory")
#define CP_WAIT(N)  asm volatile("cp.async.wait_group %0;" :: "n"(N) : "memory")

__device__ __forceinline__ unsigned pack_bf2(float lo, float hi) {
    unsigned d;
    asm("cvt.rn.bf16x2.f32 %0, %1, %2;" : "=r"(d) : "f"(hi), "f"(lo));
    return d;
}
__device__ __forceinline__ void split2(float v0, float v1, unsigned& ph, unsigned& pl) {
    float h0 = __bfloat162float(__float2bfloat16(v0));
    float h1 = __bfloat162float(__float2bfloat16(v1));
    ph = pack_bf2(v0, v1);
    pl = pack_bf2(v0 - h0, v1 - h1);
}
__device__ __forceinline__ unsigned pack_h2(float lo, float hi) {
    __half2 h = __floats2half2_rn(lo, hi);
    return *reinterpret_cast<unsigned*>(&h);
}
__device__ __forceinline__ void split2h(float v0, float v1, unsigned& ph, unsigned& pl) {
    float h0 = __half2float(__float2half_rn(v0));
    float h1 = __half2float(__float2half_rn(v1));
    ph = pack_h2(v0, v1);
    pl = pack_h2(v0 - h0, v1 - h1);
}

// ============================================================================
// Conversion kernels
// ============================================================================
__global__ __launch_bounds__(256) void split_x(const float* __restrict__ x) {
    size_t i = ((size_t)blockIdx.x * 256 + threadIdx.x) * 4;
    float4 v = *reinterpret_cast<const float4*>(x + i);
    float f[4] = {v.x, v.y, v.z, v.w};
    #pragma unroll
    for (int j = 0; j < 4; j++) {
        __half h = __float2half_rn(f[j]);
        g_Xh[i + j] = h;
        g_Xl[i + j] = __float2half_rn(f[j] - __half2float(h));
    }
}

__global__ __launch_bounds__(256) void conv_wqkv(
    const float* __restrict__ Wq, const float* __restrict__ bq,
    const float* __restrict__ Wk, const float* __restrict__ bk,
    const float* __restrict__ Wv, const float* __restrict__ bv) {
    size_t idx = (size_t)blockIdx.x * 256 + threadIdx.x;  // n*1024 + k
    int n = (int)(idx >> 10), k = (int)(idx & 1023);
    int proj = n >> 10, nc = n & 1023, h = nc >> 6, e = nc & 63;
    const float* W = (proj == 0) ? Wq : (proj == 1) ? Wk : Wv;
    float v = W[((size_t)h * D_MODEL + k) * HEAD_DIM + e];
    g_Bqkv[idx] = __float2half_rn(v);
    if (k == 0) {
        const float* b = (proj == 0) ? bq : (proj == 1) ? bk : bv;
        g_bias_qkv[n] = b[nc];
    }
}

__global__ __launch_bounds__(256) void conv_wo(const float* __restrict__ Wo) {
    size_t idx = (size_t)blockIdx.x * 256 + threadIdx.x;
    int n = (int)(idx >> 10), k = (int)(idx & 1023);
    g_Wo[idx] = __float2half_rn(Wo[(size_t)k * D_MODEL + n]);
}

// ============================================================================
// GEMM on mma.sync, fp16 2-pass split: C = (Ah+Al) * B^T, fp32 acc.
// 2 CTAs/SM, BK=32, 2-stage cp.async, stride 40 el (80 B).
// CTA 128x128, 256 threads, warps 2(M)x4(N), warp tile 64x32.
// ============================================================================
#define AST 40
#define MMS_A_H 0
#define MMS_A_L (128 * AST)
#define MMS_B   (2 * 128 * AST)
#define STAGE_EL (3 * 128 * AST)          // 15360 el = 30720 B
#define MM_SMEM  (2 * STAGE_EL * 2)       // 61440 B per CTA

__global__ __launch_bounds__(256, 2) void mm_mma(const float* __restrict__ bias_ext,
                                                 float* __restrict__ outp, int mode) {
    extern __shared__ __align__(16) __half smm[];
    const unsigned sbase = smem_u32(smm);
    const int tid = threadIdx.x;
    const int lane = tid & 31;
    const int w = tid >> 5;
    const int mw = w >> 2, nw = w & 3;
    const int n0 = blockIdx.x * 128;
    const int m0 = blockIdx.y * 128;

    const __half* __restrict__ Ahg = (mode == 1) ? g_Xh : g_A2h;
    const __half* __restrict__ Alg = (mode == 1) ? g_Xl : g_A2l;
    const __half* __restrict__ Bg  = (mode == 1) ? g_Bqkv : g_Wo;
    const float* __restrict__ bias = (mode == 1) ? g_bias_qkv : bias_ext;

    float acc[4][4][4];
    #pragma unroll
    for (int a = 0; a < 4; a++)
        #pragma unroll
        for (int b = 0; b < 4; b++)
            #pragma unroll
            for (int c = 0; c < 4; c++) acc[a][b][c] = 0.f;

    auto issue = [&](int kc) {
        const int k0 = kc * 32;
        const unsigned sst = sbase + (unsigned)(2 * STAGE_EL) * (kc & 1);
        #pragma unroll
        for (int i = 0; i < 2; i++) {
            const int t = tid + 256 * i;
            const int row = t >> 2, slot = t & 3;
            const unsigned so = 2u * (row * AST + slot * 8);
            const size_t ga = (size_t)(m0 + row) * D_MODEL + k0 + slot * 8;
            const size_t gb = (size_t)(n0 + row) * D_MODEL + k0 + slot * 8;
            cp_async16(sst + 2u * MMS_A_H + so, Ahg + ga);
            cp_async16(sst + 2u * MMS_A_L + so, Alg + ga);
            cp_async16(sst + 2u * MMS_B + so, Bg + gb);
        }
        CP_COMMIT();
    };

    issue(0);

    for (int kc = 0; kc < 32; kc++) {
        CP_WAIT(0);
        __syncthreads();
        if (kc + 1 < 32) issue(kc + 1);

        const unsigned sst = sbase + (unsigned)(2 * STAGE_EL) * (kc & 1);
        #pragma unroll
        for (int ks = 0; ks < 2; ks++) {
            unsigned ah[4][4], al[4][4], bh[4][2];
            const int arow = mw * 64 + (lane & 15);
            const int acol = ks * 16 + (lane >> 4) * 8;
            #pragma unroll
            for (int mt = 0; mt < 4; mt++) {
                const unsigned off = 2u * ((arow + mt * 16) * AST + acol);
                ldm_x4(ah[mt], sst + 2 * MMS_A_H + off);
                ldm_x4(al[mt], sst + 2 * MMS_A_L + off);
            }
            const int g = lane >> 3;
            const int browo = (g >> 1) * 8 + (lane & 7);
            const int bko = (g & 1) * 8;
            #pragma unroll
            for (int np = 0; np < 2; np++) {
                const unsigned off = 2u * ((nw * 32 + np * 16 + browo) * AST + ks * 16 + bko);
                ldm_x4(&bh[np * 2][0], sst + 2 * MMS_B + off);
            }
            #pragma unroll
            for (int mt = 0; mt < 4; mt++)
                #pragma unroll
                for (int nt = 0; nt < 4; nt++) {
                    mma16816h(acc[mt][nt], ah[mt], bh[nt]);
                    mma16816h(acc[mt][nt], al[mt], bh[nt]);
                }
        }
    }

    // Epilogue
    #pragma unroll
    for (int mt = 0; mt < 4; mt++) {
        const int r0 = m0 + mw * 64 + mt * 16 + (lane >> 2);
        #pragma unroll
        for (int nt = 0; nt < 4; nt++) {
            const int c = n0 + nw * 32 + nt * 8 + (lane & 3) * 2;
            const float b0 = bias[c], b1 = bias[c + 1];
            #pragma unroll
            for (int h2 = 0; h2 < 2; h2++) {
                const int r = r0 + h2 * 8;
                float v0 = acc[mt][nt][h2 * 2 + 0] + b0;
                float v1 = acc[mt][nt][h2 * 2 + 1] + b1;
                if (mode == 0) {
                    float2 vv = make_float2(v0, v1);
                    *reinterpret_cast<float2*>(outp + (size_t)r * D_MODEL + c) = vv;
                } else {
                    const int proj = c >> 10, nc = c & 1023, hh = nc >> 6, e = nc & 63;
                    const size_t idx =
                        (((size_t)((r >> 11) * NUM_HEADS + hh)) * SEQ + (r & 2047)) * HEAD_DIM + e;
                    if (proj == 2) {
                        *reinterpret_cast<unsigned*>(g_vh + idx) = pack_h2(v0, v1);
                    } else {
                        if (proj == 0) { v0 *= 0.125f; v1 *= 0.125f; }
                        bf16* dh = (proj == 0) ? g_qh : g_kh;
                        bf16* dl = (proj == 0) ? g_ql : g_kl;
                        unsigned ph, pl;
                        split2(v0, v1, ph, pl);
                        *reinterpret_cast<unsigned*>(dh + idx) = ph;
                        *reinterpret_cast<unsigned*>(dl + idx) = pl;
                    }
                }
            }
        }
    }
}

// ============================================================================
// Flash attention, FA2-style, 2 CTAs/SM: 128 q-rows x 64-key tiles.
// QK^T: split-bf16 3-pass. PV: fp16 P x fp16 V, 1 pass.
// Epilogue writes fp16 split for the fp16 out-projection.
// NOTE: dynamic smem declared as __half (same 2-byte layout; bf16 data is
// accessed via reinterpret/byte addresses, so only the declared type changed).
// ============================================================================
#define TST 72
#define AQ_H 0
#define AQ_L 9216
#define AKH(s) (18432 + (s) * 9216)
#define AKL(s) (18432 + (s) * 9216 + 4608)
#define AVH(s) (36864 + (s) * 4608)
#define ATTN_SMEM (46080 * 2)   // 92160 B

__global__ __launch_bounds__(256, 2) void attn_mma() {
    extern __shared__ __align__(16) __half smm[];
    const unsigned sbase = smem_u32(smm);
    const int tid = threadIdx.x;
    const int lane = tid & 31;
    const int w = tid >> 5;
    const int q0 = blockIdx.x * 128;
    const int bh = blockIdx.y;
    const size_t gbase = (size_t)bh * SEQ * HEAD_DIM;

    const int g = lane >> 3;
    const int browo = (g >> 1) * 8 + (lane & 7);
    const int bko = (g & 1) * 8;

    auto issueK = [&](int kt2) {
        const int t0 = kt2 * 64;
        const int s = kt2 & 1;
        #pragma unroll
        for (int i = 0; i < 2; i++) {
            const int t = tid + 256 * i;
            const int row = t >> 3, slot = t & 7;
            const unsigned so = 2u * (row * TST + slot * 8);
            const size_t gk = gbase + (size_t)(t0 + row) * HEAD_DIM + slot * 8;
            cp_async16(sbase + 2u * AKH(s) + so, g_kh + gk);
            cp_async16(sbase + 2u * AKL(s) + so, g_kl + gk);
        }
        CP_COMMIT();
    };
    auto issueV = [&](int kt2) {
        const int t0 = kt2 * 64;
        const int s = kt2 & 1;
        #pragma unroll
        for (int i = 0; i < 2; i++) {
            const int t = tid + 256 * i;
            const int row = t >> 3, slot = t & 7;
            const unsigned so = 2u * (row * TST + slot * 8);
            const size_t gv = gbase + (size_t)(t0 + row) * HEAD_DIM + slot * 8;
            cp_async16(sbase + 2u * AVH(s) + so, g_vh + gv);
        }
        CP_COMMIT();
    };

    issueK(0);
    issueV(0);

    // stage Q (hi+lo, bf16 bits) into smem
    #pragma unroll
    for (int i = 0; i < 4; i++) {
        const int t = tid + 256 * i;
        const int row = t >> 3, slot = t & 7;
        const int so = row * TST + slot * 8;
        const size_t gq = gbase + (size_t)(q0 + row) * HEAD_DIM + slot * 8;
        *reinterpret_cast<float4*>(smm + AQ_H + so) = *reinterpret_cast<const float4*>(g_qh + gq);
        *reinterpret_cast<float4*>(smm + AQ_L + so) = *reinterpret_cast<const float4*>(g_ql + gq);
    }
    __syncthreads();

    float m_run[2] = {-INFINITY, -INFINITY};
    float l_run[2] = {0.f, 0.f};
    float oacc[8][4];
    #pragma unroll
    for (int a = 0; a < 8; a++)
        #pragma unroll
        for (int c = 0; c < 4; c++) oacc[a][c] = 0.f;

    for (int kt = 0; kt < 32; kt++) {
        CP_WAIT(1);        // K[kt] landed
        __syncthreads();   // K[kt] visible; prev-tile smem fully consumed

        if (kt < 31) { issueK(kt + 1); issueV(kt + 1); }

        const unsigned skh = sbase + 2u * AKH(kt & 1);
        const unsigned skl = sbase + 2u * AKL(kt & 1);

        // ---- S = Q K^T (split-bf16 3-pass): 8 n8-tiles of keys ----
        float sacc[8][4];
        #pragma unroll
        for (int a = 0; a < 8; a++)
            #pragma unroll
            for (int c = 0; c < 4; c++) sacc[a][c] = 0.f;

        #pragma unroll
        for (int ks = 0; ks < 4; ks++) {
            unsigned qh4[4], ql4[4];
            const int arow = w * 16 + (lane & 15);
            const unsigned qoff = 2u * (arow * TST + ks * 16 + (lane >> 4) * 8);
            ldm_x4(qh4, sbase + 2 * AQ_H + qoff);
            ldm_x4(ql4, sbase + 2 * AQ_L + qoff);
            #pragma unroll
            for (int kb = 0; kb < 4; kb++) {
                unsigned kh4[4], kl4[4];
                const unsigned off = 2u * ((kb * 16 + browo) * TST + ks * 16 + bko);
                ldm_x4(kh4, skh + off);
                ldm_x4(kl4, skl + off);
                #pragma unroll
                for (int j = 0; j < 2; j++) {
                    const int nt = kb * 2 + j;
                    mma16816(sacc[nt], qh4, &kh4[2 * j]);
                    mma16816(sacc[nt], qh4, &kl4[2 * j]);
                    mma16816(sacc[nt], ql4, &kh4[2 * j]);
                }
            }
        }

        // ---- softmax (registers + quad shuffles only) ----
        float mx0 = -INFINITY, mx1 = -INFINITY;
        #pragma unroll
        for (int nt = 0; nt < 8; nt++) {
            mx0 = fmaxf(mx0, fmaxf(sacc[nt][0], sacc[nt][1]));
            mx1 = fmaxf(mx1, fmaxf(sacc[nt][2], sacc[nt][3]));
        }
        mx0 = fmaxf(mx0, __shfl_xor_sync(0xffffffffu, mx0, 1));
        mx0 = fmaxf(mx0, __shfl_xor_sync(0xffffffffu, mx0, 2));
        mx1 = fmaxf(mx1, __shfl_xor_sync(0xffffffffu, mx1, 1));
        mx1 = fmaxf(mx1, __shfl_xor_sync(0xffffffffu, mx1, 2));
        const float mn0 = fmaxf(m_run[0], mx0);
        const float mn1 = fmaxf(m_run[1], mx1);
        const float al0 = __expf(m_run[0] - mn0);
        const float al1 = __expf(m_run[1] - mn1);
        m_run[0] = mn0; m_run[1] = mn1;

        unsigned ph[4][4];
        float s0 = 0.f, s1 = 0.f;
        #pragma unroll
        for (int kb = 0; kb < 4; kb++) {
            #pragma unroll
            for (int j = 0; j < 2; j++) {
                const int nt = kb * 2 + j;
                const float p0 = __expf(sacc[nt][0] - mn0);
                const float p1 = __expf(sacc[nt][1] - mn0);
                const float p2 = __expf(sacc[nt][2] - mn1);
                const float p3 = __expf(sacc[nt][3] - mn1);
                s0 += p0 + p1;
                s1 += p2 + p3;
                ph[kb][2 * j + 0] = pack_h2(p0, p1);
                ph[kb][2 * j + 1] = pack_h2(p2, p3);
            }
        }
        s0 += __shfl_xor_sync(0xffffffffu, s0, 1);
        s0 += __shfl_xor_sync(0xffffffffu, s0, 2);
        s1 += __shfl_xor_sync(0xffffffffu, s1, 1);
        s1 += __shfl_xor_sync(0xffffffffu, s1, 2);
        l_run[0] = l_run[0] * al0 + s0;
        l_run[1] = l_run[1] * al1 + s1;
        #pragma unroll
        for (int ot = 0; ot < 8; ot++) {
            oacc[ot][0] *= al0; oacc[ot][1] *= al0;
            oacc[ot][2] *= al1; oacc[ot][3] *= al1;
        }

        if (kt < 31) { CP_WAIT(2); } else { CP_WAIT(0); }
        __syncthreads();   // V[kt] visible

        const unsigned svh = sbase + 2u * AVH(kt & 1);

        // ---- O += P V (fp16 x fp16, single pass) ----
        #pragma unroll
        for (int ks = 0; ks < 4; ks++) {
            const int kr = ks * 16 + (g & 1) * 8 + (lane & 7);
            #pragma unroll
            for (int eb = 0; eb < 4; eb++) {
                unsigned vh4[4];
                const unsigned voff = 2u * (kr * TST + eb * 16 + (g >> 1) * 8);
                ldm_x4_t(vh4, svh + voff);
                #pragma unroll
                for (int j = 0; j < 2; j++) {
                    mma16816h(oacc[eb * 2 + j], ph[ks], &vh4[2 * j]);
                }
            }
        }
    }

    // Epilogue: normalize, split to fp16, write g_A2 (concat layout)
    const int bb = bh >> 4, hh = bh & 15;
    const int r0 = w * 16 + (lane >> 2);
    const float inv0 = 1.f / l_run[0];
    const float inv1 = 1.f / l_run[1];
    const size_t mrow0 = ((size_t)bb * SEQ + q0 + r0) * D_MODEL + hh * HEAD_DIM;
    const size_t mrow1 = ((size_t)bb * SEQ + q0 + r0 + 8) * D_MODEL + hh * HEAD_DIM;
    #pragma unroll
    for (int ot = 0; ot < 8; ot++) {
        const int e = ot * 8 + (lane & 3) * 2;
        unsigned ph, pl;
        split2h(oacc[ot][0] * inv0, oacc[ot][1] * inv0, ph, pl);
        *reinterpret_cast<unsigned*>(g_A2h + mrow0 + e) = ph;
        *reinterpret_cast<unsigned*>(g_A2l + mrow0 + e) = pl;
        split2h(oacc[ot][2] * inv1, oacc[ot][3] * inv1, ph, pl);
        *reinterpret_cast<unsigned*>(g_A2h + mrow1 + e) = ph;
        *reinterpret_cast<unsigned*>(g_A2l + mrow1 + e) = pl;
    }
}

// ============================================================================
extern "C" void kernel_launch(void* const* d_in, const int* in_sizes, int n_in,
                              void* d_out, int out_size)
{
    const float* x  = (const float*)d_in[0];
    const float* Wq = (const float*)d_in[1];
    const float* bq = (const float*)d_in[2];
    const float* Wk = (const float*)d_in[3];
    const float* bk = (const float*)d_in[4];
    const float* Wv = (const float*)d_in[5];
    const float* bv = (const float*)d_in[6];
    const float* Wo = (const float*)d_in[7];
    const float* bo = (const float*)d_in[8];
    float* out = (float*)d_out;

    cudaFuncSetAttribute(mm_mma, cudaFuncAttributeMaxDynamicSharedMemorySize, MM_SMEM);
    cudaFuncSetAttribute(attn_mma, cudaFuncAttributeMaxDynamicSharedMemorySize, ATTN_SMEM);

    split_x<<<(M_TOTAL * D_MODEL) / 1024, 256>>>(x);
    conv_wqkv<<<(NQKV * D_MODEL) / 256, 256>>>(Wq, bq, Wk, bk, Wv, bv);
    conv_wo<<<(D_MODEL * D_MODEL) / 256, 256>>>(Wo);

    mm_mma<<<dim3(NQKV / 128, M_TOTAL / 128), 256, MM_SMEM>>>(nullptr, nullptr, 1);
    attn_mma<<<dim3(SEQ / 128, NBH), 256, ATTN_SMEM>>>();
    mm_mma<<<dim3(D_MODEL / 128, M_TOTAL / 128), 256, MM_SMEM>>>(bo, out, 0);
}

// round 12
// speedup vs baseline: 4.9261x; 1.0592x over previous
#include <cuda_runtime.h>
#include <cuda_bf16.h>
#include <cuda_fp16.h>
#include <math.h>

#define D_MODEL   1024
#define NUM_HEADS 16
#define HEAD_DIM  64
#define BATCH     4
#define SEQ       2048
#define M_TOTAL   (BATCH * SEQ)   // 8192
#define NQKV      (3 * D_MODEL)   // 3072
#define NBH       (BATCH * NUM_HEADS)  // 64

// ============================================================================
// Device global scratch (allocation-free rule)
// ============================================================================
__device__ __half g_Xh[M_TOTAL * D_MODEL], g_Xl[M_TOTAL * D_MODEL];  // X fp16 split
__device__ __half g_Bqkv[NQKV * D_MODEL];                            // [n][k] fp16
__device__ __half g_Wo[D_MODEL * D_MODEL];                           // [n][k] fp16
__device__ float g_bias_qkv[NQKV];
__device__ __half g_qh[NBH * SEQ * HEAD_DIM], g_ql[NBH * SEQ * HEAD_DIM]; // Q fp16 split
__device__ __half g_k[NBH * SEQ * HEAD_DIM];                         // K fp16 single
__device__ __half g_vh[NBH * SEQ * HEAD_DIM];                        // V fp16 single
__device__ __half g_A2h[M_TOTAL * D_MODEL], g_A2l[M_TOTAL * D_MODEL]; // attn out fp16 split

// ============================================================================
// PTX helpers (portable, compute_103-safe)
// ============================================================================
__device__ __forceinline__ unsigned smem_u32(const void* p) {
    unsigned a;
    asm("{ .reg .u64 t; cvta.to.shared.u64 t, %1; cvt.u32.u64 %0, t; }"
        : "=r"(a) : "l"(p));
    return a;
}
__device__ __forceinline__ void ldm_x4(unsigned* r, unsigned addr) {
    asm volatile("ldmatrix.sync.aligned.m8n8.x4.shared.b16 {%0,%1,%2,%3}, [%4];"
        : "=r"(r[0]), "=r"(r[1]), "=r"(r[2]), "=r"(r[3]) : "r"(addr));
}
__device__ __forceinline__ void ldm_x4_t(unsigned* r, unsigned addr) {
    asm volatile("ldmatrix.sync.aligned.m8n8.x4.trans.shared.b16 {%0,%1,%2,%3}, [%4];"
        : "=r"(r[0]), "=r"(r[1]), "=r"(r[2]), "=r"(r[3]) : "r"(addr));
}
__device__ __forceinline__ void mma16816h(float* c, const unsigned* a, const unsigned* b) {
    asm volatile("mma.sync.aligned.m16n8k16.row.col.f32.f16.f16.f32 "
        "{%0,%1,%2,%3}, {%4,%5,%6,%7}, {%8,%9}, {%0,%1,%2,%3};"
        : "+f"(c[0]), "+f"(c[1]), "+f"(c[2]), "+f"(c[3])
        : "r"(a[0]), "r"(a[1]), "r"(a[2]), "r"(a[3]), "r"(b[0]), "r"(b[1]));
}
__device__ __forceinline__ void cp_async16(unsigned saddr, const void* gptr) {
    asm volatile("cp.async.cg.shared.global [%0], [%1], 16;"
                 :: "r"(saddr), "l"(gptr) : "memory");
}
#define CP_COMMIT() asm volatile("cp.async.commit_group;" ::: "memory")
#define CP_WAIT(N)  asm volatile("cp.async.wait_group %0;" :: "n"(N) : "memory")

__device__ __forceinline__ unsigned pack_h2(float lo, float hi) {
    __half2 h = __floats2half2_rn(lo, hi);
    return *reinterpret_cast<unsigned*>(&h);
}
__device__ __forceinline__ void split2h(float v0, float v1, unsigned& ph, unsigned& pl) {
    float h0 = __half2float(__float2half_rn(v0));
    float h1 = __half2float(__float2half_rn(v1));
    ph = pack_h2(v0, v1);
    pl = pack_h2(v0 - h0, v1 - h1);
}

// ============================================================================
// Conversion kernels
// ============================================================================
__global__ __launch_bounds__(256) void split_x(const float* __restrict__ x) {
    size_t i = ((size_t)blockIdx.x * 256 + threadIdx.x) * 4;
    float4 v = *reinterpret_cast<const float4*>(x + i);
    float f[4] = {v.x, v.y, v.z, v.w};
    #pragma unroll
    for (int j = 0; j < 4; j++) {
        __half h = __float2half_rn(f[j]);
        g_Xh[i + j] = h;
        g_Xl[i + j] = __float2half_rn(f[j] - __half2float(h));
    }
}

__global__ __launch_bounds__(256) void conv_wqkv(
    const float* __restrict__ Wq, const float* __restrict__ bq,
    const float* __restrict__ Wk, const float* __restrict__ bk,
    const float* __restrict__ Wv, const float* __restrict__ bv) {
    size_t idx = (size_t)blockIdx.x * 256 + threadIdx.x;  // n*1024 + k
    int n = (int)(idx >> 10), k = (int)(idx & 1023);
    int proj = n >> 10, nc = n & 1023, h = nc >> 6, e = nc & 63;
    const float* W = (proj == 0) ? Wq : (proj == 1) ? Wk : Wv;
    float v = W[((size_t)h * D_MODEL + k) * HEAD_DIM + e];
    g_Bqkv[idx] = __float2half_rn(v);
    if (k == 0) {
        const float* b = (proj == 0) ? bq : (proj == 1) ? bk : bv;
        g_bias_qkv[n] = b[nc];
    }
}

__global__ __launch_bounds__(256) void conv_wo(const float* __restrict__ Wo) {
    size_t idx = (size_t)blockIdx.x * 256 + threadIdx.x;
    int n = (int)(idx >> 10), k = (int)(idx & 1023);
    g_Wo[idx] = __float2half_rn(Wo[(size_t)k * D_MODEL + n]);
}

// ============================================================================
// GEMM on mma.sync, fp16 2-pass split, 3-stage cp.async pipeline.
// 2 CTAs/SM, BK=32, stride 40 el (80 B). CTA 128x128, warps 2(M)x4(N).
// ============================================================================
#define AST 40
#define MMS_A_H 0
#define MMS_A_L (128 * AST)
#define MMS_B   (2 * 128 * AST)
#define STAGE_EL (3 * 128 * AST)          // 15360 el = 30720 B
#define MM_SMEM  (3 * STAGE_EL * 2)       // 92160 B per CTA

__global__ __launch_bounds__(256, 2) void mm_mma(const float* __restrict__ bias_ext,
                                                 float* __restrict__ outp, int mode) {
    extern __shared__ __align__(16) __half smm[];
    const unsigned sbase = smem_u32(smm);
    const int tid = threadIdx.x;
    const int lane = tid & 31;
    const int w = tid >> 5;
    const int mw = w >> 2, nw = w & 3;
    const int n0 = blockIdx.x * 128;
    const int m0 = blockIdx.y * 128;

    const __half* __restrict__ Ahg = (mode == 1) ? g_Xh : g_A2h;
    const __half* __restrict__ Alg = (mode == 1) ? g_Xl : g_A2l;
    const __half* __restrict__ Bg  = (mode == 1) ? g_Bqkv : g_Wo;
    const float* __restrict__ bias = (mode == 1) ? g_bias_qkv : bias_ext;

    float acc[4][4][4];
    #pragma unroll
    for (int a = 0; a < 4; a++)
        #pragma unroll
        for (int b = 0; b < 4; b++)
            #pragma unroll
            for (int c = 0; c < 4; c++) acc[a][b][c] = 0.f;

    auto issue = [&](int kc) {
        const int k0 = kc * 32;
        const unsigned sst = sbase + (unsigned)(2 * STAGE_EL) * (kc % 3);
        #pragma unroll
        for (int i = 0; i < 2; i++) {
            const int t = tid + 256 * i;
            const int row = t >> 2, slot = t & 3;
            const unsigned so = 2u * (row * AST + slot * 8);
            const size_t ga = (size_t)(m0 + row) * D_MODEL + k0 + slot * 8;
            const size_t gb = (size_t)(n0 + row) * D_MODEL + k0 + slot * 8;
            cp_async16(sst + 2u * MMS_A_H + so, Ahg + ga);
            cp_async16(sst + 2u * MMS_A_L + so, Alg + ga);
            cp_async16(sst + 2u * MMS_B + so, Bg + gb);
        }
        CP_COMMIT();
    };

    issue(0);
    issue(1);

    for (int kc = 0; kc < 32; kc++) {
        if (kc < 31) { CP_WAIT(1); } else { CP_WAIT(0); }
        __syncthreads();          // stage kc ready; stage (kc+2)%3 fully consumed
        if (kc + 2 < 32) issue(kc + 2);

        const unsigned sst = sbase + (unsigned)(2 * STAGE_EL) * (kc % 3);
        #pragma unroll
        for (int ks = 0; ks < 2; ks++) {
            unsigned ah[4][4], al[4][4], bh[4][2];
            const int arow = mw * 64 + (lane & 15);
            const int acol = ks * 16 + (lane >> 4) * 8;
            #pragma unroll
            for (int mt = 0; mt < 4; mt++) {
                const unsigned off = 2u * ((arow + mt * 16) * AST + acol);
                ldm_x4(ah[mt], sst + 2 * MMS_A_H + off);
                ldm_x4(al[mt], sst + 2 * MMS_A_L + off);
            }
            const int g = lane >> 3;
            const int browo = (g >> 1) * 8 + (lane & 7);
            const int bko = (g & 1) * 8;
            #pragma unroll
            for (int np = 0; np < 2; np++) {
                const unsigned off = 2u * ((nw * 32 + np * 16 + browo) * AST + ks * 16 + bko);
                ldm_x4(&bh[np * 2][0], sst + 2 * MMS_B + off);
            }
            #pragma unroll
            for (int mt = 0; mt < 4; mt++)
                #pragma unroll
                for (int nt = 0; nt < 4; nt++) {
                    mma16816h(acc[mt][nt], ah[mt], bh[nt]);
                    mma16816h(acc[mt][nt], al[mt], bh[nt]);
                }
        }
    }

    // Epilogue
    #pragma unroll
    for (int mt = 0; mt < 4; mt++) {
        const int r0 = m0 + mw * 64 + mt * 16 + (lane >> 2);
        #pragma unroll
        for (int nt = 0; nt < 4; nt++) {
            const int c = n0 + nw * 32 + nt * 8 + (lane & 3) * 2;
            const float b0 = bias[c], b1 = bias[c + 1];
            #pragma unroll
            for (int h2 = 0; h2 < 2; h2++) {
                const int r = r0 + h2 * 8;
                float v0 = acc[mt][nt][h2 * 2 + 0] + b0;
                float v1 = acc[mt][nt][h2 * 2 + 1] + b1;
                if (mode == 0) {
                    float2 vv = make_float2(v0, v1);
                    *reinterpret_cast<float2*>(outp + (size_t)r * D_MODEL + c) = vv;
                } else {
                    const int proj = c >> 10, nc = c & 1023, hh = nc >> 6, e = nc & 63;
                    const size_t idx =
                        (((size_t)((r >> 11) * NUM_HEADS + hh)) * SEQ + (r & 2047)) * HEAD_DIM + e;
                    if (proj == 0) {
                        v0 *= 0.125f; v1 *= 0.125f;
                        unsigned ph, pl;
                        split2h(v0, v1, ph, pl);
                        *reinterpret_cast<unsigned*>(g_qh + idx) = ph;
                        *reinterpret_cast<unsigned*>(g_ql + idx) = pl;
                    } else if (proj == 1) {
                        *reinterpret_cast<unsigned*>(g_k + idx) = pack_h2(v0, v1);
                    } else {
                        *reinterpret_cast<unsigned*>(g_vh + idx) = pack_h2(v0, v1);
                    }
                }
            }
        }
    }
}

// ============================================================================
// Flash attention, FA2-style, 2 CTAs/SM: 128 q-rows x 64-key tiles.
// QK^T: fp16 2-pass (Q split, K single). PV: fp16 single pass.
// smem: Q(hi,lo) 36.9KB + K 2x9.2KB + V 2x9.2KB = 73.7KB/CTA.
// ============================================================================
#define TST 72
#define AQ_H 0
#define AQ_L 9216
#define AK(s) (18432 + (s) * 4608)
#define AV(s) (27648 + (s) * 4608)
#define ATTN_SMEM (36864 * 2)   // 73728 B

__global__ __launch_bounds__(256, 2) void attn_mma() {
    extern __shared__ __align__(16) __half smm[];
    const unsigned sbase = smem_u32(smm);
    const int tid = threadIdx.x;
    const int lane = tid & 31;
    const int w = tid >> 5;
    const int q0 = blockIdx.x * 128;
    const int bh = blockIdx.y;
    const size_t gbase = (size_t)bh * SEQ * HEAD_DIM;

    const int g = lane >> 3;
    const int browo = (g >> 1) * 8 + (lane & 7);
    const int bko = (g & 1) * 8;

    auto issueK = [&](int kt2) {
        const int t0 = kt2 * 64;
        const unsigned sk = sbase + 2u * AK(kt2 & 1);
        #pragma unroll
        for (int i = 0; i < 2; i++) {
            const int t = tid + 256 * i;
            const int row = t >> 3, slot = t & 7;
            const unsigned so = 2u * (row * TST + slot * 8);
            const size_t gk = gbase + (size_t)(t0 + row) * HEAD_DIM + slot * 8;
            cp_async16(sk + so, g_k + gk);
        }
        CP_COMMIT();
    };
    auto issueV = [&](int kt2) {
        const int t0 = kt2 * 64;
        const unsigned sv = sbase + 2u * AV(kt2 & 1);
        #pragma unroll
        for (int i = 0; i < 2; i++) {
            const int t = tid + 256 * i;
            const int row = t >> 3, slot = t & 7;
            const unsigned so = 2u * (row * TST + slot * 8);
            const size_t gv = gbase + (size_t)(t0 + row) * HEAD_DIM + slot * 8;
            cp_async16(sv + so, g_vh + gv);
        }
        CP_COMMIT();
    };

    issueK(0);
    issueV(0);

    // stage Q (hi+lo) into smem
    #pragma unroll
    for (int i = 0; i < 4; i++) {
        const int t = tid + 256 * i;
        const int row = t >> 3, slot = t & 7;
        const int so = row * TST + slot * 8;
        const size_t gq = gbase + (size_t)(q0 + row) * HEAD_DIM + slot * 8;
        *reinterpret_cast<float4*>(smm + AQ_H + so) = *reinterpret_cast<const float4*>(g_qh + gq);
        *reinterpret_cast<float4*>(smm + AQ_L + so) = *reinterpret_cast<const float4*>(g_ql + gq);
    }
    __syncthreads();

    float m_run[2] = {-INFINITY, -INFINITY};
    float l_run[2] = {0.f, 0.f};
    float oacc[8][4];
    #pragma unroll
    for (int a = 0; a < 8; a++)
        #pragma unroll
        for (int c = 0; c < 4; c++) oacc[a][c] = 0.f;

    for (int kt = 0; kt < 32; kt++) {
        CP_WAIT(1);        // K[kt] landed
        __syncthreads();   // K[kt] visible; prev-tile smem fully consumed

        if (kt < 31) { issueK(kt + 1); issueV(kt + 1); }

        const unsigned sk = sbase + 2u * AK(kt & 1);

        // ---- S = Q K^T (fp16 2-pass): 8 n8-tiles of keys ----
        float sacc[8][4];
        #pragma unroll
        for (int a = 0; a < 8; a++)
            #pragma unroll
            for (int c = 0; c < 4; c++) sacc[a][c] = 0.f;

        #pragma unroll
        for (int ks = 0; ks < 4; ks++) {
            unsigned qh4[4], ql4[4];
            const int arow = w * 16 + (lane & 15);
            const unsigned qoff = 2u * (arow * TST + ks * 16 + (lane >> 4) * 8);
            ldm_x4(qh4, sbase + 2 * AQ_H + qoff);
            ldm_x4(ql4, sbase + 2 * AQ_L + qoff);
            #pragma unroll
            for (int kb = 0; kb < 4; kb++) {
                unsigned kh4[4];
                const unsigned off = 2u * ((kb * 16 + browo) * TST + ks * 16 + bko);
                ldm_x4(kh4, sk + off);
                #pragma unroll
                for (int j = 0; j < 2; j++) {
                    const int nt = kb * 2 + j;
                    mma16816h(sacc[nt], qh4, &kh4[2 * j]);
                    mma16816h(sacc[nt], ql4, &kh4[2 * j]);
                }
            }
        }

        // ---- softmax (registers + quad shuffles only) ----
        float mx0 = -INFINITY, mx1 = -INFINITY;
        #pragma unroll
        for (int nt = 0; nt < 8; nt++) {
            mx0 = fmaxf(mx0, fmaxf(sacc[nt][0], sacc[nt][1]));
            mx1 = fmaxf(mx1, fmaxf(sacc[nt][2], sacc[nt][3]));
        }
        mx0 = fmaxf(mx0, __shfl_xor_sync(0xffffffffu, mx0, 1));
        mx0 = fmaxf(mx0, __shfl_xor_sync(0xffffffffu, mx0, 2));
        mx1 = fmaxf(mx1, __shfl_xor_sync(0xffffffffu, mx1, 1));
        mx1 = fmaxf(mx1, __shfl_xor_sync(0xffffffffu, mx1, 2));
        const float mn0 = fmaxf(m_run[0], mx0);
        const float mn1 = fmaxf(m_run[1], mx1);
        const float al0 = __expf(m_run[0] - mn0);
        const float al1 = __expf(m_run[1] - mn1);
        m_run[0] = mn0; m_run[1] = mn1;

        unsigned ph[4][4];
        float s0 = 0.f, s1 = 0.f;
        #pragma unroll
        for (int kb = 0; kb < 4; kb++) {
            #pragma unroll
            for (int j = 0; j < 2; j++) {
                const int nt = kb * 2 + j;
                const float p0 = __expf(sacc[nt][0] - mn0);
                const float p1 = __expf(sacc[nt][1] - mn0);
                const float p2 = __expf(sacc[nt][2] - mn1);
                const float p3 = __expf(sacc[nt][3] - mn1);
                s0 += p0 + p1;
                s1 += p2 + p3;
                ph[kb][2 * j + 0] = pack_h2(p0, p1);
                ph[kb][2 * j + 1] = pack_h2(p2, p3);
            }
        }
        s0 += __shfl_xor_sync(0xffffffffu, s0, 1);
        s0 += __shfl_xor_sync(0xffffffffu, s0, 2);
        s1 += __shfl_xor_sync(0xffffffffu, s1, 1);
        s1 += __shfl_xor_sync(0xffffffffu, s1, 2);
        l_run[0] = l_run[0] * al0 + s0;
        l_run[1] = l_run[1] * al1 + s1;
        #pragma unroll
        for (int ot = 0; ot < 8; ot++) {
            oacc[ot][0] *= al0; oacc[ot][1] *= al0;
            oacc[ot][2] *= al1; oacc[ot][3] *= al1;
        }

        if (kt < 31) { CP_WAIT(2); } else { CP_WAIT(0); }
        __syncthreads();   // V[kt] visible

        const unsigned sv = sbase + 2u * AV(kt & 1);

        // ---- O += P V (fp16 x fp16, single pass) ----
        #pragma unroll
        for (int ks = 0; ks < 4; ks++) {
            const int kr = ks * 16 + (g & 1) * 8 + (lane & 7);
            #pragma unroll
            for (int eb = 0; eb < 4; eb++) {
                unsigned vh4[4];
                const unsigned voff = 2u * (kr * TST + eb * 16 + (g >> 1) * 8);
                ldm_x4_t(vh4, sv + voff);
                #pragma unroll
                for (int j = 0; j < 2; j++) {
                    mma16816h(oacc[eb * 2 + j], ph[ks], &vh4[2 * j]);
                }
            }
        }
    }

    // Epilogue: normalize, split to fp16, write g_A2 (concat layout)
    const int bb = bh >> 4, hh = bh & 15;
    const int r0 = w * 16 + (lane >> 2);
    const float inv0 = 1.f / l_run[0];
    const float inv1 = 1.f / l_run[1];
    const size_t mrow0 = ((size_t)bb * SEQ + q0 + r0) * D_MODEL + hh * HEAD_DIM;
    const size_t mrow1 = ((size_t)bb * SEQ + q0 + r0 + 8) * D_MODEL + hh * HEAD_DIM;
    #pragma unroll
    for (int ot = 0; ot < 8; ot++) {
        const int e = ot * 8 + (lane & 3) * 2;
        unsigned ph, pl;
        split2h(oacc[ot][0] * inv0, oacc[ot][1] * inv0, ph, pl);
        *reinterpret_cast<unsigned*>(g_A2h + mrow0 + e) = ph;
        *reinterpret_cast<unsigned*>(g_A2l + mrow0 + e) = pl;
        split2h(oacc[ot][2] * inv1, oacc[ot][3] * inv1, ph, pl);
        *reinterpret_cast<unsigned*>(g_A2h + mrow1 + e) = ph;
        *reinterpret_cast<unsigned*>(g_A2l + mrow1 + e) = pl;
    }
}

// ============================================================================
extern "C" void kernel_launch(void* const* d_in, const int* in_sizes, int n_in,
                              void* d_out, int out_size)
{
    const float* x  = (const float*)d_in[0];
    const float* Wq = (const float*)d_in[1];
    const float* bq = (const float*)d_in[2];
    const float* Wk = (const float*)d_in[3];
    const float* bk = (const float*)d_in[4];
    const float* Wv = (const float*)d_in[5];
    const float* bv = (const float*)d_in[6];
    const float* Wo = (const float*)d_in[7];
    const float* bo = (const float*)d_in[8];
    float* out = (float*)d_out;

    cudaFuncSetAttribute(mm_mma, cudaFuncAttributeMaxDynamicSharedMemorySize, MM_SMEM);
    cudaFuncSetAttribute(attn_mma, cudaFuncAttributeMaxDynamicSharedMemorySize, ATTN_SMEM);

    split_x<<<(M_TOTAL * D_MODEL) / 1024, 256>>>(x);
    conv_wqkv<<<(NQKV * D_MODEL) / 256, 256>>>(Wq, bq, Wk, bk, Wv, bv);
    conv_wo<<<(D_MODEL * D_MODEL) / 256, 256>>>(Wo);

    mm_mma<<<dim3(NQKV / 128, M_TOTAL / 128), 256, MM_SMEM>>>(nullptr, nullptr, 1);
    attn_mma<<<dim3(SEQ / 128, NBH), 256, ATTN_SMEM>>>();
    mm_mma<<<dim3(D_MODEL / 128, M_TOTAL / 128), 256, MM_SMEM>>>(bo, out, 0);
}

// round 13
// speedup vs baseline: 6.8298x; 1.3864x over previous
#include <cuda_runtime.h>
#include <cuda_bf16.h>
#include <cuda_fp16.h>
#include <math.h>

#define D_MODEL   1024
#define NUM_HEADS 16
#define HEAD_DIM  64
#define BATCH     4
#define SEQ       2048
#define M_TOTAL   (BATCH * SEQ)   // 8192
#define NQKV      (3 * D_MODEL)   // 3072
#define NBH       (BATCH * NUM_HEADS)  // 64

// ============================================================================
// Device global scratch (allocation-free rule)
// ============================================================================
__device__ __half g_X[M_TOTAL * D_MODEL];                            // X fp16 single
__device__ __half g_Bqkv[NQKV * D_MODEL];                            // [n][k] fp16
__device__ __half g_Wo[D_MODEL * D_MODEL];                           // [n][k] fp16
__device__ float g_bias_qkv[NQKV];
__device__ __half g_qh[NBH * SEQ * HEAD_DIM], g_ql[NBH * SEQ * HEAD_DIM]; // Q fp16 split
__device__ __half g_k[NBH * SEQ * HEAD_DIM];                         // K fp16 single
__device__ __half g_vh[NBH * SEQ * HEAD_DIM];                        // V fp16 single
__device__ __half g_A2[M_TOTAL * D_MODEL];                           // attn out fp16 single

// ============================================================================
// PTX helpers (portable, compute_103-safe)
// ============================================================================
__device__ __forceinline__ unsigned smem_u32(const void* p) {
    unsigned a;
    asm("{ .reg .u64 t; cvta.to.shared.u64 t, %1; cvt.u32.u64 %0, t; }"
        : "=r"(a) : "l"(p));
    return a;
}
__device__ __forceinline__ void ldm_x4(unsigned* r, unsigned addr) {
    asm volatile("ldmatrix.sync.aligned.m8n8.x4.shared.b16 {%0,%1,%2,%3}, [%4];"
        : "=r"(r[0]), "=r"(r[1]), "=r"(r[2]), "=r"(r[3]) : "r"(addr));
}
__device__ __forceinline__ void ldm_x4_t(unsigned* r, unsigned addr) {
    asm volatile("ldmatrix.sync.aligned.m8n8.x4.trans.shared.b16 {%0,%1,%2,%3}, [%4];"
        : "=r"(r[0]), "=r"(r[1]), "=r"(r[2]), "=r"(r[3]) : "r"(addr));
}
__device__ __forceinline__ void mma16816h(float* c, const unsigned* a, const unsigned* b) {
    asm volatile("mma.sync.aligned.m16n8k16.row.col.f32.f16.f16.f32 "
        "{%0,%1,%2,%3}, {%4,%5,%6,%7}, {%8,%9}, {%0,%1,%2,%3};"
        : "+f"(c[0]), "+f"(c[1]), "+f"(c[2]), "+f"(c[3])
        : "r"(a[0]), "r"(a[1]), "r"(a[2]), "r"(a[3]), "r"(b[0]), "r"(b[1]));
}
__device__ __forceinline__ void cp_async16(unsigned saddr, const void* gptr) {
    asm volatile("cp.async.cg.shared.global [%0], [%1], 16;"
                 :: "r"(saddr), "l"(gptr) : "memory");
}
#define CP_COMMIT() asm volatile("cp.async.commit_group;" ::: "memory")
#define CP_WAIT(N)  asm volatile("cp.async.wait_group %0;" :: "n"(N) : "memory")

__device__ __forceinline__ unsigned pack_h2(float lo, float hi) {
    __half2 h = __floats2half2_rn(lo, hi);
    return *reinterpret_cast<unsigned*>(&h);
}
__device__ __forceinline__ void split2h(float v0, float v1, unsigned& ph, unsigned& pl) {
    float h0 = __half2float(__float2half_rn(v0));
    float h1 = __half2float(__float2half_rn(v1));
    ph = pack_h2(v0, v1);
    pl = pack_h2(v0 - h0, v1 - h1);
}

// ============================================================================
// Conversion kernels
// ============================================================================
__global__ __launch_bounds__(256) void conv_x(const float* __restrict__ x) {
    size_t i = ((size_t)blockIdx.x * 256 + threadIdx.x) * 4;
    float4 v = *reinterpret_cast<const float4*>(x + i);
    g_X[i + 0] = __float2half_rn(v.x);
    g_X[i + 1] = __float2half_rn(v.y);
    g_X[i + 2] = __float2half_rn(v.z);
    g_X[i + 3] = __float2half_rn(v.w);
}

__global__ __launch_bounds__(256) void conv_wqkv(
    const float* __restrict__ Wq, const float* __restrict__ bq,
    const float* __restrict__ Wk, const float* __restrict__ bk,
    const float* __restrict__ Wv, const float* __restrict__ bv) {
    size_t idx = (size_t)blockIdx.x * 256 + threadIdx.x;  // n*1024 + k
    int n = (int)(idx >> 10), k = (int)(idx & 1023);
    int proj = n >> 10, nc = n & 1023, h = nc >> 6, e = nc & 63;
    const float* W = (proj == 0) ? Wq : (proj == 1) ? Wk : Wv;
    float v = W[((size_t)h * D_MODEL + k) * HEAD_DIM + e];
    g_Bqkv[idx] = __float2half_rn(v);
    if (k == 0) {
        const float* b = (proj == 0) ? bq : (proj == 1) ? bk : bv;
        g_bias_qkv[n] = b[nc];
    }
}

__global__ __launch_bounds__(256) void conv_wo(const float* __restrict__ Wo) {
    size_t idx = (size_t)blockIdx.x * 256 + threadIdx.x;
    int n = (int)(idx >> 10), k = (int)(idx & 1023);
    g_Wo[idx] = __float2half_rn(Wo[(size_t)k * D_MODEL + n]);
}

// ============================================================================
// GEMM on mma.sync, single-pass fp16, 2-stage cp.async, BK=64.
// 2 CTAs/SM, stride 72 el (144 B). CTA 128x128, warps 2(M)x4(N).
// ============================================================================
#define AST 72
#define MMS_A 0
#define MMS_B (128 * AST)
#define STAGE_EL (2 * 128 * AST)          // 18432 el = 36864 B
#define MM_SMEM  (2 * STAGE_EL * 2)       // 73728 B per CTA

__global__ __launch_bounds__(256, 2) void mm_mma(const float* __restrict__ bias_ext,
                                                 float* __restrict__ outp, int mode) {
    extern __shared__ __align__(16) __half smm[];
    const unsigned sbase = smem_u32(smm);
    const int tid = threadIdx.x;
    const int lane = tid & 31;
    const int w = tid >> 5;
    const int mw = w >> 2, nw = w & 3;
    const int n0 = blockIdx.x * 128;
    const int m0 = blockIdx.y * 128;

    const __half* __restrict__ Ag = (mode == 1) ? g_X : g_A2;
    const __half* __restrict__ Bg = (mode == 1) ? g_Bqkv : g_Wo;
    const float* __restrict__ bias = (mode == 1) ? g_bias_qkv : bias_ext;

    float acc[4][4][4];
    #pragma unroll
    for (int a = 0; a < 4; a++)
        #pragma unroll
        for (int b = 0; b < 4; b++)
            #pragma unroll
            for (int c = 0; c < 4; c++) acc[a][b][c] = 0.f;

    auto issue = [&](int kc) {
        const int k0 = kc * 64;
        const unsigned sst = sbase + (unsigned)(2 * STAGE_EL) * (kc & 1);
        #pragma unroll
        for (int i = 0; i < 4; i++) {
            const int t = tid + 256 * i;
            const int row = t >> 3, slot = t & 7;       // 128 rows x 8 slots of 8 el
            const unsigned so = 2u * (row * AST + slot * 8);
            const size_t ga = (size_t)(m0 + row) * D_MODEL + k0 + slot * 8;
            const size_t gb = (size_t)(n0 + row) * D_MODEL + k0 + slot * 8;
            cp_async16(sst + 2u * MMS_A + so, Ag + ga);
            cp_async16(sst + 2u * MMS_B + so, Bg + gb);
        }
        CP_COMMIT();
    };

    issue(0);

    for (int kc = 0; kc < 16; kc++) {
        CP_WAIT(0);
        __syncthreads();          // stage kc ready; other stage fully consumed
        if (kc + 1 < 16) issue(kc + 1);

        const unsigned sst = sbase + (unsigned)(2 * STAGE_EL) * (kc & 1);
        #pragma unroll
        for (int ks = 0; ks < 4; ks++) {
            unsigned ah[4][4], bh[4][2];
            const int arow = mw * 64 + (lane & 15);
            const int acol = ks * 16 + (lane >> 4) * 8;
            #pragma unroll
            for (int mt = 0; mt < 4; mt++) {
                const unsigned off = 2u * ((arow + mt * 16) * AST + acol);
                ldm_x4(ah[mt], sst + 2 * MMS_A + off);
            }
            const int g = lane >> 3;
            const int browo = (g >> 1) * 8 + (lane & 7);
            const int bko = (g & 1) * 8;
            #pragma unroll
            for (int np = 0; np < 2; np++) {
                const unsigned off = 2u * ((nw * 32 + np * 16 + browo) * AST + ks * 16 + bko);
                ldm_x4(&bh[np * 2][0], sst + 2 * MMS_B + off);
            }
            #pragma unroll
            for (int mt = 0; mt < 4; mt++)
                #pragma unroll
                for (int nt = 0; nt < 4; nt++)
                    mma16816h(acc[mt][nt], ah[mt], bh[nt]);
        }
    }

    // Epilogue
    #pragma unroll
    for (int mt = 0; mt < 4; mt++) {
        const int r0 = m0 + mw * 64 + mt * 16 + (lane >> 2);
        #pragma unroll
        for (int nt = 0; nt < 4; nt++) {
            const int c = n0 + nw * 32 + nt * 8 + (lane & 3) * 2;
            const float b0 = bias[c], b1 = bias[c + 1];
            #pragma unroll
            for (int h2 = 0; h2 < 2; h2++) {
                const int r = r0 + h2 * 8;
                float v0 = acc[mt][nt][h2 * 2 + 0] + b0;
                float v1 = acc[mt][nt][h2 * 2 + 1] + b1;
                if (mode == 0) {
                    float2 vv = make_float2(v0, v1);
                    *reinterpret_cast<float2*>(outp + (size_t)r * D_MODEL + c) = vv;
                } else {
                    const int proj = c >> 10, nc = c & 1023, hh = nc >> 6, e = nc & 63;
                    const size_t idx =
                        (((size_t)((r >> 11) * NUM_HEADS + hh)) * SEQ + (r & 2047)) * HEAD_DIM + e;
                    if (proj == 0) {
                        v0 *= 0.125f; v1 *= 0.125f;
                        unsigned ph, pl;
                        split2h(v0, v1, ph, pl);
                        *reinterpret_cast<unsigned*>(g_qh + idx) = ph;
                        *reinterpret_cast<unsigned*>(g_ql + idx) = pl;
                    } else if (proj == 1) {
                        *reinterpret_cast<unsigned*>(g_k + idx) = pack_h2(v0, v1);
                    } else {
                        *reinterpret_cast<unsigned*>(g_vh + idx) = pack_h2(v0, v1);
                    }
                }
            }
        }
    }
}

// ============================================================================
// Flash attention, FA2-style, 2 CTAs/SM: 128 q-rows x 64-key tiles.
// QK^T: fp16 2-pass (Q split, K single). PV: fp16 single pass.
// Epilogue writes single-fp16 A2 for the 1-pass out-projection.
// ============================================================================
#define TST 72
#define AQ_H 0
#define AQ_L 9216
#define AK(s) (18432 + (s) * 4608)
#define AV(s) (27648 + (s) * 4608)
#define ATTN_SMEM (36864 * 2)   // 73728 B

__global__ __launch_bounds__(256, 2) void attn_mma() {
    extern __shared__ __align__(16) __half smm[];
    const unsigned sbase = smem_u32(smm);
    const int tid = threadIdx.x;
    const int lane = tid & 31;
    const int w = tid >> 5;
    const int q0 = blockIdx.x * 128;
    const int bh = blockIdx.y;
    const size_t gbase = (size_t)bh * SEQ * HEAD_DIM;

    const int g = lane >> 3;
    const int browo = (g >> 1) * 8 + (lane & 7);
    const int bko = (g & 1) * 8;

    auto issueK = [&](int kt2) {
        const int t0 = kt2 * 64;
        const unsigned sk = sbase + 2u * AK(kt2 & 1);
        #pragma unroll
        for (int i = 0; i < 2; i++) {
            const int t = tid + 256 * i;
            const int row = t >> 3, slot = t & 7;
            const unsigned so = 2u * (row * TST + slot * 8);
            const size_t gk = gbase + (size_t)(t0 + row) * HEAD_DIM + slot * 8;
            cp_async16(sk + so, g_k + gk);
        }
        CP_COMMIT();
    };
    auto issueV = [&](int kt2) {
        const int t0 = kt2 * 64;
        const unsigned sv = sbase + 2u * AV(kt2 & 1);
        #pragma unroll
        for (int i = 0; i < 2; i++) {
            const int t = tid + 256 * i;
            const int row = t >> 3, slot = t & 7;
            const unsigned so = 2u * (row * TST + slot * 8);
            const size_t gv = gbase + (size_t)(t0 + row) * HEAD_DIM + slot * 8;
            cp_async16(sv + so, g_vh + gv);
        }
        CP_COMMIT();
    };

    issueK(0);
    issueV(0);

    // stage Q (hi+lo) into smem
    #pragma unroll
    for (int i = 0; i < 4; i++) {
        const int t = tid + 256 * i;
        const int row = t >> 3, slot = t & 7;
        const int so = row * TST + slot * 8;
        const size_t gq = gbase + (size_t)(q0 + row) * HEAD_DIM + slot * 8;
        *reinterpret_cast<float4*>(smm + AQ_H + so) = *reinterpret_cast<const float4*>(g_qh + gq);
        *reinterpret_cast<float4*>(smm + AQ_L + so) = *reinterpret_cast<const float4*>(g_ql + gq);
    }
    __syncthreads();

    float m_run[2] = {-INFINITY, -INFINITY};
    float l_run[2] = {0.f, 0.f};
    float oacc[8][4];
    #pragma unroll
    for (int a = 0; a < 8; a++)
        #pragma unroll
        for (int c = 0; c < 4; c++) oacc[a][c] = 0.f;

    for (int kt = 0; kt < 32; kt++) {
        CP_WAIT(1);        // K[kt] landed
        __syncthreads();   // K[kt] visible; prev-tile smem fully consumed

        if (kt < 31) { issueK(kt + 1); issueV(kt + 1); }

        const unsigned sk = sbase + 2u * AK(kt & 1);

        // ---- S = Q K^T (fp16 2-pass): 8 n8-tiles of keys ----
        float sacc[8][4];
        #pragma unroll
        for (int a = 0; a < 8; a++)
            #pragma unroll
            for (int c = 0; c < 4; c++) sacc[a][c] = 0.f;

        #pragma unroll
        for (int ks = 0; ks < 4; ks++) {
            unsigned qh4[4], ql4[4];
            const int arow = w * 16 + (lane & 15);
            const unsigned qoff = 2u * (arow * TST + ks * 16 + (lane >> 4) * 8);
            ldm_x4(qh4, sbase + 2 * AQ_H + qoff);
            ldm_x4(ql4, sbase + 2 * AQ_L + qoff);
            #pragma unroll
            for (int kb = 0; kb < 4; kb++) {
                unsigned kh4[4];
                const unsigned off = 2u * ((kb * 16 + browo) * TST + ks * 16 + bko);
                ldm_x4(kh4, sk + off);
                #pragma unroll
                for (int j = 0; j < 2; j++) {
                    const int nt = kb * 2 + j;
                    mma16816h(sacc[nt], qh4, &kh4[2 * j]);
                    mma16816h(sacc[nt], ql4, &kh4[2 * j]);
                }
            }
        }

        // ---- softmax (registers + quad shuffles only) ----
        float mx0 = -INFINITY, mx1 = -INFINITY;
        #pragma unroll
        for (int nt = 0; nt < 8; nt++) {
            mx0 = fmaxf(mx0, fmaxf(sacc[nt][0], sacc[nt][1]));
            mx1 = fmaxf(mx1, fmaxf(sacc[nt][2], sacc[nt][3]));
        }
        mx0 = fmaxf(mx0, __shfl_xor_sync(0xffffffffu, mx0, 1));
        mx0 = fmaxf(mx0, __shfl_xor_sync(0xffffffffu, mx0, 2));
        mx1 = fmaxf(mx1, __shfl_xor_sync(0xffffffffu, mx1, 1));
        mx1 = fmaxf(mx1, __shfl_xor_sync(0xffffffffu, mx1, 2));
        const float mn0 = fmaxf(m_run[0], mx0);
        const float mn1 = fmaxf(m_run[1], mx1);
        const float al0 = __expf(m_run[0] - mn0);
        const float al1 = __expf(m_run[1] - mn1);
        m_run[0] = mn0; m_run[1] = mn1;

        unsigned ph[4][4];
        float s0 = 0.f, s1 = 0.f;
        #pragma unroll
        for (int kb = 0; kb < 4; kb++) {
            #pragma unroll
            for (int j = 0; j < 2; j++) {
                const int nt = kb * 2 + j;
                const float p0 = __expf(sacc[nt][0] - mn0);
                const float p1 = __expf(sacc[nt][1] - mn0);
                const float p2 = __expf(sacc[nt][2] - mn1);
                const float p3 = __expf(sacc[nt][3] - mn1);
                s0 += p0 + p1;
                s1 += p2 + p3;
                ph[kb][2 * j + 0] = pack_h2(p0, p1);
                ph[kb][2 * j + 1] = pack_h2(p2, p3);
            }
        }
        s0 += __shfl_xor_sync(0xffffffffu, s0, 1);
        s0 += __shfl_xor_sync(0xffffffffu, s0, 2);
        s1 += __shfl_xor_sync(0xffffffffu, s1, 1);
        s1 += __shfl_xor_sync(0xffffffffu, s1, 2);
        l_run[0] = l_run[0] * al0 + s0;
        l_run[1] = l_run[1] * al1 + s1;
        #pragma unroll
        for (int ot = 0; ot < 8; ot++) {
            oacc[ot][0] *= al0; oacc[ot][1] *= al0;
            oacc[ot][2] *= al1; oacc[ot][3] *= al1;
        }

        if (kt < 31) { CP_WAIT(2); } else { CP_WAIT(0); }
        __syncthreads();   // V[kt] visible

        const unsigned sv = sbase + 2u * AV(kt & 1);

        // ---- O += P V (fp16 x fp16, single pass) ----
        #pragma unroll
        for (int ks = 0; ks < 4; ks++) {
            const int kr = ks * 16 + (g & 1) * 8 + (lane & 7);
            #pragma unroll
            for (int eb = 0; eb < 4; eb++) {
                unsigned vh4[4];
                const unsigned voff = 2u * (kr * TST + eb * 16 + (g >> 1) * 8);
                ldm_x4_t(vh4, sv + voff);
                #pragma unroll
                for (int j = 0; j < 2; j++) {
                    mma16816h(oacc[eb * 2 + j], ph[ks], &vh4[2 * j]);
                }
            }
        }
    }

    // Epilogue: normalize, write single-fp16 A2 (concat layout)
    const int bb = bh >> 4, hh = bh & 15;
    const int r0 = w * 16 + (lane >> 2);
    const float inv0 = 1.f / l_run[0];
    const float inv1 = 1.f / l_run[1];
    const size_t mrow0 = ((size_t)bb * SEQ + q0 + r0) * D_MODEL + hh * HEAD_DIM;
    const size_t mrow1 = ((size_t)bb * SEQ + q0 + r0 + 8) * D_MODEL + hh * HEAD_DIM;
    #pragma unroll
    for (int ot = 0; ot < 8; ot++) {
        const int e = ot * 8 + (lane & 3) * 2;
        *reinterpret_cast<unsigned*>(g_A2 + mrow0 + e) =
            pack_h2(oacc[ot][0] * inv0, oacc[ot][1] * inv0);
        *reinterpret_cast<unsigned*>(g_A2 + mrow1 + e) =
            pack_h2(oacc[ot][2] * inv1, oacc[ot][3] * inv1);
    }
}

// ============================================================================
extern "C" void kernel_launch(void* const* d_in, const int* in_sizes, int n_in,
                              void* d_out, int out_size)
{
    const float* x  = (const float*)d_in[0];
    const float* Wq = (const float*)d_in[1];
    const float* bq = (const float*)d_in[2];
    const float* Wk = (const float*)d_in[3];
    const float* bk = (const float*)d_in[4];
    const float* Wv = (const float*)d_in[5];
    const float* bv = (const float*)d_in[6];
    const float* Wo = (const float*)d_in[7];
    const float* bo = (const float*)d_in[8];
    float* out = (float*)d_out;

    cudaFuncSetAttribute(mm_mma, cudaFuncAttributeMaxDynamicSharedMemorySize, MM_SMEM);
    cudaFuncSetAttribute(attn_mma, cudaFuncAttributeMaxDynamicSharedMemorySize, ATTN_SMEM);

    conv_x<<<(M_TOTAL * D_MODEL) / 1024, 256>>>(x);
    conv_wqkv<<<(NQKV * D_MODEL) / 256, 256>>>(Wq, bq, Wk, bk, Wv, bv);
    conv_wo<<<(D_MODEL * D_MODEL) / 256, 256>>>(Wo);

    mm_mma<<<dim3(NQKV / 128, M_TOTAL / 128), 256, MM_SMEM>>>(nullptr, nullptr, 1);
    attn_mma<<<dim3(SEQ / 128, NBH), 256, ATTN_SMEM>>>();
    mm_mma<<<dim3(D_MODEL / 128, M_TOTAL / 128), 256, MM_SMEM>>>(bo, out, 0);
}

// round 14
// speedup vs baseline: 7.7103x; 1.1289x over previous
#include <cuda_runtime.h>
#include <cuda_bf16.h>
#include <cuda_fp16.h>
#include <math.h>

#define D_MODEL   1024
#define NUM_HEADS 16
#define HEAD_DIM  64
#define BATCH     4
#define SEQ       2048
#define M_TOTAL   (BATCH * SEQ)   // 8192
#define NQKV      (3 * D_MODEL)   // 3072
#define NBH       (BATCH * NUM_HEADS)  // 64

// ============================================================================
// Device global scratch (allocation-free rule)
// ============================================================================
__device__ __half g_X[M_TOTAL * D_MODEL];                            // X fp16 single
__device__ __half g_Bqkv[NQKV * D_MODEL];                            // [n][k] fp16
__device__ __half g_Wo[D_MODEL * D_MODEL];                           // [n][k] fp16
__device__ float g_bias_qkv[NQKV];
__device__ __half g_q[NBH * SEQ * HEAD_DIM];                         // Q fp16 single (pre-scaled)
__device__ __half g_k[NBH * SEQ * HEAD_DIM];                         // K fp16 single
__device__ __half g_vh[NBH * SEQ * HEAD_DIM];                        // V fp16 single
__device__ __half g_A2[M_TOTAL * D_MODEL];                           // attn out fp16 single

// ============================================================================
// PTX helpers (portable, compute_103-safe)
// ============================================================================
__device__ __forceinline__ unsigned smem_u32(const void* p) {
    unsigned a;
    asm("{ .reg .u64 t; cvta.to.shared.u64 t, %1; cvt.u32.u64 %0, t; }"
        : "=r"(a) : "l"(p));
    return a;
}
__device__ __forceinline__ void ldm_x4(unsigned* r, unsigned addr) {
    asm volatile("ldmatrix.sync.aligned.m8n8.x4.shared.b16 {%0,%1,%2,%3}, [%4];"
        : "=r"(r[0]), "=r"(r[1]), "=r"(r[2]), "=r"(r[3]) : "r"(addr));
}
__device__ __forceinline__ void ldm_x4_t(unsigned* r, unsigned addr) {
    asm volatile("ldmatrix.sync.aligned.m8n8.x4.trans.shared.b16 {%0,%1,%2,%3}, [%4];"
        : "=r"(r[0]), "=r"(r[1]), "=r"(r[2]), "=r"(r[3]) : "r"(addr));
}
__device__ __forceinline__ void mma16816h(float* c, const unsigned* a, const unsigned* b) {
    asm volatile("mma.sync.aligned.m16n8k16.row.col.f32.f16.f16.f32 "
        "{%0,%1,%2,%3}, {%4,%5,%6,%7}, {%8,%9}, {%0,%1,%2,%3};"
        : "+f"(c[0]), "+f"(c[1]), "+f"(c[2]), "+f"(c[3])
        : "r"(a[0]), "r"(a[1]), "r"(a[2]), "r"(a[3]), "r"(b[0]), "r"(b[1]));
}
__device__ __forceinline__ void cp_async16(unsigned saddr, const void* gptr) {
    asm volatile("cp.async.cg.shared.global [%0], [%1], 16;"
                 :: "r"(saddr), "l"(gptr) : "memory");
}
#define CP_COMMIT() asm volatile("cp.async.commit_group;" ::: "memory")
#define CP_WAIT(N)  asm volatile("cp.async.wait_group %0;" :: "n"(N) : "memory")

__device__ __forceinline__ unsigned pack_h2(float lo, float hi) {
    __half2 h = __floats2half2_rn(lo, hi);
    return *reinterpret_cast<unsigned*>(&h);
}

// ============================================================================
// Conversion kernels
// ============================================================================
__global__ __launch_bounds__(256) void conv_x(const float* __restrict__ x) {
    size_t i = ((size_t)blockIdx.x * 256 + threadIdx.x) * 4;
    float4 v = *reinterpret_cast<const float4*>(x + i);
    g_X[i + 0] = __float2half_rn(v.x);
    g_X[i + 1] = __float2half_rn(v.y);
    g_X[i + 2] = __float2half_rn(v.z);
    g_X[i + 3] = __float2half_rn(v.w);
}

__global__ __launch_bounds__(256) void conv_wqkv(
    const float* __restrict__ Wq, const float* __restrict__ bq,
    const float* __restrict__ Wk, const float* __restrict__ bk,
    const float* __restrict__ Wv, const float* __restrict__ bv) {
    size_t idx = (size_t)blockIdx.x * 256 + threadIdx.x;  // n*1024 + k
    int n = (int)(idx >> 10), k = (int)(idx & 1023);
    int proj = n >> 10, nc = n & 1023, h = nc >> 6, e = nc & 63;
    const float* W = (proj == 0) ? Wq : (proj == 1) ? Wk : Wv;
    float v = W[((size_t)h * D_MODEL + k) * HEAD_DIM + e];
    g_Bqkv[idx] = __float2half_rn(v);
    if (k == 0) {
        const float* b = (proj == 0) ? bq : (proj == 1) ? bk : bv;
        g_bias_qkv[n] = b[nc];
    }
}

__global__ __launch_bounds__(256) void conv_wo(const float* __restrict__ Wo) {
    size_t idx = (size_t)blockIdx.x * 256 + threadIdx.x;
    int n = (int)(idx >> 10), k = (int)(idx & 1023);
    g_Wo[idx] = __float2half_rn(Wo[(size_t)k * D_MODEL + n]);
}

// ============================================================================
// GEMM on mma.sync, single-pass fp16, 2-stage cp.async, BK=64.
// 2 CTAs/SM, stride 72 el (144 B). CTA 128x128, warps 2(M)x4(N).
// ============================================================================
#define AST 72
#define MMS_A 0
#define MMS_B (128 * AST)
#define STAGE_EL (2 * 128 * AST)          // 18432 el = 36864 B
#define MM_SMEM  (2 * STAGE_EL * 2)       // 73728 B per CTA

__global__ __launch_bounds__(256, 2) void mm_mma(const float* __restrict__ bias_ext,
                                                 float* __restrict__ outp, int mode) {
    extern __shared__ __align__(16) __half smm[];
    const unsigned sbase = smem_u32(smm);
    const int tid = threadIdx.x;
    const int lane = tid & 31;
    const int w = tid >> 5;
    const int mw = w >> 2, nw = w & 3;
    const int n0 = blockIdx.x * 128;
    const int m0 = blockIdx.y * 128;

    const __half* __restrict__ Ag = (mode == 1) ? g_X : g_A2;
    const __half* __restrict__ Bg = (mode == 1) ? g_Bqkv : g_Wo;
    const float* __restrict__ bias = (mode == 1) ? g_bias_qkv : bias_ext;

    float acc[4][4][4];
    #pragma unroll
    for (int a = 0; a < 4; a++)
        #pragma unroll
        for (int b = 0; b < 4; b++)
            #pragma unroll
            for (int c = 0; c < 4; c++) acc[a][b][c] = 0.f;

    auto issue = [&](int kc) {
        const int k0 = kc * 64;
        const unsigned sst = sbase + (unsigned)(2 * STAGE_EL) * (kc & 1);
        #pragma unroll
        for (int i = 0; i < 4; i++) {
            const int t = tid + 256 * i;
            const int row = t >> 3, slot = t & 7;
            const unsigned so = 2u * (row * AST + slot * 8);
            const size_t ga = (size_t)(m0 + row) * D_MODEL + k0 + slot * 8;
            const size_t gb = (size_t)(n0 + row) * D_MODEL + k0 + slot * 8;
            cp_async16(sst + 2u * MMS_A + so, Ag + ga);
            cp_async16(sst + 2u * MMS_B + so, Bg + gb);
        }
        CP_COMMIT();
    };

    issue(0);

    for (int kc = 0; kc < 16; kc++) {
        CP_WAIT(0);
        __syncthreads();
        if (kc + 1 < 16) issue(kc + 1);

        const unsigned sst = sbase + (unsigned)(2 * STAGE_EL) * (kc & 1);
        #pragma unroll
        for (int ks = 0; ks < 4; ks++) {
            unsigned ah[4][4], bh[4][2];
            const int arow = mw * 64 + (lane & 15);
            const int acol = ks * 16 + (lane >> 4) * 8;
            #pragma unroll
            for (int mt = 0; mt < 4; mt++) {
                const unsigned off = 2u * ((arow + mt * 16) * AST + acol);
                ldm_x4(ah[mt], sst + 2 * MMS_A + off);
            }
            const int g = lane >> 3;
            const int browo = (g >> 1) * 8 + (lane & 7);
            const int bko = (g & 1) * 8;
            #pragma unroll
            for (int np = 0; np < 2; np++) {
                const unsigned off = 2u * ((nw * 32 + np * 16 + browo) * AST + ks * 16 + bko);
                ldm_x4(&bh[np * 2][0], sst + 2 * MMS_B + off);
            }
            #pragma unroll
            for (int mt = 0; mt < 4; mt++)
                #pragma unroll
                for (int nt = 0; nt < 4; nt++)
                    mma16816h(acc[mt][nt], ah[mt], bh[nt]);
        }
    }

    // Epilogue
    #pragma unroll
    for (int mt = 0; mt < 4; mt++) {
        const int r0 = m0 + mw * 64 + mt * 16 + (lane >> 2);
        #pragma unroll
        for (int nt = 0; nt < 4; nt++) {
            const int c = n0 + nw * 32 + nt * 8 + (lane & 3) * 2;
            const float b0 = bias[c], b1 = bias[c + 1];
            #pragma unroll
            for (int h2 = 0; h2 < 2; h2++) {
                const int r = r0 + h2 * 8;
                float v0 = acc[mt][nt][h2 * 2 + 0] + b0;
                float v1 = acc[mt][nt][h2 * 2 + 1] + b1;
                if (mode == 0) {
                    float2 vv = make_float2(v0, v1);
                    *reinterpret_cast<float2*>(outp + (size_t)r * D_MODEL + c) = vv;
                } else {
                    const int proj = c >> 10, nc = c & 1023, hh = nc >> 6, e = nc & 63;
                    const size_t idx =
                        (((size_t)((r >> 11) * NUM_HEADS + hh)) * SEQ + (r & 2047)) * HEAD_DIM + e;
                    if (proj == 0) {
                        *reinterpret_cast<unsigned*>(g_q + idx) =
                            pack_h2(v0 * 0.125f, v1 * 0.125f);
                    } else if (proj == 1) {
                        *reinterpret_cast<unsigned*>(g_k + idx) = pack_h2(v0, v1);
                    } else {
                        *reinterpret_cast<unsigned*>(g_vh + idx) = pack_h2(v0, v1);
                    }
                }
            }
        }
    }
}

// ============================================================================
// Flash attention, FA2-style, 2 CTAs/SM: 128 q-rows x 64-key tiles.
// QK^T: fp16 single pass. PV: fp16 single pass.
// smem: Q 18.4KB + K 2x9.2KB + V 2x9.2KB = 55.3KB/CTA... (el counts below)
// ============================================================================
#define TST 72
#define AQ 0
#define AK(s) (9216 + (s) * 4608)
#define AV(s) (18432 + (s) * 4608)
#define ATTN_SMEM (27648 * 2)   // 55296 B

__global__ __launch_bounds__(256, 2) void attn_mma() {
    extern __shared__ __align__(16) __half smm[];
    const unsigned sbase = smem_u32(smm);
    const int tid = threadIdx.x;
    const int lane = tid & 31;
    const int w = tid >> 5;
    const int q0 = blockIdx.x * 128;
    const int bh = blockIdx.y;
    const size_t gbase = (size_t)bh * SEQ * HEAD_DIM;

    const int g = lane >> 3;
    const int browo = (g >> 1) * 8 + (lane & 7);
    const int bko = (g & 1) * 8;

    auto issueK = [&](int kt2) {
        const int t0 = kt2 * 64;
        const unsigned sk = sbase + 2u * AK(kt2 & 1);
        #pragma unroll
        for (int i = 0; i < 2; i++) {
            const int t = tid + 256 * i;
            const int row = t >> 3, slot = t & 7;
            const unsigned so = 2u * (row * TST + slot * 8);
            const size_t gk = gbase + (size_t)(t0 + row) * HEAD_DIM + slot * 8;
            cp_async16(sk + so, g_k + gk);
        }
        CP_COMMIT();
    };
    auto issueV = [&](int kt2) {
        const int t0 = kt2 * 64;
        const unsigned sv = sbase + 2u * AV(kt2 & 1);
        #pragma unroll
        for (int i = 0; i < 2; i++) {
            const int t = tid + 256 * i;
            const int row = t >> 3, slot = t & 7;
            const unsigned so = 2u * (row * TST + slot * 8);
            const size_t gv = gbase + (size_t)(t0 + row) * HEAD_DIM + slot * 8;
            cp_async16(sv + so, g_vh + gv);
        }
        CP_COMMIT();
    };

    issueK(0);
    issueV(0);

    // stage Q into smem
    #pragma unroll
    for (int i = 0; i < 4; i++) {
        const int t = tid + 256 * i;
        const int row = t >> 3, slot = t & 7;
        const int so = row * TST + slot * 8;
        const size_t gq = gbase + (size_t)(q0 + row) * HEAD_DIM + slot * 8;
        *reinterpret_cast<float4*>(smm + AQ + so) = *reinterpret_cast<const float4*>(g_q + gq);
    }
    __syncthreads();

    // warp's Q fragments (persistent in registers)
    unsigned qf[4][4];
    {
        const int arow = w * 16 + (lane & 15);
        #pragma unroll
        for (int ks = 0; ks < 4; ks++) {
            const unsigned qoff = 2u * (arow * TST + ks * 16 + (lane >> 4) * 8);
            ldm_x4(qf[ks], sbase + 2 * AQ + qoff);
        }
    }

    float m_run[2] = {-INFINITY, -INFINITY};
    float l_run[2] = {0.f, 0.f};
    float oacc[8][4];
    #pragma unroll
    for (int a = 0; a < 8; a++)
        #pragma unroll
        for (int c = 0; c < 4; c++) oacc[a][c] = 0.f;

    for (int kt = 0; kt < 32; kt++) {
        CP_WAIT(1);        // K[kt] landed
        __syncthreads();   // K[kt] visible; prev-tile smem fully consumed

        if (kt < 31) { issueK(kt + 1); issueV(kt + 1); }

        const unsigned sk = sbase + 2u * AK(kt & 1);

        // ---- S = Q K^T (fp16 single pass): 8 n8-tiles of keys ----
        float sacc[8][4];
        #pragma unroll
        for (int a = 0; a < 8; a++)
            #pragma unroll
            for (int c = 0; c < 4; c++) sacc[a][c] = 0.f;

        #pragma unroll
        for (int ks = 0; ks < 4; ks++) {
            #pragma unroll
            for (int kb = 0; kb < 4; kb++) {
                unsigned kh4[4];
                const unsigned off = 2u * ((kb * 16 + browo) * TST + ks * 16 + bko);
                ldm_x4(kh4, sk + off);
                #pragma unroll
                for (int j = 0; j < 2; j++)
                    mma16816h(sacc[kb * 2 + j], qf[ks], &kh4[2 * j]);
            }
        }

        // ---- softmax (registers + quad shuffles only) ----
        float mx0 = -INFINITY, mx1 = -INFINITY;
        #pragma unroll
        for (int nt = 0; nt < 8; nt++) {
            mx0 = fmaxf(mx0, fmaxf(sacc[nt][0], sacc[nt][1]));
            mx1 = fmaxf(mx1, fmaxf(sacc[nt][2], sacc[nt][3]));
        }
        mx0 = fmaxf(mx0, __shfl_xor_sync(0xffffffffu, mx0, 1));
        mx0 = fmaxf(mx0, __shfl_xor_sync(0xffffffffu, mx0, 2));
        mx1 = fmaxf(mx1, __shfl_xor_sync(0xffffffffu, mx1, 1));
        mx1 = fmaxf(mx1, __shfl_xor_sync(0xffffffffu, mx1, 2));
        const float mn0 = fmaxf(m_run[0], mx0);
        const float mn1 = fmaxf(m_run[1], mx1);
        const float al0 = __expf(m_run[0] - mn0);
        const float al1 = __expf(m_run[1] - mn1);
        m_run[0] = mn0; m_run[1] = mn1;

        unsigned ph[4][4];
        float s0 = 0.f, s1 = 0.f;
        #pragma unroll
        for (int kb = 0; kb < 4; kb++) {
            #pragma unroll
            for (int j = 0; j < 2; j++) {
                const int nt = kb * 2 + j;
                const float p0 = __expf(sacc[nt][0] - mn0);
                const float p1 = __expf(sacc[nt][1] - mn0);
                const float p2 = __expf(sacc[nt][2] - mn1);
                const float p3 = __expf(sacc[nt][3] - mn1);
                s0 += p0 + p1;
                s1 += p2 + p3;
                ph[kb][2 * j + 0] = pack_h2(p0, p1);
                ph[kb][2 * j + 1] = pack_h2(p2, p3);
            }
        }
        s0 += __shfl_xor_sync(0xffffffffu, s0, 1);
        s0 += __shfl_xor_sync(0xffffffffu, s0, 2);
        s1 += __shfl_xor_sync(0xffffffffu, s1, 1);
        s1 += __shfl_xor_sync(0xffffffffu, s1, 2);
        l_run[0] = l_run[0] * al0 + s0;
        l_run[1] = l_run[1] * al1 + s1;
        #pragma unroll
        for (int ot = 0; ot < 8; ot++) {
            oacc[ot][0] *= al0; oacc[ot][1] *= al0;
            oacc[ot][2] *= al1; oacc[ot][3] *= al1;
        }

        if (kt < 31) { CP_WAIT(2); } else { CP_WAIT(0); }
        __syncthreads();   // V[kt] visible

        const unsigned sv = sbase + 2u * AV(kt & 1);

        // ---- O += P V (fp16 x fp16, single pass) ----
        #pragma unroll
        for (int ks = 0; ks < 4; ks++) {
            const int kr = ks * 16 + (g & 1) * 8 + (lane & 7);
            #pragma unroll
            for (int eb = 0; eb < 4; eb++) {
                unsigned vh4[4];
                const unsigned voff = 2u * (kr * TST + eb * 16 + (g >> 1) * 8);
                ldm_x4_t(vh4, sv + voff);
                #pragma unroll
                for (int j = 0; j < 2; j++)
                    mma16816h(oacc[eb * 2 + j], ph[ks], &vh4[2 * j]);
            }
        }
    }

    // Epilogue: normalize, write single-fp16 A2 (concat layout)
    const int bb = bh >> 4, hh = bh & 15;
    const int r0 = w * 16 + (lane >> 2);
    const float inv0 = 1.f / l_run[0];
    const float inv1 = 1.f / l_run[1];
    const size_t mrow0 = ((size_t)bb * SEQ + q0 + r0) * D_MODEL + hh * HEAD_DIM;
    const size_t mrow1 = ((size_t)bb * SEQ + q0 + r0 + 8) * D_MODEL + hh * HEAD_DIM;
    #pragma unroll
    for (int ot = 0; ot < 8; ot++) {
        const int e = ot * 8 + (lane & 3) * 2;
        *reinterpret_cast<unsigned*>(g_A2 + mrow0 + e) =
            pack_h2(oacc[ot][0] * inv0, oacc[ot][1] * inv0);
        *reinterpret_cast<unsigned*>(g_A2 + mrow1 + e) =
            pack_h2(oacc[ot][2] * inv1, oacc[ot][3] * inv1);
    }
}

// ============================================================================
extern "C" void kernel_launch(void* const* d_in, const int* in_sizes, int n_in,
                              void* d_out, int out_size)
{
    const float* x  = (const float*)d_in[0];
    const float* Wq = (const float*)d_in[1];
    const float* bq = (const float*)d_in[2];
    const float* Wk = (const float*)d_in[3];
    const float* bk = (const float*)d_in[4];
    const float* Wv = (const float*)d_in[5];
    const float* bv = (const float*)d_in[6];
    const float* Wo = (const float*)d_in[7];
    const float* bo = (const float*)d_in[8];
    float* out = (float*)d_out;

    cudaFuncSetAttribute(mm_mma, cudaFuncAttributeMaxDynamicSharedMemorySize, MM_SMEM);
    cudaFuncSetAttribute(attn_mma, cudaFuncAttributeMaxDynamicSharedMemorySize, ATTN_SMEM);

    conv_x<<<(M_TOTAL * D_MODEL) / 1024, 256>>>(x);
    conv_wqkv<<<(NQKV * D_MODEL) / 256, 256>>>(Wq, bq, Wk, bk, Wv, bv);
    conv_wo<<<(D_MODEL * D_MODEL) / 256, 256>>>(Wo);

    mm_mma<<<dim3(NQKV / 128, M_TOTAL / 128), 256, MM_SMEM>>>(nullptr, nullptr, 1);
    attn_mma<<<dim3(SEQ / 128, NBH), 256, ATTN_SMEM>>>();
    mm_mma<<<dim3(D_MODEL / 128, M_TOTAL / 128), 256, MM_SMEM>>>(bo, out, 0);
}

// round 15
// speedup vs baseline: 8.4976x; 1.1021x over previous
#include <cuda_runtime.h>
#include <cuda_bf16.h>
#include <cuda_fp16.h>
#include <math.h>

#define D_MODEL   1024
#define NUM_HEADS 16
#define HEAD_DIM  64
#define BATCH     4
#define SEQ       2048
#define M_TOTAL   (BATCH * SEQ)   // 8192
#define NQKV      (3 * D_MODEL)   // 3072
#define NBH       (BATCH * NUM_HEADS)  // 64

// ============================================================================
// Device global scratch (allocation-free rule)
// ============================================================================
__device__ __half g_X[M_TOTAL * D_MODEL];        // X fp16, [m][k]
__device__ __half g_Bqkv[D_MODEL * NQKV];        // [k][n] fp16 (n = proj*1024+h*64+e)
__device__ __half g_Wo2[D_MODEL * D_MODEL];      // [k][n] fp16 (natural Wo layout)
__device__ float g_bias_qkv[NQKV];
__device__ __half g_q[NBH * SEQ * HEAD_DIM];     // Q fp16 (pre-scaled x0.125)
__device__ __half g_k[NBH * SEQ * HEAD_DIM];     // K fp16
__device__ __half g_v[NBH * SEQ * HEAD_DIM];     // V fp16
__device__ __half g_A2[M_TOTAL * D_MODEL];       // attn out fp16, [m][k]

// ============================================================================
// PTX helpers (portable, compute_103-safe)
// ============================================================================
__device__ __forceinline__ unsigned smem_u32(const void* p) {
    unsigned a;
    asm("{ .reg .u64 t; cvta.to.shared.u64 t, %1; cvt.u32.u64 %0, t; }"
        : "=r"(a) : "l"(p));
    return a;
}
__device__ __forceinline__ void ldm_x4(unsigned* r, unsigned addr) {
    asm volatile("ldmatrix.sync.aligned.m8n8.x4.shared.b16 {%0,%1,%2,%3}, [%4];"
        : "=r"(r[0]), "=r"(r[1]), "=r"(r[2]), "=r"(r[3]) : "r"(addr));
}
__device__ __forceinline__ void ldm_x4_t(unsigned* r, unsigned addr) {
    asm volatile("ldmatrix.sync.aligned.m8n8.x4.trans.shared.b16 {%0,%1,%2,%3}, [%4];"
        : "=r"(r[0]), "=r"(r[1]), "=r"(r[2]), "=r"(r[3]) : "r"(addr));
}
__device__ __forceinline__ void mma16816h(float* c, const unsigned* a, const unsigned* b) {
    asm volatile("mma.sync.aligned.m16n8k16.row.col.f32.f16.f16.f32 "
        "{%0,%1,%2,%3}, {%4,%5,%6,%7}, {%8,%9}, {%0,%1,%2,%3};"
        : "+f"(c[0]), "+f"(c[1]), "+f"(c[2]), "+f"(c[3])
        : "r"(a[0]), "r"(a[1]), "r"(a[2]), "r"(a[3]), "r"(b[0]), "r"(b[1]));
}
__device__ __forceinline__ void cp_async16(unsigned saddr, const void* gptr) {
    asm volatile("cp.async.cg.shared.global [%0], [%1], 16;"
                 :: "r"(saddr), "l"(gptr) : "memory");
}
#define CP_COMMIT() asm volatile("cp.async.commit_group;" ::: "memory")
#define CP_WAIT(N)  asm volatile("cp.async.wait_group %0;" :: "n"(N) : "memory")

__device__ __forceinline__ unsigned pack_h2(float lo, float hi) {
    __half2 h = __floats2half2_rn(lo, hi);
    return *reinterpret_cast<unsigned*>(&h);
}

// ============================================================================
// Fused conversion kernel: one launch, blockIdx-partitioned, fully coalesced.
// ============================================================================
#define CONV_X_BLKS   ((M_TOTAL * D_MODEL) / 1024)   // 8192
#define CONV_B_BLKS   ((NQKV * D_MODEL) / 1024)      // 3072
#define CONV_WO_BLKS  ((D_MODEL * D_MODEL) / 1024)   // 1024
#define CONV_BLKS     (CONV_X_BLKS + CONV_B_BLKS + CONV_WO_BLKS)

__global__ __launch_bounds__(256) void conv_all(
    const float* __restrict__ x,
    const float* __restrict__ Wq, const float* __restrict__ bq,
    const float* __restrict__ Wk, const float* __restrict__ bk,
    const float* __restrict__ Wv, const float* __restrict__ bv,
    const float* __restrict__ Wo)
{
    const int b = blockIdx.x;
    if (b < CONV_X_BLKS) {
        size_t i = ((size_t)b * 256 + threadIdx.x) * 4;
        float4 v = *reinterpret_cast<const float4*>(x + i);
        uint2 o;
        o.x = pack_h2(v.x, v.y);
        o.y = pack_h2(v.z, v.w);
        *reinterpret_cast<uint2*>(g_X + i) = o;
    } else if (b < CONV_X_BLKS + CONV_B_BLKS) {
        // j = ((proj*16 + h)*1024 + k)*64 + e : reads W[h][k][e] coalesced
        size_t j = ((size_t)(b - CONV_X_BLKS) * 256 + threadIdx.x) * 4;
        const int e = (int)(j & 63);
        const int k = (int)((j >> 6) & 1023);
        const int h = (int)((j >> 16) & 15);
        const int proj = (int)(j >> 20);
        const float* W = (proj == 0) ? Wq : (proj == 1) ? Wk : Wv;
        float4 v = *reinterpret_cast<const float4*>(
            W + (((size_t)h * D_MODEL + k) << 6) + e);
        const int n = proj * 1024 + h * 64 + e;
        uint2 o;
        o.x = pack_h2(v.x, v.y);
        o.y = pack_h2(v.z, v.w);
        *reinterpret_cast<uint2*>(g_Bqkv + (size_t)k * NQKV + n) = o;
        if (k == 0) {
            const float* bb = (proj == 0) ? bq : (proj == 1) ? bk : bv;
            #pragma unroll
            for (int jj = 0; jj < 4; jj++)
                g_bias_qkv[n + jj] = bb[h * 64 + e + jj];
        }
    } else {
        size_t i = ((size_t)(b - CONV_X_BLKS - CONV_B_BLKS) * 256 + threadIdx.x) * 4;
        float4 v = *reinterpret_cast<const float4*>(Wo + i);
        uint2 o;
        o.x = pack_h2(v.x, v.y);
        o.y = pack_h2(v.z, v.w);
        *reinterpret_cast<uint2*>(g_Wo2 + i) = o;
    }
}

// ============================================================================
// GEMM on mma.sync, single-pass fp16, 2-stage cp.async, BK=64.
// A [m][k] (non-trans ldmatrix), B [k][n] (trans ldmatrix, V-style).
// 2 CTAs/SM. CTA 128x128, warps 2(M)x4(N), warp tile 64x32.
// ============================================================================
#define AST 72
#define BST 136
#define MMS_A 0                           // 128*72   = 9216 el
#define MMS_B 9216                        // 64*136   = 8704 el
#define STAGE_EL (9216 + 8704)            // 17920 el = 35840 B
#define MM_SMEM  (2 * STAGE_EL * 2)       // 71680 B per CTA

__global__ __launch_bounds__(256, 2) void mm_mma(const float* __restrict__ bias_ext,
                                                 float* __restrict__ outp, int mode) {
    extern __shared__ __align__(16) __half smm[];
    const unsigned sbase = smem_u32(smm);
    const int tid = threadIdx.x;
    const int lane = tid & 31;
    const int w = tid >> 5;
    const int mw = w >> 2, nw = w & 3;
    const int n0 = blockIdx.x * 128;
    const int m0 = blockIdx.y * 128;

    const __half* __restrict__ Ag = (mode == 1) ? g_X : g_A2;
    const __half* __restrict__ Bg = (mode == 1) ? g_Bqkv : g_Wo2;
    const int bw = (mode == 1) ? NQKV : D_MODEL;
    const float* __restrict__ bias = (mode == 1) ? g_bias_qkv : bias_ext;

    float acc[4][4][4];
    #pragma unroll
    for (int a = 0; a < 4; a++)
        #pragma unroll
        for (int bq_ = 0; bq_ < 4; bq_++)
            #pragma unroll
            for (int c = 0; c < 4; c++) acc[a][bq_][c] = 0.f;

    auto issue = [&](int kc) {
        const int k0 = kc * 64;
        const unsigned sst = sbase + (unsigned)(2 * STAGE_EL) * (kc & 1);
        #pragma unroll
        for (int i = 0; i < 4; i++) {
            const int t = tid + 256 * i;
            // A: 128 rows(m) x 8 slots of 8 el(k)
            {
                const int row = t >> 3, slot = t & 7;
                const unsigned so = 2u * (row * AST + slot * 8);
                const size_t ga = (size_t)(m0 + row) * D_MODEL + k0 + slot * 8;
                cp_async16(sst + 2u * MMS_A + so, Ag + ga);
            }
            // B: 64 rows(k) x 16 slots of 8 el(n)
            {
                const int row = t >> 4, slot = t & 15;
                const unsigned so = 2u * (row * BST + slot * 8);
                const size_t gb = (size_t)(k0 + row) * bw + n0 + slot * 8;
                cp_async16(sst + 2u * MMS_B + so, Bg + gb);
            }
        }
        CP_COMMIT();
    };

    issue(0);

    const int g = lane >> 3;
    for (int kc = 0; kc < 16; kc++) {
        CP_WAIT(0);
        __syncthreads();
        if (kc + 1 < 16) issue(kc + 1);

        const unsigned sst = sbase + (unsigned)(2 * STAGE_EL) * (kc & 1);
        #pragma unroll
        for (int ks = 0; ks < 4; ks++) {
            unsigned ah[4][4], bh[4][2];
            const int arow = mw * 64 + (lane & 15);
            const int acol = ks * 16 + (lane >> 4) * 8;
            #pragma unroll
            for (int mt = 0; mt < 4; mt++) {
                const unsigned off = 2u * ((arow + mt * 16) * AST + acol);
                ldm_x4(ah[mt], sst + 2 * MMS_A + off);
            }
            // B fragments via trans ldmatrix from [k][n] tile (V-style)
            const int kr = ks * 16 + (g & 1) * 8 + (lane & 7);
            #pragma unroll
            for (int np = 0; np < 2; np++) {
                const unsigned off = 2u * (kr * BST + nw * 32 + np * 16 + (g >> 1) * 8);
                ldm_x4_t(&bh[np * 2][0], sst + 2 * MMS_B + off);
            }
            #pragma unroll
            for (int mt = 0; mt < 4; mt++)
                #pragma unroll
                for (int nt = 0; nt < 4; nt++)
                    mma16816h(acc[mt][nt], ah[mt], bh[nt]);
        }
    }

    // Epilogue
    #pragma unroll
    for (int mt = 0; mt < 4; mt++) {
        const int r0 = m0 + mw * 64 + mt * 16 + (lane >> 2);
        #pragma unroll
        for (int nt = 0; nt < 4; nt++) {
            const int c = n0 + nw * 32 + nt * 8 + (lane & 3) * 2;
            const float b0 = bias[c], b1 = bias[c + 1];
            #pragma unroll
            for (int h2 = 0; h2 < 2; h2++) {
                const int r = r0 + h2 * 8;
                float v0 = acc[mt][nt][h2 * 2 + 0] + b0;
                float v1 = acc[mt][nt][h2 * 2 + 1] + b1;
                if (mode == 0) {
                    float2 vv = make_float2(v0, v1);
                    *reinterpret_cast<float2*>(outp + (size_t)r * D_MODEL + c) = vv;
                } else {
                    const int proj = c >> 10, nc = c & 1023, hh = nc >> 6, e = nc & 63;
                    const size_t idx =
                        (((size_t)((r >> 11) * NUM_HEADS + hh)) * SEQ + (r & 2047)) * HEAD_DIM + e;
                    if (proj == 0) {
                        *reinterpret_cast<unsigned*>(g_q + idx) =
                            pack_h2(v0 * 0.125f, v1 * 0.125f);
                    } else if (proj == 1) {
                        *reinterpret_cast<unsigned*>(g_k + idx) = pack_h2(v0, v1);
                    } else {
                        *reinterpret_cast<unsigned*>(g_v + idx) = pack_h2(v0, v1);
                    }
                }
            }
        }
    }
}

// ============================================================================
// Flash attention, FA2-style, 2 CTAs/SM: 128 q-rows x 64-key tiles.
// Single-pass fp16 QK^T and PV. ONE barrier per key tile: K+V share one
// commit group, waited together at tile-top.
// ============================================================================
#define TST 72
#define AQ 0
#define AK(s) (9216 + (s) * 4608)
#define AV(s) (18432 + (s) * 4608)
#define ATTN_SMEM (27648 * 2)   // 55296 B

__global__ __launch_bounds__(256, 2) void attn_mma() {
    extern __shared__ __align__(16) __half smm[];
    const unsigned sbase = smem_u32(smm);
    const int tid = threadIdx.x;
    const int lane = tid & 31;
    const int w = tid >> 5;
    const int q0 = blockIdx.x * 128;
    const int bh = blockIdx.y;
    const size_t gbase = (size_t)bh * SEQ * HEAD_DIM;

    const int g = lane >> 3;
    const int browo = (g >> 1) * 8 + (lane & 7);
    const int bko = (g & 1) * 8;

    auto issueKV = [&](int kt2) {
        const int t0 = kt2 * 64;
        const int s = kt2 & 1;
        #pragma unroll
        for (int i = 0; i < 2; i++) {
            const int t = tid + 256 * i;
            const int row = t >> 3, slot = t & 7;
            const unsigned so = 2u * (row * TST + slot * 8);
            const size_t gk = gbase + (size_t)(t0 + row) * HEAD_DIM + slot * 8;
            cp_async16(sbase + 2u * AK(s) + so, g_k + gk);
            cp_async16(sbase + 2u * AV(s) + so, g_v + gk);
        }
        CP_COMMIT();
    };

    issueKV(0);

    // stage Q into smem
    #pragma unroll
    for (int i = 0; i < 4; i++) {
        const int t = tid + 256 * i;
        const int row = t >> 3, slot = t & 7;
        const int so = row * TST + slot * 8;
        const size_t gq = gbase + (size_t)(q0 + row) * HEAD_DIM + slot * 8;
        *reinterpret_cast<float4*>(smm + AQ + so) = *reinterpret_cast<const float4*>(g_q + gq);
    }
    __syncthreads();

    // warp's Q fragments (persistent in registers)
    unsigned qf[4][4];
    {
        const int arow = w * 16 + (lane & 15);
        #pragma unroll
        for (int ks = 0; ks < 4; ks++) {
            const unsigned qoff = 2u * (arow * TST + ks * 16 + (lane >> 4) * 8);
            ldm_x4(qf[ks], sbase + 2 * AQ + qoff);
        }
    }

    float m_run[2] = {-INFINITY, -INFINITY};
    float l_run[2] = {0.f, 0.f};
    float oacc[8][4];
    #pragma unroll
    for (int a = 0; a < 8; a++)
        #pragma unroll
        for (int c = 0; c < 4; c++) oacc[a][c] = 0.f;

    for (int kt = 0; kt < 32; kt++) {
        CP_WAIT(0);        // K[kt] and V[kt] landed (one group)
        __syncthreads();   // visible to all; prev-tile smem fully consumed

        if (kt < 31) issueKV(kt + 1);   // overlaps all of S + softmax + PV

        const unsigned sk = sbase + 2u * AK(kt & 1);
        const unsigned sv = sbase + 2u * AV(kt & 1);

        // ---- S = Q K^T (fp16 single pass): 8 n8-tiles of keys ----
        float sacc[8][4];
        #pragma unroll
        for (int a = 0; a < 8; a++)
            #pragma unroll
            for (int c = 0; c < 4; c++) sacc[a][c] = 0.f;

        #pragma unroll
        for (int ks = 0; ks < 4; ks++) {
            #pragma unroll
            for (int kb = 0; kb < 4; kb++) {
                unsigned kh4[4];
                const unsigned off = 2u * ((kb * 16 + browo) * TST + ks * 16 + bko);
                ldm_x4(kh4, sk + off);
                #pragma unroll
                for (int j = 0; j < 2; j++)
                    mma16816h(sacc[kb * 2 + j], qf[ks], &kh4[2 * j]);
            }
        }

        // ---- softmax (registers + quad shuffles only) ----
        float mx0 = -INFINITY, mx1 = -INFINITY;
        #pragma unroll
        for (int nt = 0; nt < 8; nt++) {
            mx0 = fmaxf(mx0, fmaxf(sacc[nt][0], sacc[nt][1]));
            mx1 = fmaxf(mx1, fmaxf(sacc[nt][2], sacc[nt][3]));
        }
        mx0 = fmaxf(mx0, __shfl_xor_sync(0xffffffffu, mx0, 1));
        mx0 = fmaxf(mx0, __shfl_xor_sync(0xffffffffu, mx0, 2));
        mx1 = fmaxf(mx1, __shfl_xor_sync(0xffffffffu, mx1, 1));
        mx1 = fmaxf(mx1, __shfl_xor_sync(0xffffffffu, mx1, 2));
        const float mn0 = fmaxf(m_run[0], mx0);
        const float mn1 = fmaxf(m_run[1], mx1);
        const float al0 = __expf(m_run[0] - mn0);
        const float al1 = __expf(m_run[1] - mn1);
        m_run[0] = mn0; m_run[1] = mn1;

        unsigned ph[4][4];
        float s0 = 0.f, s1 = 0.f;
        #pragma unroll
        for (int kb = 0; kb < 4; kb++) {
            #pragma unroll
            for (int j = 0; j < 2; j++) {
                const int nt = kb * 2 + j;
                const float p0 = __expf(sacc[nt][0] - mn0);
                const float p1 = __expf(sacc[nt][1] - mn0);
                const float p2 = __expf(sacc[nt][2] - mn1);
                const float p3 = __expf(sacc[nt][3] - mn1);
                s0 += p0 + p1;
                s1 += p2 + p3;
                ph[kb][2 * j + 0] = pack_h2(p0, p1);
                ph[kb][2 * j + 1] = pack_h2(p2, p3);
            }
        }
        s0 += __shfl_xor_sync(0xffffffffu, s0, 1);
        s0 += __shfl_xor_sync(0xffffffffu, s0, 2);
        s1 += __shfl_xor_sync(0xffffffffu, s1, 1);
        s1 += __shfl_xor_sync(0xffffffffu, s1, 2);
        l_run[0] = l_run[0] * al0 + s0;
        l_run[1] = l_run[1] * al1 + s1;
        #pragma unroll
        for (int ot = 0; ot < 8; ot++) {
            oacc[ot][0] *= al0; oacc[ot][1] *= al0;
            oacc[ot][2] *= al1; oacc[ot][3] *= al1;
        }

        // ---- O += P V (fp16 x fp16, single pass; V already resident) ----
        #pragma unroll
        for (int ks = 0; ks < 4; ks++) {
            const int kr = ks * 16 + (g & 1) * 8 + (lane & 7);
            #pragma unroll
            for (int eb = 0; eb < 4; eb++) {
                unsigned vh4[4];
                const unsigned voff = 2u * (kr * TST + eb * 16 + (g >> 1) * 8);
                ldm_x4_t(vh4, sv + voff);
                #pragma unroll
                for (int j = 0; j < 2; j++)
                    mma16816h(oacc[eb * 2 + j], ph[ks], &vh4[2 * j]);
            }
        }
    }

    // Epilogue: normalize, write single-fp16 A2 (concat layout)
    const int bb = bh >> 4, hh = bh & 15;
    const int r0 = w * 16 + (lane >> 2);
    const float inv0 = 1.f / l_run[0];
    const float inv1 = 1.f / l_run[1];
    const size_t mrow0 = ((size_t)bb * SEQ + q0 + r0) * D_MODEL + hh * HEAD_DIM;
    const size_t mrow1 = ((size_t)bb * SEQ + q0 + r0 + 8) * D_MODEL + hh * HEAD_DIM;
    #pragma unroll
    for (int ot = 0; ot < 8; ot++) {
        const int e = ot * 8 + (lane & 3) * 2;
        *reinterpret_cast<unsigned*>(g_A2 + mrow0 + e) =
            pack_h2(oacc[ot][0] * inv0, oacc[ot][1] * inv0);
        *reinterpret_cast<unsigned*>(g_A2 + mrow1 + e) =
            pack_h2(oacc[ot][2] * inv1, oacc[ot][3] * inv1);
    }
}

// ============================================================================
extern "C" void kernel_launch(void* const* d_in, const int* in_sizes, int n_in,
                              void* d_out, int out_size)
{
    const float* x  = (const float*)d_in[0];
    const float* Wq = (const float*)d_in[1];
    const float* bq = (const float*)d_in[2];
    const float* Wk = (const float*)d_in[3];
    const float* bk = (const float*)d_in[4];
    const float* Wv = (const float*)d_in[5];
    const float* bv = (const float*)d_in[6];
    const float* Wo = (const float*)d_in[7];
    const float* bo = (const float*)d_in[8];
    float* out = (float*)d_out;

    cudaFuncSetAttribute(mm_mma, cudaFuncAttributeMaxDynamicSharedMemorySize, MM_SMEM);
    cudaFuncSetAttribute(attn_mma, cudaFuncAttributeMaxDynamicSharedMemorySize, ATTN_SMEM);

    conv_all<<<CONV_BLKS, 256>>>(x, Wq, bq, Wk, bk, Wv, bv, Wo);

    mm_mma<<<dim3(NQKV / 128, M_TOTAL / 128), 256, MM_SMEM>>>(nullptr, nullptr, 1);
    attn_mma<<<dim3(SEQ / 128, NBH), 256, ATTN_SMEM>>>();
    mm_mma<<<dim3(D_MODEL / 128, M_TOTAL / 128), 256, MM_SMEM>>>(bo, out, 0);
}